// round 1
// baseline (speedup 1.0000x reference)
#include <cuda_runtime.h>
#include <math.h>

// Problem dims
#define BB 64
#define NI 512
#define NQ 128
#define DD 640
#define DH 1280
#define NEGV (-65504.0f)

// ---------------- scratch (static __device__ arrays; no allocs) ----------------
__device__ float g_P1[BB * NI * NQ];          // attention-1 probs (64,512,128)
__device__ float g_P2[BB * NQ * NI];          // attention-2 probs (64,128,512)
__device__ float g_iatt[BB * NI * DD];        // attention-1 out   (64,512,640)
__device__ float g_latt[BB * NQ * DD];        // attention-2 out   (64,128,640)
__device__ float g_atti[BB * NI];             // attflat-1 logits/probs
__device__ float g_attl[BB * NQ];             // attflat-2 logits/probs
__device__ float g_pooli[BB * DD];
__device__ float g_pooll[BB * DD];

// ---------------- generic 128x128x16 fp32 SGEMM, 8x8 micro-tile ----------------
// C[b] = alpha * A[b] (MxK) @ op(B[b]) (+bias)      op = B (KxN) or B^T (NxK rows)
// EPI==0: store C (optional bias[n])
// EPI==2: fused attflat logits: atomicAdd_m( sum_n relu(acc + bias[n]) * w2[n] )
template <bool TRANSB, int EPI>
__global__ __launch_bounds__(256, 2)
void gemm128(const float* __restrict__ A, const float* __restrict__ Bm,
             float* __restrict__ C, int M, int N, int K,
             long sA, long sB, long sC, float alpha,
             const float* __restrict__ bias,
             const float* __restrict__ w2,
             float* __restrict__ attOut)
{
    __shared__ __align__(16) float As[16][128];
    __shared__ __align__(16) float Bs[16][128];

    const int zb = blockIdx.z;
    A  += (long)zb * sA;
    Bm += (long)zb * sB;
    if (EPI == 0) C += (long)zb * sC;

    const int m0  = blockIdx.y * 128;
    const int n0  = blockIdx.x * 128;
    const int tid = threadIdx.x;
    const int tx  = tid & 15;
    const int ty  = tid >> 4;

    float acc[8][8];
#pragma unroll
    for (int i = 0; i < 8; i++)
#pragma unroll
        for (int j = 0; j < 8; j++) acc[i][j] = 0.f;

    for (int k0 = 0; k0 < K; k0 += 16) {
        // --- load A tile (128 rows x 16 k) transposed into As[k][m] ---
#pragma unroll
        for (int i = 0; i < 2; i++) {
            int f  = tid + i * 256;       // 0..511 float4 slots
            int ml = f >> 2;              // 0..127
            int kl = (f & 3) << 2;        // 0,4,8,12
            float4 v = make_float4(0.f, 0.f, 0.f, 0.f);
            if (m0 + ml < M)
                v = *(const float4*)(A + (long)(m0 + ml) * K + (k0 + kl));
            As[kl + 0][ml] = v.x; As[kl + 1][ml] = v.y;
            As[kl + 2][ml] = v.z; As[kl + 3][ml] = v.w;
        }
        // --- load B tile into Bs[k][n] ---
        if (TRANSB) {
#pragma unroll
            for (int i = 0; i < 2; i++) {
                int f  = tid + i * 256;
                int nl = f >> 2;
                int kl = (f & 3) << 2;
                float4 v = make_float4(0.f, 0.f, 0.f, 0.f);
                if (n0 + nl < N)
                    v = *(const float4*)(Bm + (long)(n0 + nl) * K + (k0 + kl));
                Bs[kl + 0][nl] = v.x; Bs[kl + 1][nl] = v.y;
                Bs[kl + 2][nl] = v.z; Bs[kl + 3][nl] = v.w;
            }
        } else {
#pragma unroll
            for (int i = 0; i < 2; i++) {
                int f  = tid + i * 256;
                int kl = f >> 5;              // 0..15
                int nl = (f & 31) << 2;       // 0..124
                float4 v = make_float4(0.f, 0.f, 0.f, 0.f);
                if (n0 + nl < N)
                    v = *(const float4*)(Bm + (long)(k0 + kl) * N + (n0 + nl));
                *(float4*)&Bs[kl][nl] = v;
            }
        }
        __syncthreads();

#pragma unroll
        for (int kk = 0; kk < 16; kk++) {
            float a[8], b[8];
            *(float4*)&a[0] = *(const float4*)&As[kk][ty * 4];
            *(float4*)&a[4] = *(const float4*)&As[kk][64 + ty * 4];
            *(float4*)&b[0] = *(const float4*)&Bs[kk][tx * 4];
            *(float4*)&b[4] = *(const float4*)&Bs[kk][64 + tx * 4];
#pragma unroll
            for (int i = 0; i < 8; i++)
#pragma unroll
                for (int j = 0; j < 8; j++)
                    acc[i][j] = fmaf(a[i], b[j], acc[i][j]);
        }
        __syncthreads();
    }

    if (EPI == 0) {
#pragma unroll
        for (int i = 0; i < 8; i++) {
            int m = m0 + ((i < 4) ? (ty * 4 + i) : (64 + ty * 4 + i - 4));
            if (m >= M) continue;
#pragma unroll
            for (int g = 0; g < 2; g++) {
                int n = n0 + g * 64 + tx * 4;
                float4 v;
                v.x = acc[i][g * 4 + 0] * alpha;
                v.y = acc[i][g * 4 + 1] * alpha;
                v.z = acc[i][g * 4 + 2] * alpha;
                v.w = acc[i][g * 4 + 3] * alpha;
                if (bias) {
                    v.x += bias[n]; v.y += bias[n + 1];
                    v.z += bias[n + 2]; v.w += bias[n + 3];
                }
                *(float4*)(C + (long)m * N + n) = v;
            }
        }
    } else {
        float bv[8], wv[8];
#pragma unroll
        for (int j = 0; j < 8; j++) {
            int n = n0 + ((j < 4) ? (tx * 4 + j) : (64 + tx * 4 + j - 4));
            bv[j] = bias[n];
            wv[j] = w2[n];
        }
#pragma unroll
        for (int i = 0; i < 8; i++) {
            float s = 0.f;
#pragma unroll
            for (int j = 0; j < 8; j++)
                s += fmaxf(acc[i][j] + bv[j], 0.f) * wv[j];
#pragma unroll
            for (int off = 8; off > 0; off >>= 1)
                s += __shfl_down_sync(0xffffffffu, s, off, 16);
            if ((tid & 15) == 0) {
                int m = m0 + ((i < 4) ? (ty * 4 + i) : (64 + ty * 4 + i - 4));
                if (m < M) atomicAdd(attOut + m, s);
            }
        }
    }
}

// ---------------- masked row softmax (in place), optional copy-out ----------------
__device__ __forceinline__ float warpMax(float v)
{
#pragma unroll
    for (int o = 16; o > 0; o >>= 1) v = fmaxf(v, __shfl_xor_sync(0xffffffffu, v, o));
    return v;
}
__device__ __forceinline__ float warpSum(float v)
{
#pragma unroll
    for (int o = 16; o > 0; o >>= 1) v += __shfl_xor_sync(0xffffffffu, v, o);
    return v;
}

// one block (128 threads) per row; row length N in {128, 512}; mask[b*N + n] != 0 => NEG
__global__ void softmax_rows(float* __restrict__ P,
                             const unsigned int* __restrict__ mask,
                             int rowsPerBatch, int N,
                             float* __restrict__ wout)
{
    const int row = blockIdx.x;
    const int bb  = row / rowsPerBatch;
    float* prow = P + (long)row * N;
    const unsigned int* mrow = mask + (long)bb * N;
    const int tid = threadIdx.x;
    const int cnt = N >> 7;   // 1 or 4

    float v[4];
    float mx = -3.4e38f;
    for (int c = 0; c < cnt; c++) {
        int n = (c << 7) + tid;
        float x = prow[n];
        if (mrow[n] != 0u) x = NEGV;
        v[c] = x;
        mx = fmaxf(mx, x);
    }
    __shared__ float sr[4];
    float wm = warpMax(mx);
    if ((tid & 31) == 0) sr[tid >> 5] = wm;
    __syncthreads();
    mx = fmaxf(fmaxf(sr[0], sr[1]), fmaxf(sr[2], sr[3]));

    float sum = 0.f;
    for (int c = 0; c < cnt; c++) { v[c] = expf(v[c] - mx); sum += v[c]; }
    __syncthreads();
    float ws = warpSum(sum);
    if ((tid & 31) == 0) sr[tid >> 5] = ws;
    __syncthreads();
    sum = sr[0] + sr[1] + sr[2] + sr[3];

    float inv = 1.f / sum;
    for (int c = 0; c < cnt; c++) {
        int n = (c << 7) + tid;
        float r = v[c] * inv;
        prow[n] = r;
        if (wout) wout[(long)row * N + n] = r;
    }
}

// pooled[b, d] = sum_m att[b, m] * X[b, m, d]
__global__ void pool_kernel(const float* __restrict__ X,
                            const float* __restrict__ att,
                            float* __restrict__ pooled, int Nseq)
{
    int bb = blockIdx.y;
    int d  = blockIdx.x * 128 + threadIdx.x;
    const float* Xb = X + (long)bb * Nseq * DD + d;
    const float* ab = att + bb * Nseq;
    float a0 = 0.f, a1 = 0.f, a2 = 0.f, a3 = 0.f;
    for (int m = 0; m < Nseq; m += 4) {
        a0 = fmaf(ab[m + 0], Xb[(long)(m + 0) * DD], a0);
        a1 = fmaf(ab[m + 1], Xb[(long)(m + 1) * DD], a1);
        a2 = fmaf(ab[m + 2], Xb[(long)(m + 2) * DD], a2);
        a3 = fmaf(ab[m + 3], Xb[(long)(m + 3) * DD], a3);
    }
    pooled[bb * DD + d] = (a0 + a1) + (a2 + a3);
}

__global__ void fill_scalar(float* __restrict__ p, int n, const float* __restrict__ s)
{
    int i = blockIdx.x * 256 + threadIdx.x;
    if (i < n) p[i] = *s;
}

// ---------------------------------- launch ----------------------------------
extern "C" void kernel_launch(void* const* d_in, const int* in_sizes, int n_in,
                              void* d_out, int out_size)
{
    const float* i_batch = (const float*)d_in[0];
    const float* q_batch = (const float*)d_in[1];
    const unsigned int* i_mask = (const unsigned int*)d_in[2];
    const unsigned int* q_mask = (const unsigned int*)d_in[3];
    const float* lW1 = (const float*)d_in[4];
    const float* lb1 = (const float*)d_in[5];
    const float* lW2 = (const float*)d_in[6];
    const float* lb2 = (const float*)d_in[7];
    const float* lWm = (const float*)d_in[8];
    const float* lbm = (const float*)d_in[9];
    const float* iW1 = (const float*)d_in[10];
    const float* ib1 = (const float*)d_in[11];
    const float* iW2 = (const float*)d_in[12];
    const float* ib2 = (const float*)d_in[13];
    const float* iWm = (const float*)d_in[14];
    const float* ibm = (const float*)d_in[15];
    float* out = (float*)d_out;

    float *P1, *P2, *iatt, *latt, *atti, *attl, *pooli, *pooll;
    cudaGetSymbolAddress((void**)&P1, g_P1);
    cudaGetSymbolAddress((void**)&P2, g_P2);
    cudaGetSymbolAddress((void**)&iatt, g_iatt);
    cudaGetSymbolAddress((void**)&latt, g_latt);
    cudaGetSymbolAddress((void**)&atti, g_atti);
    cudaGetSymbolAddress((void**)&attl, g_attl);
    cudaGetSymbolAddress((void**)&pooli, g_pooli);
    cudaGetSymbolAddress((void**)&pooll, g_pooll);

    const float SCALE = 0.039528470752104744f;  // 1/sqrt(640)

    // ---- attention 1: i_feat_att = softmax(i @ q^T * s, mask=q_mask) @ q ----
    gemm128<true, 0><<<dim3(NQ / 128, NI / 128, BB), 256>>>(
        i_batch, q_batch, P1, NI, NQ, DD,
        (long)NI * DD, (long)NQ * DD, (long)NI * NQ, SCALE, nullptr, nullptr, nullptr);
    softmax_rows<<<BB * NI, 128>>>(P1, q_mask, NI, NQ, nullptr);
    gemm128<false, 0><<<dim3(DD / 128, NI / 128, BB), 256>>>(
        P1, q_batch, iatt, NI, DD, NQ,
        (long)NI * NQ, (long)NQ * DD, (long)NI * DD, 1.f, nullptr, nullptr, nullptr);

    // ---- attention 2: l_feat_att = softmax(q @ i^T * s, mask=i_mask) @ i ----
    gemm128<true, 0><<<dim3(NI / 128, NQ / 128, BB), 256>>>(
        q_batch, i_batch, P2, NQ, NI, DD,
        (long)NQ * DD, (long)NI * DD, (long)NQ * NI, SCALE, nullptr, nullptr, nullptr);
    softmax_rows<<<BB * NQ, 128>>>(P2, i_mask, NQ, NI, nullptr);
    gemm128<false, 0><<<dim3(DD / 128, NQ / 128, BB), 256>>>(
        P2, i_batch, latt, NQ, DD, NI,
        (long)NQ * NI, (long)NI * DD, (long)NQ * DD, 1.f, nullptr, nullptr, nullptr);

    // ---- attflat logits: att = relu(X @ W1 + b1) @ W2 + b2 (fused epilogue) ----
    fill_scalar<<<(BB * NI + 255) / 256, 256>>>(atti, BB * NI, lb2);
    fill_scalar<<<(BB * NQ + 255) / 256, 256>>>(attl, BB * NQ, ib2);
    gemm128<false, 2><<<dim3(DH / 128, (BB * NI) / 128, 1), 256>>>(
        iatt, lW1, nullptr, BB * NI, DH, DD, 0, 0, 0, 1.f, lb1, lW2, atti);
    gemm128<false, 2><<<dim3(DH / 128, (BB * NQ) / 128, 1), 256>>>(
        latt, iW1, nullptr, BB * NQ, DH, DD, 0, 0, 0, 1.f, ib1, iW2, attl);

    // ---- attflat softmax over sequence (i path also emits i_weight) ----
    softmax_rows<<<BB, 128>>>(atti, i_mask, 1, NI, out + 2 * BB * DD);
    softmax_rows<<<BB, 128>>>(attl, q_mask, 1, NQ, nullptr);

    // ---- pooled = sum_m att * X ----
    pool_kernel<<<dim3(DD / 128, BB), 128>>>(iatt, atti, pooli, NI);
    pool_kernel<<<dim3(DD / 128, BB), 128>>>(latt, attl, pooll, NQ);

    // ---- final linears: out = pooled @ Wm + bm ----
    gemm128<false, 0><<<dim3(DD / 128, 1, 1), 256>>>(
        pooli, lWm, out, BB, DD, DD, 0, 0, 0, 1.f, lbm, nullptr, nullptr);
    gemm128<false, 0><<<dim3(DD / 128, 1, 1), 256>>>(
        pooll, iWm, out + BB * DD, BB, DD, DD, 0, 0, 0, 1.f, ibm, nullptr, nullptr);
}

// round 2
// speedup vs baseline: 1.4609x; 1.4609x over previous
#include <cuda_runtime.h>
#include <math.h>
#include <stdint.h>

// Problem dims
#define BB 64
#define NI 512
#define NQ 128
#define DD 640
#define DH 1280
#define NEGV (-65504.0f)

// ---------------- scratch (static __device__ arrays; no allocs) ----------------
__device__ float g_P1[BB * NI * NQ];          // attention-1 probs (64,512,128)
__device__ float g_P2[BB * NQ * NI];          // attention-2 probs (64,128,512)
__device__ float g_iatt[BB * NI * DD];        // attention-1 out   (64,512,640)
__device__ float g_latt[BB * NQ * DD];        // attention-2 out   (64,128,640)
__device__ float g_atti[BB * NI];             // attflat-1 logits/probs
__device__ float g_attl[BB * NQ];             // attflat-2 logits/probs
__device__ float g_pooli[BB * DD];
__device__ float g_pooll[BB * DD];

// ---------------- helpers ----------------
__device__ __forceinline__ float tf32r(float x)
{
    uint32_t u;
    asm("cvt.rna.tf32.f32 %0, %1;" : "=r"(u) : "f"(x));
    return __uint_as_float(u);
}

__device__ __forceinline__ void mma_tf32(float c[4],
                                         uint32_t a0, uint32_t a1, uint32_t a2, uint32_t a3,
                                         uint32_t b0, uint32_t b1)
{
    asm volatile(
        "mma.sync.aligned.m16n8k8.row.col.f32.tf32.tf32.f32 "
        "{%0,%1,%2,%3}, {%4,%5,%6,%7}, {%8,%9}, {%0,%1,%2,%3};"
        : "+f"(c[0]), "+f"(c[1]), "+f"(c[2]), "+f"(c[3])
        : "r"(a0), "r"(a1), "r"(a2), "r"(a3), "r"(b0), "r"(b1));
}

// ---------------- tf32 tensor-core hidden-GEMM with fused attflat-logit epilogue ----
// attOut[m] += sum_n relu( (A @ W1)[m,n] + b1[n] ) * w2[n]
// A: M x 640 fp32 (M multiple of 128), W1: 640 x 1280 fp32.
__global__ __launch_bounds__(256, 2)
void hidden_logits_tf32(const float* __restrict__ A, const float* __restrict__ W1,
                        const float* __restrict__ b1, const float* __restrict__ w2,
                        float* __restrict__ attOut, int M)
{
    __shared__ __align__(16) float As[16][132];
    __shared__ __align__(16) float Bs[16][132];

    const int tid = threadIdx.x;
    const int lane = tid & 31;
    const int wid = tid >> 5;
    const int gid = lane >> 2;          // 0..7
    const int tig = lane & 3;           // 0..3
    const int warp_m = wid & 1;         // 0..1
    const int warp_n = wid >> 1;        // 0..3
    const int m0 = blockIdx.y * 128;
    const int n0 = blockIdx.x * 128;

    float acc[4][4][4];
#pragma unroll
    for (int i = 0; i < 4; i++)
#pragma unroll
        for (int j = 0; j < 4; j++)
#pragma unroll
            for (int r = 0; r < 4; r++) acc[i][j][r] = 0.f;

    for (int k0 = 0; k0 < DD; k0 += 16) {
#pragma unroll
        for (int i = 0; i < 2; i++) {
            int f = tid + i * 256;
            // A tile: 128 rows x 16 k, stored transposed As[k][m]
            int ml = f >> 2;
            int kl = (f & 3) << 2;
            float4 v = *(const float4*)(A + (long)(m0 + ml) * DD + k0 + kl);
            As[kl + 0][ml] = tf32r(v.x);
            As[kl + 1][ml] = tf32r(v.y);
            As[kl + 2][ml] = tf32r(v.z);
            As[kl + 3][ml] = tf32r(v.w);
            // B tile: 16 k x 128 n, Bs[k][n]
            int kb = f >> 5;
            int nb = (f & 31) << 2;
            float4 w = *(const float4*)(W1 + (long)(k0 + kb) * DH + n0 + nb);
            float4 wt;
            wt.x = tf32r(w.x); wt.y = tf32r(w.y);
            wt.z = tf32r(w.z); wt.w = tf32r(w.w);
            *(float4*)&Bs[kb][nb] = wt;
        }
        __syncthreads();

#pragma unroll
        for (int s = 0; s < 2; s++) {
            const int kk = s * 8;
            uint32_t b[4][2];
#pragma unroll
            for (int nt = 0; nt < 4; nt++) {
                int nb = warp_n * 32 + nt * 8 + gid;
                b[nt][0] = __float_as_uint(Bs[kk + tig][nb]);
                b[nt][1] = __float_as_uint(Bs[kk + tig + 4][nb]);
            }
#pragma unroll
            for (int mt = 0; mt < 4; mt++) {
                int mb = warp_m * 64 + mt * 16 + gid;
                uint32_t a0 = __float_as_uint(As[kk + tig][mb]);
                uint32_t a1 = __float_as_uint(As[kk + tig][mb + 8]);
                uint32_t a2 = __float_as_uint(As[kk + tig + 4][mb]);
                uint32_t a3 = __float_as_uint(As[kk + tig + 4][mb + 8]);
#pragma unroll
                for (int nt = 0; nt < 4; nt++)
                    mma_tf32(acc[mt][nt], a0, a1, a2, a3, b[nt][0], b[nt][1]);
            }
        }
        __syncthreads();
    }

    // fused epilogue: logits[m] += sum_n relu(acc + b1[n]) * w2[n]
    float bv[8], wv[8];
#pragma unroll
    for (int nt = 0; nt < 4; nt++)
#pragma unroll
        for (int c = 0; c < 2; c++) {
            int n = n0 + warp_n * 32 + nt * 8 + tig * 2 + c;
            bv[nt * 2 + c] = b1[n];
            wv[nt * 2 + c] = w2[n];
        }
#pragma unroll
    for (int mt = 0; mt < 4; mt++) {
#pragma unroll
        for (int r = 0; r < 2; r++) {
            float s = 0.f;
#pragma unroll
            for (int nt = 0; nt < 4; nt++)
#pragma unroll
                for (int c = 0; c < 2; c++)
                    s += fmaxf(acc[mt][nt][r * 2 + c] + bv[nt * 2 + c], 0.f) * wv[nt * 2 + c];
            s += __shfl_xor_sync(0xffffffffu, s, 1);
            s += __shfl_xor_sync(0xffffffffu, s, 2);
            if (tig == 0) {
                int m = m0 + warp_m * 64 + mt * 16 + r * 8 + gid;
                atomicAdd(attOut + m, s);
            }
        }
    }
}

// ---------------- generic 128x128x16 fp32 SGEMM, 8x8 micro-tile ----------------
template <bool TRANSB>
__global__ __launch_bounds__(256, 2)
void gemm128(const float* __restrict__ A, const float* __restrict__ Bm,
             float* __restrict__ C, int M, int N, int K,
             long sA, long sB, long sC, float alpha,
             const float* __restrict__ bias)
{
    __shared__ __align__(16) float As[16][128];
    __shared__ __align__(16) float Bs[16][128];

    const int zb = blockIdx.z;
    A  += (long)zb * sA;
    Bm += (long)zb * sB;
    C  += (long)zb * sC;

    const int m0  = blockIdx.y * 128;
    const int n0  = blockIdx.x * 128;
    const int tid = threadIdx.x;
    const int tx  = tid & 15;
    const int ty  = tid >> 4;

    float acc[8][8];
#pragma unroll
    for (int i = 0; i < 8; i++)
#pragma unroll
        for (int j = 0; j < 8; j++) acc[i][j] = 0.f;

    for (int k0 = 0; k0 < K; k0 += 16) {
#pragma unroll
        for (int i = 0; i < 2; i++) {
            int f  = tid + i * 256;
            int ml = f >> 2;
            int kl = (f & 3) << 2;
            float4 v = make_float4(0.f, 0.f, 0.f, 0.f);
            if (m0 + ml < M)
                v = *(const float4*)(A + (long)(m0 + ml) * K + (k0 + kl));
            As[kl + 0][ml] = v.x; As[kl + 1][ml] = v.y;
            As[kl + 2][ml] = v.z; As[kl + 3][ml] = v.w;
        }
        if (TRANSB) {
#pragma unroll
            for (int i = 0; i < 2; i++) {
                int f  = tid + i * 256;
                int nl = f >> 2;
                int kl = (f & 3) << 2;
                float4 v = make_float4(0.f, 0.f, 0.f, 0.f);
                if (n0 + nl < N)
                    v = *(const float4*)(Bm + (long)(n0 + nl) * K + (k0 + kl));
                Bs[kl + 0][nl] = v.x; Bs[kl + 1][nl] = v.y;
                Bs[kl + 2][nl] = v.z; Bs[kl + 3][nl] = v.w;
            }
        } else {
#pragma unroll
            for (int i = 0; i < 2; i++) {
                int f  = tid + i * 256;
                int kl = f >> 5;
                int nl = (f & 31) << 2;
                float4 v = make_float4(0.f, 0.f, 0.f, 0.f);
                if (n0 + nl < N)
                    v = *(const float4*)(Bm + (long)(k0 + kl) * N + (n0 + nl));
                *(float4*)&Bs[kl][nl] = v;
            }
        }
        __syncthreads();

#pragma unroll
        for (int kk = 0; kk < 16; kk++) {
            float a[8], b[8];
            *(float4*)&a[0] = *(const float4*)&As[kk][ty * 4];
            *(float4*)&a[4] = *(const float4*)&As[kk][64 + ty * 4];
            *(float4*)&b[0] = *(const float4*)&Bs[kk][tx * 4];
            *(float4*)&b[4] = *(const float4*)&Bs[kk][64 + tx * 4];
#pragma unroll
            for (int i = 0; i < 8; i++)
#pragma unroll
                for (int j = 0; j < 8; j++)
                    acc[i][j] = fmaf(a[i], b[j], acc[i][j]);
        }
        __syncthreads();
    }

#pragma unroll
    for (int i = 0; i < 8; i++) {
        int m = m0 + ((i < 4) ? (ty * 4 + i) : (64 + ty * 4 + i - 4));
        if (m >= M) continue;
#pragma unroll
        for (int g = 0; g < 2; g++) {
            int n = n0 + g * 64 + tx * 4;
            float4 v;
            v.x = acc[i][g * 4 + 0] * alpha;
            v.y = acc[i][g * 4 + 1] * alpha;
            v.z = acc[i][g * 4 + 2] * alpha;
            v.w = acc[i][g * 4 + 3] * alpha;
            if (bias) {
                v.x += bias[n]; v.y += bias[n + 1];
                v.z += bias[n + 2]; v.w += bias[n + 3];
            }
            *(float4*)(C + (long)m * N + n) = v;
        }
    }
}

// ---------------- masked row softmax (in place), optional copy-out ----------------
__device__ __forceinline__ float warpMax(float v)
{
#pragma unroll
    for (int o = 16; o > 0; o >>= 1) v = fmaxf(v, __shfl_xor_sync(0xffffffffu, v, o));
    return v;
}
__device__ __forceinline__ float warpSum(float v)
{
#pragma unroll
    for (int o = 16; o > 0; o >>= 1) v += __shfl_xor_sync(0xffffffffu, v, o);
    return v;
}

__global__ void softmax_rows(float* __restrict__ P,
                             const unsigned int* __restrict__ mask,
                             int rowsPerBatch, int N,
                             float* __restrict__ wout)
{
    const int row = blockIdx.x;
    const int bb  = row / rowsPerBatch;
    float* prow = P + (long)row * N;
    const unsigned int* mrow = mask + (long)bb * N;
    const int tid = threadIdx.x;
    const int cnt = N >> 7;   // 1 or 4

    float v[4];
    float mx = -3.4e38f;
    for (int c = 0; c < cnt; c++) {
        int n = (c << 7) + tid;
        float x = prow[n];
        if (mrow[n] != 0u) x = NEGV;
        v[c] = x;
        mx = fmaxf(mx, x);
    }
    __shared__ float sr[4];
    float wm = warpMax(mx);
    if ((tid & 31) == 0) sr[tid >> 5] = wm;
    __syncthreads();
    mx = fmaxf(fmaxf(sr[0], sr[1]), fmaxf(sr[2], sr[3]));

    float sum = 0.f;
    for (int c = 0; c < cnt; c++) { v[c] = expf(v[c] - mx); sum += v[c]; }
    __syncthreads();
    float ws = warpSum(sum);
    if ((tid & 31) == 0) sr[tid >> 5] = ws;
    __syncthreads();
    sum = sr[0] + sr[1] + sr[2] + sr[3];

    float inv = 1.f / sum;
    for (int c = 0; c < cnt; c++) {
        int n = (c << 7) + tid;
        float r = v[c] * inv;
        prow[n] = r;
        if (wout) wout[(long)row * N + n] = r;
    }
}

// pooled[b, d] = sum_m att[b, m] * X[b, m, d]
__global__ void pool_kernel(const float* __restrict__ X,
                            const float* __restrict__ att,
                            float* __restrict__ pooled, int Nseq)
{
    int bb = blockIdx.y;
    int d  = blockIdx.x * 128 + threadIdx.x;
    const float* Xb = X + (long)bb * Nseq * DD + d;
    const float* ab = att + bb * Nseq;
    float a0 = 0.f, a1 = 0.f, a2 = 0.f, a3 = 0.f;
    for (int m = 0; m < Nseq; m += 4) {
        a0 = fmaf(ab[m + 0], Xb[(long)(m + 0) * DD], a0);
        a1 = fmaf(ab[m + 1], Xb[(long)(m + 1) * DD], a1);
        a2 = fmaf(ab[m + 2], Xb[(long)(m + 2) * DD], a2);
        a3 = fmaf(ab[m + 3], Xb[(long)(m + 3) * DD], a3);
    }
    pooled[bb * DD + d] = (a0 + a1) + (a2 + a3);
}

__global__ void fill_scalar(float* __restrict__ p, int n, const float* __restrict__ s)
{
    int i = blockIdx.x * 256 + threadIdx.x;
    if (i < n) p[i] = *s;
}

// ---------------------------------- launch ----------------------------------
extern "C" void kernel_launch(void* const* d_in, const int* in_sizes, int n_in,
                              void* d_out, int out_size)
{
    const float* i_batch = (const float*)d_in[0];
    const float* q_batch = (const float*)d_in[1];
    const unsigned int* i_mask = (const unsigned int*)d_in[2];
    const unsigned int* q_mask = (const unsigned int*)d_in[3];
    const float* lW1 = (const float*)d_in[4];
    const float* lb1 = (const float*)d_in[5];
    const float* lW2 = (const float*)d_in[6];
    const float* lb2 = (const float*)d_in[7];
    const float* lWm = (const float*)d_in[8];
    const float* lbm = (const float*)d_in[9];
    const float* iW1 = (const float*)d_in[10];
    const float* ib1 = (const float*)d_in[11];
    const float* iW2 = (const float*)d_in[12];
    const float* ib2 = (const float*)d_in[13];
    const float* iWm = (const float*)d_in[14];
    const float* ibm = (const float*)d_in[15];
    float* out = (float*)d_out;

    float *P1, *P2, *iatt, *latt, *atti, *attl, *pooli, *pooll;
    cudaGetSymbolAddress((void**)&P1, g_P1);
    cudaGetSymbolAddress((void**)&P2, g_P2);
    cudaGetSymbolAddress((void**)&iatt, g_iatt);
    cudaGetSymbolAddress((void**)&latt, g_latt);
    cudaGetSymbolAddress((void**)&atti, g_atti);
    cudaGetSymbolAddress((void**)&attl, g_attl);
    cudaGetSymbolAddress((void**)&pooli, g_pooli);
    cudaGetSymbolAddress((void**)&pooll, g_pooll);

    const float SCALE = 0.039528470752104744f;  // 1/sqrt(640)

    // ---- attention 1: i_feat_att = softmax(i @ q^T * s, mask=q_mask) @ q ----
    gemm128<true><<<dim3(NQ / 128, NI / 128, BB), 256>>>(
        i_batch, q_batch, P1, NI, NQ, DD,
        (long)NI * DD, (long)NQ * DD, (long)NI * NQ, SCALE, nullptr);
    softmax_rows<<<BB * NI, 128>>>(P1, q_mask, NI, NQ, nullptr);
    gemm128<false><<<dim3(DD / 128, NI / 128, BB), 256>>>(
        P1, q_batch, iatt, NI, DD, NQ,
        (long)NI * NQ, (long)NQ * DD, (long)NI * DD, 1.f, nullptr);

    // ---- attention 2: l_feat_att = softmax(q @ i^T * s, mask=i_mask) @ i ----
    gemm128<true><<<dim3(NI / 128, NQ / 128, BB), 256>>>(
        q_batch, i_batch, P2, NQ, NI, DD,
        (long)NQ * DD, (long)NI * DD, (long)NQ * NI, SCALE, nullptr);
    softmax_rows<<<BB * NQ, 128>>>(P2, i_mask, NQ, NI, nullptr);
    gemm128<false><<<dim3(DD / 128, NQ / 128, BB), 256>>>(
        P2, i_batch, latt, NQ, DD, NI,
        (long)NQ * NI, (long)NI * DD, (long)NQ * DD, 1.f, nullptr);

    // ---- attflat logits: att = relu(X @ W1 + b1) @ W2 + b2 (tf32 tensor cores) ----
    fill_scalar<<<(BB * NI + 255) / 256, 256>>>(atti, BB * NI, lb2);
    fill_scalar<<<(BB * NQ + 255) / 256, 256>>>(attl, BB * NQ, ib2);
    hidden_logits_tf32<<<dim3(DH / 128, (BB * NI) / 128), 256>>>(
        iatt, lW1, lb1, lW2, atti, BB * NI);
    hidden_logits_tf32<<<dim3(DH / 128, (BB * NQ) / 128), 256>>>(
        latt, iW1, ib1, iW2, attl, BB * NQ);

    // ---- attflat softmax over sequence (i path also emits i_weight) ----
    softmax_rows<<<BB, 128>>>(atti, i_mask, 1, NI, out + 2 * BB * DD);
    softmax_rows<<<BB, 128>>>(attl, q_mask, 1, NQ, nullptr);

    // ---- pooled = sum_m att * X ----
    pool_kernel<<<dim3(DD / 128, BB), 128>>>(iatt, atti, pooli, NI);
    pool_kernel<<<dim3(DD / 128, BB), 128>>>(latt, attl, pooll, NQ);

    // ---- final linears: out = pooled @ Wm + bm ----
    gemm128<false><<<dim3(DD / 128, 1, 1), 256>>>(
        pooli, lWm, out, BB, DD, DD, 0, 0, 0, 1.f, lbm);
    gemm128<false><<<dim3(DD / 128, 1, 1), 256>>>(
        pooll, iWm, out + BB * DD, BB, DD, DD, 0, 0, 0, 1.f, ibm);
}

// round 4
// speedup vs baseline: 3.0108x; 2.0610x over previous
#include <cuda_runtime.h>
#include <cuda_fp16.h>
#include <math.h>
#include <stdint.h>

// Problem dims
#define BB 64
#define NI 512
#define NQ 128
#define DD 640
#define DH 1280
#define NEGV (-65504.0f)

// ---------------- scratch (static __device__ arrays; no allocs) ----------------
__device__ float  g_P1[BB * NI * NQ];
__device__ float  g_P2[BB * NQ * NI];
__device__ float  g_iatt[BB * NI * DD];
__device__ float  g_latt[BB * NQ * DD];
__device__ float  g_atti[BB * NI];
__device__ float  g_attl[BB * NQ];
__device__ float  g_pooli[BB * DD];
__device__ float  g_pooll[BB * DD];
__device__ __half g_ih[BB * NI * DD];     // i_batch fp16
__device__ __half g_qh[BB * NQ * DD];     // q_batch fp16
__device__ __half g_ihT[BB * DD * NI];    // i_batch^T fp16 per batch
__device__ __half g_qhT[BB * DD * NQ];    // q_batch^T fp16 per batch
__device__ __half g_P1h[BB * NI * NQ];    // P1 fp16
__device__ __half g_P2h[BB * NQ * NI];    // P2 fp16
__device__ __half g_iatth[BB * NI * DD];  // iatt fp16
__device__ __half g_latth[BB * NQ * DD];  // latt fp16
__device__ __half g_WT[DH * DD];          // W1^T fp16 [1280,640] (reused per path)

__device__ __forceinline__ uint32_t smem_u32(const void* p)
{
    uint32_t a;
    asm("{ .reg .u64 t; cvta.to.shared.u64 t, %1; cvt.u32.u64 %0, t; }" : "=r"(a) : "l"(p));
    return a;
}

__device__ __forceinline__ void ldmx4(uint32_t r[4], uint32_t addr)
{
    asm volatile("ldmatrix.sync.aligned.m8n8.x4.shared.b16 {%0,%1,%2,%3}, [%4];"
                 : "=r"(r[0]), "=r"(r[1]), "=r"(r[2]), "=r"(r[3]) : "r"(addr));
}

__device__ __forceinline__ void mma_f16(float c[4], const uint32_t a[4],
                                        uint32_t b0, uint32_t b1)
{
    asm volatile(
        "mma.sync.aligned.m16n8k16.row.col.f32.f16.f16.f32 "
        "{%0,%1,%2,%3}, {%4,%5,%6,%7}, {%8,%9}, {%0,%1,%2,%3};"
        : "+f"(c[0]), "+f"(c[1]), "+f"(c[2]), "+f"(c[3])
        : "r"(a[0]), "r"(a[1]), "r"(a[2]), "r"(a[3]), "r"(b0), "r"(b1));
}

// =============== fp16 tensor-core GEMM: C = alpha * A @ BT^T ===============
// A: [M,K] half row-major. BT: [N,K] half row-major (i.e. B transposed).
// EPI 0: store Cf (f32, * alpha)
// EPI 1: store Cf (f32) AND Ch (f16)
// EPI 2: fused attflat logits: attOut[m] += sum_n relu(acc + b1[n]) * w2[n]
// All of M, N divisible by 128; K divisible by 32.
#define SSTR 40   // smem row stride in halves (80B) -> conflict-free ldmatrix
template <int EPI>
__global__ __launch_bounds__(256, 2)
void hgemm(const __half* __restrict__ A, const __half* __restrict__ BT,
           float* __restrict__ Cf, __half* __restrict__ Ch,
           int M, int N, int K, long sA, long sB, long sC,
           float alpha,
           const float* __restrict__ b1, const float* __restrict__ w2,
           float* __restrict__ attOut)
{
    __shared__ __align__(16) __half As[128][SSTR];
    __shared__ __align__(16) __half Bs[128][SSTR];

    const int zb = blockIdx.z;
    A  += (long)zb * sA;
    BT += (long)zb * sB;

    const int tid  = threadIdx.x;
    const int lane = tid & 31;
    const int wid  = tid >> 5;
    const int gid  = lane >> 2, tig = lane & 3;
    const int warp_m = wid & 1, warp_n = wid >> 1;
    const int m0 = blockIdx.y * 128, n0 = blockIdx.x * 128;

    // ---- staging: each thread stores 2x16B to A and B tiles ----
    const int srow = tid >> 2;        // 0..63  (and +64)
    const int skq  = tid & 3;         // 16B unit within 32-half chunk row
    const uint4* Ag0 = (const uint4*)(A + (long)(m0 + srow) * K) + skq;
    const uint4* Ag1 = (const uint4*)(A + (long)(m0 + srow + 64) * K) + skq;
    const uint4* Bg0 = (const uint4*)(BT + (long)(n0 + srow) * K) + skq;
    const uint4* Bg1 = (const uint4*)(BT + (long)(n0 + srow + 64) * K) + skq;
    uint4* sA0 = (uint4*)((char*)&As[srow][0] + skq * 16);
    uint4* sA1 = (uint4*)((char*)&As[srow + 64][0] + skq * 16);
    uint4* sB0 = (uint4*)((char*)&Bs[srow][0] + skq * 16);
    uint4* sB1 = (uint4*)((char*)&Bs[srow + 64][0] + skq * 16);

    // ---- ldmatrix base addresses ----
    // A x4 tile: rows (warp_m*64 + mt*16 + (lane&15)), kbyte = ks*32 + (lane>>4)*16
    const uint32_t aAddr = smem_u32(&As[warp_m * 64 + (lane & 15)][0]) + (lane >> 4) * 16;
    // B x4 tile: rows (warp_n*32 + p*16 + (lane&15)), same k mapping
    const uint32_t bAddr = smem_u32(&Bs[warp_n * 32 + (lane & 15)][0]) + (lane >> 4) * 16;

    float acc[4][4][4];
#pragma unroll
    for (int i = 0; i < 4; i++)
#pragma unroll
        for (int j = 0; j < 4; j++)
#pragma unroll
            for (int r = 0; r < 4; r++) acc[i][j][r] = 0.f;

    const int nc = K >> 5;
    uint4 pa0 = Ag0[0], pa1 = Ag1[0], pb0 = Bg0[0], pb1 = Bg1[0];
    *sA0 = pa0; *sA1 = pa1; *sB0 = pb0; *sB1 = pb1;
    __syncthreads();

#pragma unroll 1
    for (int c = 0; c < nc; ++c) {
        if (c + 1 < nc) {
            pa0 = Ag0[(c + 1) * 4]; pa1 = Ag1[(c + 1) * 4];
            pb0 = Bg0[(c + 1) * 4]; pb1 = Bg1[(c + 1) * 4];
        }
#pragma unroll
        for (int ks = 0; ks < 2; ++ks) {
            uint32_t b[2][4];
            ldmx4(b[0], bAddr + ks * 32);
            ldmx4(b[1], bAddr + 16 * (SSTR * 2) + ks * 32);
#pragma unroll
            for (int mt = 0; mt < 4; ++mt) {
                uint32_t a[4];
                ldmx4(a, aAddr + mt * 16 * (SSTR * 2) + ks * 32);
                // nt: 0->(b[0]:r0,r2) 1->(b[0]:r1,r3) 2->(b[1]:r0,r2) 3->(b[1]:r1,r3)
                mma_f16(acc[mt][0], a, b[0][0], b[0][2]);
                mma_f16(acc[mt][1], a, b[0][1], b[0][3]);
                mma_f16(acc[mt][2], a, b[1][0], b[1][2]);
                mma_f16(acc[mt][3], a, b[1][1], b[1][3]);
            }
        }
        __syncthreads();
        if (c + 1 < nc) {
            *sA0 = pa0; *sA1 = pa1; *sB0 = pb0; *sB1 = pb1;
        }
        __syncthreads();
    }

    if (EPI == 2) {
        float bv[8], wv[8];
#pragma unroll
        for (int nt = 0; nt < 4; nt++)
#pragma unroll
            for (int cc = 0; cc < 2; cc++) {
                int n = n0 + warp_n * 32 + nt * 8 + tig * 2 + cc;
                bv[nt * 2 + cc] = b1[n];
                wv[nt * 2 + cc] = w2[n];
            }
#pragma unroll
        for (int mt = 0; mt < 4; mt++) {
#pragma unroll
            for (int r = 0; r < 2; r++) {
                float s = 0.f;
#pragma unroll
                for (int nt = 0; nt < 4; nt++)
#pragma unroll
                    for (int cc = 0; cc < 2; cc++)
                        s += fmaxf(acc[mt][nt][r * 2 + cc] + bv[nt * 2 + cc], 0.f) * wv[nt * 2 + cc];
                s += __shfl_xor_sync(0xffffffffu, s, 1);
                s += __shfl_xor_sync(0xffffffffu, s, 2);
                if (tig == 0) {
                    int m = m0 + warp_m * 64 + mt * 16 + r * 8 + gid;
                    atomicAdd(attOut + m, s);
                }
            }
        }
    } else {
        Cf += (long)zb * sC;
        if (EPI == 1) Ch += (long)zb * sC;
#pragma unroll
        for (int mt = 0; mt < 4; mt++) {
#pragma unroll
            for (int r = 0; r < 2; r++) {
                long m = m0 + warp_m * 64 + mt * 16 + r * 8 + gid;
#pragma unroll
                for (int nt = 0; nt < 4; nt++) {
                    int n = n0 + warp_n * 32 + nt * 8 + tig * 2;
                    float x = acc[mt][nt][r * 2 + 0] * alpha;
                    float y = acc[mt][nt][r * 2 + 1] * alpha;
                    *(float2*)(Cf + m * N + n) = make_float2(x, y);
                    if (EPI == 1)
                        *(__half2*)(Ch + m * N + n) = __floats2half2_rn(x, y);
                }
            }
        }
    }
}

// ---- f32 [Nseq,DD] -> fp16 same layout + fp16 transposed [DD,Nseq], per batch ----
__global__ void conv_trans(const float* __restrict__ X, __half* __restrict__ Xh,
                           __half* __restrict__ XhT, int Nseq)
{
    __shared__ float t[32][33];
    const long bo = (long)blockIdx.z * Nseq * DD;
    X += bo; Xh += bo; XhT += bo;
    const int d0 = blockIdx.x * 32, s0 = blockIdx.y * 32;
    const int tx = threadIdx.x;
#pragma unroll
    for (int i = threadIdx.y; i < 32; i += 8) {
        float v = X[(long)(s0 + i) * DD + d0 + tx];
        t[i][tx] = v;
        Xh[(long)(s0 + i) * DD + d0 + tx] = __float2half(v);
    }
    __syncthreads();
#pragma unroll
    for (int i = threadIdx.y; i < 32; i += 8)
        XhT[(long)(d0 + i) * Nseq + s0 + tx] = __float2half(t[tx][i]);
}

// ---- W1 (640x1280 f32) -> W1T (1280x640 fp16) ----
__global__ void transpose_h(const float* __restrict__ W, __half* __restrict__ WT)
{
    __shared__ float t[32][33];
    int c0 = blockIdx.x * 32, r0 = blockIdx.y * 32;
#pragma unroll
    for (int i = threadIdx.y; i < 32; i += 8)
        t[i][threadIdx.x] = W[(long)(r0 + i) * DH + c0 + threadIdx.x];
    __syncthreads();
#pragma unroll
    for (int i = threadIdx.y; i < 32; i += 8)
        WT[(long)(c0 + i) * DD + r0 + threadIdx.x] = __float2half(t[threadIdx.x][i]);
}

// ---------------- generic 128x128x16 fp32 SGEMM (small final linears) ----------------
template <bool TRANSB>
__global__ __launch_bounds__(256, 2)
void gemm128(const float* __restrict__ A, const float* __restrict__ Bm,
             float* __restrict__ C, int M, int N, int K,
             long sA, long sB, long sC, float alpha,
             const float* __restrict__ bias)
{
    __shared__ __align__(16) float As[16][128];
    __shared__ __align__(16) float Bs[16][128];

    const int zb = blockIdx.z;
    A  += (long)zb * sA;
    Bm += (long)zb * sB;
    C  += (long)zb * sC;

    const int m0  = blockIdx.y * 128;
    const int n0  = blockIdx.x * 128;
    const int tid = threadIdx.x;
    const int tx  = tid & 15;
    const int ty  = tid >> 4;

    float acc[8][8];
#pragma unroll
    for (int i = 0; i < 8; i++)
#pragma unroll
        for (int j = 0; j < 8; j++) acc[i][j] = 0.f;

    for (int k0 = 0; k0 < K; k0 += 16) {
#pragma unroll
        for (int i = 0; i < 2; i++) {
            int f  = tid + i * 256;
            int ml = f >> 2;
            int kl = (f & 3) << 2;
            float4 v = make_float4(0.f, 0.f, 0.f, 0.f);
            if (m0 + ml < M)
                v = *(const float4*)(A + (long)(m0 + ml) * K + (k0 + kl));
            As[kl + 0][ml] = v.x; As[kl + 1][ml] = v.y;
            As[kl + 2][ml] = v.z; As[kl + 3][ml] = v.w;
        }
        if (TRANSB) {
#pragma unroll
            for (int i = 0; i < 2; i++) {
                int f  = tid + i * 256;
                int nl = f >> 2;
                int kl = (f & 3) << 2;
                float4 v = make_float4(0.f, 0.f, 0.f, 0.f);
                if (n0 + nl < N)
                    v = *(const float4*)(Bm + (long)(n0 + nl) * K + (k0 + kl));
                Bs[kl + 0][nl] = v.x; Bs[kl + 1][nl] = v.y;
                Bs[kl + 2][nl] = v.z; Bs[kl + 3][nl] = v.w;
            }
        } else {
#pragma unroll
            for (int i = 0; i < 2; i++) {
                int f  = tid + i * 256;
                int kl = f >> 5;
                int nl = (f & 31) << 2;
                float4 v = make_float4(0.f, 0.f, 0.f, 0.f);
                if (n0 + nl < N)
                    v = *(const float4*)(Bm + (long)(k0 + kl) * N + (n0 + nl));
                *(float4*)&Bs[kl][nl] = v;
            }
        }
        __syncthreads();

#pragma unroll
        for (int kk = 0; kk < 16; kk++) {
            float a[8], b[8];
            *(float4*)&a[0] = *(const float4*)&As[kk][ty * 4];
            *(float4*)&a[4] = *(const float4*)&As[kk][64 + ty * 4];
            *(float4*)&b[0] = *(const float4*)&Bs[kk][tx * 4];
            *(float4*)&b[4] = *(const float4*)&Bs[kk][64 + tx * 4];
#pragma unroll
            for (int i = 0; i < 8; i++)
#pragma unroll
                for (int j = 0; j < 8; j++)
                    acc[i][j] = fmaf(a[i], b[j], acc[i][j]);
        }
        __syncthreads();
    }

#pragma unroll
    for (int i = 0; i < 8; i++) {
        int m = m0 + ((i < 4) ? (ty * 4 + i) : (64 + ty * 4 + i - 4));
        if (m >= M) continue;
#pragma unroll
        for (int g = 0; g < 2; g++) {
            int n = n0 + g * 64 + tx * 4;
            float4 v;
            v.x = acc[i][g * 4 + 0] * alpha;
            v.y = acc[i][g * 4 + 1] * alpha;
            v.z = acc[i][g * 4 + 2] * alpha;
            v.w = acc[i][g * 4 + 3] * alpha;
            if (bias) {
                v.x += bias[n]; v.y += bias[n + 1];
                v.z += bias[n + 2]; v.w += bias[n + 3];
            }
            *(float4*)(C + (long)m * N + n) = v;
        }
    }
}

// ---------------- masked row softmax ----------------
__device__ __forceinline__ float warpMax(float v)
{
#pragma unroll
    for (int o = 16; o > 0; o >>= 1) v = fmaxf(v, __shfl_xor_sync(0xffffffffu, v, o));
    return v;
}
__device__ __forceinline__ float warpSum(float v)
{
#pragma unroll
    for (int o = 16; o > 0; o >>= 1) v += __shfl_xor_sync(0xffffffffu, v, o);
    return v;
}

// in-place f32 softmax; optional f16 copy (pout) and f32 copy (wout)
__global__ void softmax_rows(float* __restrict__ P,
                             const unsigned int* __restrict__ mask,
                             int rowsPerBatch, int N,
                             __half* __restrict__ pout,
                             float* __restrict__ wout)
{
    const int row = blockIdx.x;
    const int bb  = row / rowsPerBatch;
    float* prow = P + (long)row * N;
    const unsigned int* mrow = mask + (long)bb * N;
    const int tid = threadIdx.x;
    const int cnt = N >> 7;

    float v[4];
    float mx = -3.4e38f;
    for (int c = 0; c < cnt; c++) {
        int n = (c << 7) + tid;
        float x = prow[n];
        if (mrow[n] != 0u) x = NEGV;
        v[c] = x;
        mx = fmaxf(mx, x);
    }
    __shared__ float sr[4];
    float wm = warpMax(mx);
    if ((tid & 31) == 0) sr[tid >> 5] = wm;
    __syncthreads();
    mx = fmaxf(fmaxf(sr[0], sr[1]), fmaxf(sr[2], sr[3]));

    float sum = 0.f;
    for (int c = 0; c < cnt; c++) { v[c] = expf(v[c] - mx); sum += v[c]; }
    __syncthreads();
    float ws = warpSum(sum);
    if ((tid & 31) == 0) sr[tid >> 5] = ws;
    __syncthreads();
    sum = sr[0] + sr[1] + sr[2] + sr[3];

    float inv = 1.f / sum;
    for (int c = 0; c < cnt; c++) {
        int n = (c << 7) + tid;
        float r = v[c] * inv;
        prow[n] = r;
        if (pout) pout[(long)row * N + n] = __float2half(r);
        if (wout) wout[(long)row * N + n] = r;
    }
}

// pooled[b, d] = sum_m att[b, m] * X[b, m, d]
__global__ void pool_kernel(const float* __restrict__ X,
                            const float* __restrict__ att,
                            float* __restrict__ pooled, int Nseq)
{
    int bb = blockIdx.y;
    int d  = blockIdx.x * 128 + threadIdx.x;
    const float* Xb = X + (long)bb * Nseq * DD + d;
    const float* ab = att + bb * Nseq;
    float a0 = 0.f, a1 = 0.f, a2 = 0.f, a3 = 0.f;
    for (int m = 0; m < Nseq; m += 4) {
        a0 = fmaf(ab[m + 0], Xb[(long)(m + 0) * DD], a0);
        a1 = fmaf(ab[m + 1], Xb[(long)(m + 1) * DD], a1);
        a2 = fmaf(ab[m + 2], Xb[(long)(m + 2) * DD], a2);
        a3 = fmaf(ab[m + 3], Xb[(long)(m + 3) * DD], a3);
    }
    pooled[bb * DD + d] = (a0 + a1) + (a2 + a3);
}

__global__ void fill_scalar(float* __restrict__ p, int n, const float* __restrict__ s)
{
    int i = blockIdx.x * 256 + threadIdx.x;
    if (i < n) p[i] = *s;
}

// ---------------------------------- launch ----------------------------------
extern "C" void kernel_launch(void* const* d_in, const int* in_sizes, int n_in,
                              void* d_out, int out_size)
{
    const float* i_batch = (const float*)d_in[0];
    const float* q_batch = (const float*)d_in[1];
    const unsigned int* i_mask = (const unsigned int*)d_in[2];
    const unsigned int* q_mask = (const unsigned int*)d_in[3];
    const float* lW1 = (const float*)d_in[4];
    const float* lb1 = (const float*)d_in[5];
    const float* lW2 = (const float*)d_in[6];
    const float* lb2 = (const float*)d_in[7];
    const float* lWm = (const float*)d_in[8];
    const float* lbm = (const float*)d_in[9];
    const float* iW1 = (const float*)d_in[10];
    const float* ib1 = (const float*)d_in[11];
    const float* iW2 = (const float*)d_in[12];
    const float* ib2 = (const float*)d_in[13];
    const float* iWm = (const float*)d_in[14];
    const float* ibm = (const float*)d_in[15];
    float* out = (float*)d_out;

    float *P1, *P2, *iatt, *latt, *atti, *attl, *pooli, *pooll;
    __half *ih, *qh, *ihT, *qhT, *P1h, *P2h, *iatth, *latth, *WT;
    cudaGetSymbolAddress((void**)&P1, g_P1);
    cudaGetSymbolAddress((void**)&P2, g_P2);
    cudaGetSymbolAddress((void**)&iatt, g_iatt);
    cudaGetSymbolAddress((void**)&latt, g_latt);
    cudaGetSymbolAddress((void**)&atti, g_atti);
    cudaGetSymbolAddress((void**)&attl, g_attl);
    cudaGetSymbolAddress((void**)&pooli, g_pooli);
    cudaGetSymbolAddress((void**)&pooll, g_pooll);
    cudaGetSymbolAddress((void**)&ih, g_ih);
    cudaGetSymbolAddress((void**)&qh, g_qh);
    cudaGetSymbolAddress((void**)&ihT, g_ihT);
    cudaGetSymbolAddress((void**)&qhT, g_qhT);
    cudaGetSymbolAddress((void**)&P1h, g_P1h);
    cudaGetSymbolAddress((void**)&P2h, g_P2h);
    cudaGetSymbolAddress((void**)&iatth, g_iatth);
    cudaGetSymbolAddress((void**)&latth, g_latth);
    cudaGetSymbolAddress((void**)&WT, g_WT);

    const float SCALE = 0.039528470752104744f;  // 1/sqrt(640)

    // ---- fp16 conversions + per-batch transposes ----
    conv_trans<<<dim3(DD / 32, NI / 32, BB), dim3(32, 8)>>>(i_batch, ih, ihT, NI);
    conv_trans<<<dim3(DD / 32, NQ / 32, BB), dim3(32, 8)>>>(q_batch, qh, qhT, NQ);

    // ---- attention 1: P1 = softmax(i @ q^T * s, q_mask); iatt = P1 @ q ----
    hgemm<0><<<dim3(NQ / 128, NI / 128, BB), 256>>>(
        ih, qh, P1, nullptr, NI, NQ, DD,
        (long)NI * DD, (long)NQ * DD, (long)NI * NQ, SCALE, nullptr, nullptr, nullptr);
    softmax_rows<<<BB * NI, 128>>>(P1, q_mask, NI, NQ, P1h, nullptr);
    hgemm<1><<<dim3(DD / 128, NI / 128, BB), 256>>>(
        P1h, qhT, iatt, iatth, NI, DD, NQ,
        (long)NI * NQ, (long)DD * NQ, (long)NI * DD, 1.f, nullptr, nullptr, nullptr);

    // ---- attention 2: P2 = softmax(q @ i^T * s, i_mask); latt = P2 @ i ----
    hgemm<0><<<dim3(NI / 128, NQ / 128, BB), 256>>>(
        qh, ih, P2, nullptr, NQ, NI, DD,
        (long)NQ * DD, (long)NI * DD, (long)NQ * NI, SCALE, nullptr, nullptr, nullptr);
    softmax_rows<<<BB * NQ, 128>>>(P2, i_mask, NQ, NI, P2h, nullptr);
    hgemm<1><<<dim3(DD / 128, NQ / 128, BB), 256>>>(
        P2h, ihT, latt, latth, NQ, DD, NI,
        (long)NQ * NI, (long)DD * NI, (long)NQ * DD, 1.f, nullptr, nullptr, nullptr);

    // ---- attflat logits: relu(X @ W1 + b1) @ W2 + b2 (fp16 tensor cores) ----
    fill_scalar<<<(BB * NI + 255) / 256, 256>>>(atti, BB * NI, lb2);
    fill_scalar<<<(BB * NQ + 255) / 256, 256>>>(attl, BB * NQ, ib2);

    transpose_h<<<dim3(DH / 32, DD / 32), dim3(32, 8)>>>(lW1, WT);
    hgemm<2><<<dim3(DH / 128, (BB * NI) / 128, 1), 256>>>(
        iatth, WT, nullptr, nullptr, BB * NI, DH, DD, 0, 0, 0, 1.f, lb1, lW2, atti);

    transpose_h<<<dim3(DH / 32, DD / 32), dim3(32, 8)>>>(iW1, WT);
    hgemm<2><<<dim3(DH / 128, (BB * NQ) / 128, 1), 256>>>(
        latth, WT, nullptr, nullptr, BB * NQ, DH, DD, 0, 0, 0, 1.f, ib1, iW2, attl);

    // ---- attflat softmax over sequence (i path also emits i_weight) ----
    softmax_rows<<<BB, 128>>>(atti, i_mask, 1, NI, nullptr, out + 2 * BB * DD);
    softmax_rows<<<BB, 128>>>(attl, q_mask, 1, NQ, nullptr, nullptr);

    // ---- pooled = sum_m att * X ----
    pool_kernel<<<dim3(DD / 128, BB), 128>>>(iatt, atti, pooli, NI);
    pool_kernel<<<dim3(DD / 128, BB), 128>>>(latt, attl, pooll, NQ);

    // ---- final linears: out = pooled @ Wm + bm (tiny, fp32) ----
    gemm128<false><<<dim3(DD / 128, 1, 1), 256>>>(
        pooli, lWm, out, BB, DD, DD, 0, 0, 0, 1.f, lbm);
    gemm128<false><<<dim3(DD / 128, 1, 1), 256>>>(
        pooll, iWm, out + BB * DD, BB, DD, DD, 0, 0, 0, 1.f, ibm);
}

// round 5
// speedup vs baseline: 3.0832x; 1.0240x over previous
#include <cuda_runtime.h>
#include <cuda_fp16.h>
#include <math.h>
#include <stdint.h>

// Problem dims
#define BB 64
#define NI 512
#define NQ 128
#define DD 640
#define DH 1280
#define NEGV (-65504.0f)

// ---------------- scratch (static __device__ arrays; no allocs) ----------------
__device__ float  g_S[BB * NI * NQ];      // raw scores (64,512,128)
__device__ float  g_ST[BB * NQ * NI];     // scores transposed (64,128,512)
__device__ float  g_iatt[BB * NI * DD];
__device__ float  g_latt[BB * NQ * DD];
__device__ float  g_atti[BB * NI];
__device__ float  g_attl[BB * NQ];
__device__ float  g_pooli[BB * DD];
__device__ float  g_pooll[BB * DD];
__device__ __half g_ih[BB * NI * DD];
__device__ __half g_qh[BB * NQ * DD];
__device__ __half g_ihT[BB * DD * NI];
__device__ __half g_qhT[BB * DD * NQ];
__device__ __half g_P1h[BB * NI * NQ];
__device__ __half g_P2h[BB * NQ * NI];
__device__ __half g_iatth[BB * NI * DD];
__device__ __half g_latth[BB * NQ * DD];
__device__ __half g_WT[DH * DD];

__device__ __forceinline__ uint32_t smem_u32(const void* p)
{
    uint32_t a;
    asm("{ .reg .u64 t; cvta.to.shared.u64 t, %1; cvt.u32.u64 %0, t; }" : "=r"(a) : "l"(p));
    return a;
}
__device__ __forceinline__ void ldmx4(uint32_t r[4], uint32_t addr)
{
    asm volatile("ldmatrix.sync.aligned.m8n8.x4.shared.b16 {%0,%1,%2,%3}, [%4];"
                 : "=r"(r[0]), "=r"(r[1]), "=r"(r[2]), "=r"(r[3]) : "r"(addr));
}
__device__ __forceinline__ void mma_f16(float c[4], const uint32_t a[4],
                                        uint32_t b0, uint32_t b1)
{
    asm volatile(
        "mma.sync.aligned.m16n8k16.row.col.f32.f16.f16.f32 "
        "{%0,%1,%2,%3}, {%4,%5,%6,%7}, {%8,%9}, {%0,%1,%2,%3};"
        : "+f"(c[0]), "+f"(c[1]), "+f"(c[2]), "+f"(c[3])
        : "r"(a[0]), "r"(a[1]), "r"(a[2]), "r"(a[3]), "r"(b0), "r"(b1));
}
__device__ __forceinline__ void cp16(uint32_t dst, const void* src)
{
    asm volatile("cp.async.cg.shared.global [%0], [%1], 16;" :: "r"(dst), "l"(src));
}
#define CP_COMMIT() asm volatile("cp.async.commit_group;" ::: "memory")
#define CP_WAIT1()  asm volatile("cp.async.wait_group 1;" ::: "memory")

// =============== fp16 tensor-core GEMM: C = alpha * A @ BT^T ===============
// A: [M,K] half row-major. BT: [N,K] half row-major. M,N %128==0, K %32==0.
// EPI 0: store Cf (f32 * alpha); EPI 1: store Cf (f32) AND Ch (f16);
// EPI 2: fused attflat logits: attOut[m] += sum_n relu(acc + b1[n]) * w2[n]
#define SSTR 40                      // smem row stride in halves (80B)
#define STAGE_B (128 * SSTR * 2)     // one tile: 10240 B
#define STAGE2_B (2 * STAGE_B)       // A+B per stage: 20480 B
#define HG_SMEM (3 * STAGE2_B)       // 3 stages: 61440 B
template <int EPI>
__global__ __launch_bounds__(256, 2)
void hgemm(const __half* __restrict__ A, const __half* __restrict__ BT,
           float* __restrict__ Cf, __half* __restrict__ Ch,
           int M, int N, int K, long sA, long sB, long sC,
           float alpha,
           const float* __restrict__ b1, const float* __restrict__ w2,
           float* __restrict__ attOut)
{
    extern __shared__ __align__(16) char smx[];
    const uint32_t smb = smem_u32(smx);

    const int zb = blockIdx.z;
    A  += (long)zb * sA;
    BT += (long)zb * sB;

    const int tid  = threadIdx.x;
    const int lane = tid & 31;
    const int wid  = tid >> 5;
    const int gid  = lane >> 2, tig = lane & 3;
    const int warp_m = wid & 1, warp_n = wid >> 1;
    const int m0 = blockIdx.y * 128, n0 = blockIdx.x * 128;

    // per-thread staging coords: rows srow, srow+64; 16B unit skq within 64B chunk row
    const int srow = tid >> 2;
    const int skq  = tid & 3;
    const __half* Ag0 = A + (long)(m0 + srow) * K + skq * 8;
    const __half* Ag1 = A + (long)(m0 + srow + 64) * K + skq * 8;
    const __half* Bg0 = BT + (long)(n0 + srow) * K + skq * 8;
    const __half* Bg1 = BT + (long)(n0 + srow + 64) * K + skq * 8;
    const uint32_t dA0 = srow * (SSTR * 2) + skq * 16;
    const uint32_t dA1 = (srow + 64) * (SSTR * 2) + skq * 16;

    // ldmatrix row offsets (within a stage)
    const uint32_t aRowOff = (warp_m * 64 + (lane & 15)) * (SSTR * 2) + (lane >> 4) * 16;
    const uint32_t bRowOff = STAGE_B + (warp_n * 32 + (lane & 15)) * (SSTR * 2) + (lane >> 4) * 16;

    float acc[4][4][4];
#pragma unroll
    for (int i = 0; i < 4; i++)
#pragma unroll
        for (int j = 0; j < 4; j++)
#pragma unroll
            for (int r = 0; r < 4; r++) acc[i][j][r] = 0.f;

    const int nc = K >> 5;

    // prologue: issue chunks 0 and 1
#pragma unroll
    for (int p = 0; p < 2; ++p) {
        const uint32_t sb = smb + p * STAGE2_B;
        cp16(sb + dA0, Ag0 + p * 32);
        cp16(sb + dA1, Ag1 + p * 32);
        cp16(sb + STAGE_B + dA0, Bg0 + p * 32);
        cp16(sb + STAGE_B + dA1, Bg1 + p * 32);
        CP_COMMIT();
    }

#pragma unroll 1
    for (int c = 0; c < nc; ++c) {
        CP_WAIT1();
        __syncthreads();
        // issue chunk c+2 into buffer (c+2)%3
        if (c + 2 < nc) {
            const int st = (c + 2) % 3;
            const uint32_t sb = smb + st * STAGE2_B;
            cp16(sb + dA0, Ag0 + (c + 2) * 32);
            cp16(sb + dA1, Ag1 + (c + 2) * 32);
            cp16(sb + STAGE_B + dA0, Bg0 + (c + 2) * 32);
            cp16(sb + STAGE_B + dA1, Bg1 + (c + 2) * 32);
        }
        CP_COMMIT();

        // compute chunk c from buffer c%3
        const uint32_t sb = smb + (c % 3) * STAGE2_B;
        const uint32_t aB = sb + aRowOff;
        const uint32_t bB = sb + bRowOff;
#pragma unroll
        for (int ks = 0; ks < 2; ++ks) {
            uint32_t b[2][4];
            ldmx4(b[0], bB + ks * 32);
            ldmx4(b[1], bB + 16 * (SSTR * 2) + ks * 32);
#pragma unroll
            for (int mt = 0; mt < 4; ++mt) {
                uint32_t a[4];
                ldmx4(a, aB + mt * 16 * (SSTR * 2) + ks * 32);
                mma_f16(acc[mt][0], a, b[0][0], b[0][2]);
                mma_f16(acc[mt][1], a, b[0][1], b[0][3]);
                mma_f16(acc[mt][2], a, b[1][0], b[1][2]);
                mma_f16(acc[mt][3], a, b[1][1], b[1][3]);
            }
        }
        __syncthreads();
    }

    if (EPI == 2) {
        float bv[8], wv[8];
#pragma unroll
        for (int nt = 0; nt < 4; nt++)
#pragma unroll
            for (int cc = 0; cc < 2; cc++) {
                int n = n0 + warp_n * 32 + nt * 8 + tig * 2 + cc;
                bv[nt * 2 + cc] = b1[n];
                wv[nt * 2 + cc] = w2[n];
            }
#pragma unroll
        for (int mt = 0; mt < 4; mt++) {
#pragma unroll
            for (int r = 0; r < 2; r++) {
                float s = 0.f;
#pragma unroll
                for (int nt = 0; nt < 4; nt++)
#pragma unroll
                    for (int cc = 0; cc < 2; cc++)
                        s += fmaxf(acc[mt][nt][r * 2 + cc] + bv[nt * 2 + cc], 0.f) * wv[nt * 2 + cc];
                s += __shfl_xor_sync(0xffffffffu, s, 1);
                s += __shfl_xor_sync(0xffffffffu, s, 2);
                if (tig == 0) {
                    int m = m0 + warp_m * 64 + mt * 16 + r * 8 + gid;
                    atomicAdd(attOut + m, s);
                }
            }
        }
    } else {
        Cf += (long)zb * sC;
        if (EPI == 1) Ch += (long)zb * sC;
#pragma unroll
        for (int mt = 0; mt < 4; mt++) {
#pragma unroll
            for (int r = 0; r < 2; r++) {
                long m = m0 + warp_m * 64 + mt * 16 + r * 8 + gid;
#pragma unroll
                for (int nt = 0; nt < 4; nt++) {
                    int n = n0 + warp_n * 32 + nt * 8 + tig * 2;
                    float x = acc[mt][nt][r * 2 + 0] * alpha;
                    float y = acc[mt][nt][r * 2 + 1] * alpha;
                    *(float2*)(Cf + m * N + n) = make_float2(x, y);
                    if (EPI == 1)
                        *(__half2*)(Ch + m * N + n) = __floats2half2_rn(x, y);
                }
            }
        }
    }
}

// ---- f32 [Nseq,DD] -> fp16 same layout + fp16 transposed [DD,Nseq], per batch ----
__global__ void conv_trans(const float* __restrict__ X, __half* __restrict__ Xh,
                           __half* __restrict__ XhT, int Nseq)
{
    __shared__ float t[32][33];
    const long bo = (long)blockIdx.z * Nseq * DD;
    X += bo; Xh += bo; XhT += bo;
    const int d0 = blockIdx.x * 32, s0 = blockIdx.y * 32;
    const int tx = threadIdx.x;
#pragma unroll
    for (int i = threadIdx.y; i < 32; i += 8) {
        float v = X[(long)(s0 + i) * DD + d0 + tx];
        t[i][tx] = v;
        Xh[(long)(s0 + i) * DD + d0 + tx] = __float2half(v);
    }
    __syncthreads();
#pragma unroll
    for (int i = threadIdx.y; i < 32; i += 8)
        XhT[(long)(d0 + i) * Nseq + s0 + tx] = __float2half(t[tx][i]);
}

// ---- per-batch f32 transpose: X [R,C] -> XT [C,R] ----
__global__ void transpose_f32(const float* __restrict__ X, float* __restrict__ XT,
                              int R, int C)
{
    __shared__ float t[32][33];
    const long bo = (long)blockIdx.z * R * C;
    const int c0 = blockIdx.x * 32, r0 = blockIdx.y * 32;
    const int tx = threadIdx.x;
#pragma unroll
    for (int i = threadIdx.y; i < 32; i += 8)
        t[i][tx] = X[bo + (long)(r0 + i) * C + c0 + tx];
    __syncthreads();
#pragma unroll
    for (int i = threadIdx.y; i < 32; i += 8)
        XT[bo + (long)(c0 + i) * R + r0 + tx] = t[tx][i];
}

// ---- W1 (640x1280 f32) -> W1T (1280x640 fp16) ----
__global__ void transpose_h(const float* __restrict__ W, __half* __restrict__ WT)
{
    __shared__ float t[32][33];
    int c0 = blockIdx.x * 32, r0 = blockIdx.y * 32;
#pragma unroll
    for (int i = threadIdx.y; i < 32; i += 8)
        t[i][threadIdx.x] = W[(long)(r0 + i) * DH + c0 + threadIdx.x];
    __syncthreads();
#pragma unroll
    for (int i = threadIdx.y; i < 32; i += 8)
        WT[(long)(c0 + i) * DD + r0 + threadIdx.x] = __float2half(t[threadIdx.x][i]);
}

// ---------------- generic fp32 SGEMM (small final linears only) ----------------
__global__ __launch_bounds__(256, 2)
void gemm128(const float* __restrict__ A, const float* __restrict__ Bm,
             float* __restrict__ C, int M, int N, int K,
             const float* __restrict__ bias)
{
    __shared__ __align__(16) float As[16][128];
    __shared__ __align__(16) float Bs[16][128];

    const int m0  = blockIdx.y * 128;
    const int n0  = blockIdx.x * 128;
    const int tid = threadIdx.x;
    const int tx  = tid & 15;
    const int ty  = tid >> 4;

    float acc[8][8];
#pragma unroll
    for (int i = 0; i < 8; i++)
#pragma unroll
        for (int j = 0; j < 8; j++) acc[i][j] = 0.f;

    for (int k0 = 0; k0 < K; k0 += 16) {
#pragma unroll
        for (int i = 0; i < 2; i++) {
            int f  = tid + i * 256;
            int ml = f >> 2;
            int kl = (f & 3) << 2;
            float4 v = make_float4(0.f, 0.f, 0.f, 0.f);
            if (m0 + ml < M)
                v = *(const float4*)(A + (long)(m0 + ml) * K + (k0 + kl));
            As[kl + 0][ml] = v.x; As[kl + 1][ml] = v.y;
            As[kl + 2][ml] = v.z; As[kl + 3][ml] = v.w;
        }
#pragma unroll
        for (int i = 0; i < 2; i++) {
            int f  = tid + i * 256;
            int kl = f >> 5;
            int nl = (f & 31) << 2;
            float4 v = make_float4(0.f, 0.f, 0.f, 0.f);
            if (n0 + nl < N)
                v = *(const float4*)(Bm + (long)(k0 + kl) * N + (n0 + nl));
            *(float4*)&Bs[kl][nl] = v;
        }
        __syncthreads();

#pragma unroll
        for (int kk = 0; kk < 16; kk++) {
            float a[8], b[8];
            *(float4*)&a[0] = *(const float4*)&As[kk][ty * 4];
            *(float4*)&a[4] = *(const float4*)&As[kk][64 + ty * 4];
            *(float4*)&b[0] = *(const float4*)&Bs[kk][tx * 4];
            *(float4*)&b[4] = *(const float4*)&Bs[kk][64 + tx * 4];
#pragma unroll
            for (int i = 0; i < 8; i++)
#pragma unroll
                for (int j = 0; j < 8; j++)
                    acc[i][j] = fmaf(a[i], b[j], acc[i][j]);
        }
        __syncthreads();
    }

#pragma unroll
    for (int i = 0; i < 8; i++) {
        int m = m0 + ((i < 4) ? (ty * 4 + i) : (64 + ty * 4 + i - 4));
        if (m >= M) continue;
#pragma unroll
        for (int g = 0; g < 2; g++) {
            int n = n0 + g * 64 + tx * 4;
            float4 v;
            v.x = acc[i][g * 4 + 0] + bias[n];
            v.y = acc[i][g * 4 + 1] + bias[n + 1];
            v.z = acc[i][g * 4 + 2] + bias[n + 2];
            v.w = acc[i][g * 4 + 3] + bias[n + 3];
            *(float4*)(C + (long)m * N + n) = v;
        }
    }
}

// ---------------- masked row softmax ----------------
__device__ __forceinline__ float warpMax(float v)
{
#pragma unroll
    for (int o = 16; o > 0; o >>= 1) v = fmaxf(v, __shfl_xor_sync(0xffffffffu, v, o));
    return v;
}
__device__ __forceinline__ float warpSum(float v)
{
#pragma unroll
    for (int o = 16; o > 0; o >>= 1) v += __shfl_xor_sync(0xffffffffu, v, o);
    return v;
}

__global__ void softmax_rows(float* __restrict__ P,
                             const unsigned int* __restrict__ mask,
                             int rowsPerBatch, int N,
                             __half* __restrict__ pout,
                             float* __restrict__ wout)
{
    const int row = blockIdx.x;
    const int bb  = row / rowsPerBatch;
    float* prow = P + (long)row * N;
    const unsigned int* mrow = mask + (long)bb * N;
    const int tid = threadIdx.x;
    const int cnt = N >> 7;

    float v[4];
    float mx = -3.4e38f;
    for (int c = 0; c < cnt; c++) {
        int n = (c << 7) + tid;
        float x = prow[n];
        if (mrow[n] != 0u) x = NEGV;
        v[c] = x;
        mx = fmaxf(mx, x);
    }
    __shared__ float sr[4];
    float wm = warpMax(mx);
    if ((tid & 31) == 0) sr[tid >> 5] = wm;
    __syncthreads();
    mx = fmaxf(fmaxf(sr[0], sr[1]), fmaxf(sr[2], sr[3]));

    float sum = 0.f;
    for (int c = 0; c < cnt; c++) { v[c] = expf(v[c] - mx); sum += v[c]; }
    __syncthreads();
    float ws = warpSum(sum);
    if ((tid & 31) == 0) sr[tid >> 5] = ws;
    __syncthreads();
    sum = sr[0] + sr[1] + sr[2] + sr[3];

    float inv = 1.f / sum;
    for (int c = 0; c < cnt; c++) {
        int n = (c << 7) + tid;
        float r = v[c] * inv;
        if (pout) pout[(long)row * N + n] = __float2half(r);
        else      prow[n] = r;
        if (wout) wout[(long)row * N + n] = r;
    }
}

// pooled[b, d] = sum_m att[b, m] * X[b, m, d]
__global__ void pool_kernel(const float* __restrict__ X,
                            const float* __restrict__ att,
                            float* __restrict__ pooled, int Nseq)
{
    int bb = blockIdx.y;
    int d  = blockIdx.x * 128 + threadIdx.x;
    const float* Xb = X + (long)bb * Nseq * DD + d;
    const float* ab = att + bb * Nseq;
    float a0 = 0.f, a1 = 0.f, a2 = 0.f, a3 = 0.f;
    for (int m = 0; m < Nseq; m += 4) {
        a0 = fmaf(ab[m + 0], Xb[(long)(m + 0) * DD], a0);
        a1 = fmaf(ab[m + 1], Xb[(long)(m + 1) * DD], a1);
        a2 = fmaf(ab[m + 2], Xb[(long)(m + 2) * DD], a2);
        a3 = fmaf(ab[m + 3], Xb[(long)(m + 3) * DD], a3);
    }
    pooled[bb * DD + d] = (a0 + a1) + (a2 + a3);
}

__global__ void fill_scalar(float* __restrict__ p, int n, const float* __restrict__ s)
{
    int i = blockIdx.x * 256 + threadIdx.x;
    if (i < n) p[i] = *s;
}

// ---------------------------------- launch ----------------------------------
extern "C" void kernel_launch(void* const* d_in, const int* in_sizes, int n_in,
                              void* d_out, int out_size)
{
    const float* i_batch = (const float*)d_in[0];
    const float* q_batch = (const float*)d_in[1];
    const unsigned int* i_mask = (const unsigned int*)d_in[2];
    const unsigned int* q_mask = (const unsigned int*)d_in[3];
    const float* lW1 = (const float*)d_in[4];
    const float* lb1 = (const float*)d_in[5];
    const float* lW2 = (const float*)d_in[6];
    const float* lb2 = (const float*)d_in[7];
    const float* lWm = (const float*)d_in[8];
    const float* lbm = (const float*)d_in[9];
    const float* iW1 = (const float*)d_in[10];
    const float* ib1 = (const float*)d_in[11];
    const float* iW2 = (const float*)d_in[12];
    const float* ib2 = (const float*)d_in[13];
    const float* iWm = (const float*)d_in[14];
    const float* ibm = (const float*)d_in[15];
    float* out = (float*)d_out;

    float *S, *ST, *iatt, *latt, *atti, *attl, *pooli, *pooll;
    __half *ih, *qh, *ihT, *qhT, *P1h, *P2h, *iatth, *latth, *WT;
    cudaGetSymbolAddress((void**)&S, g_S);
    cudaGetSymbolAddress((void**)&ST, g_ST);
    cudaGetSymbolAddress((void**)&iatt, g_iatt);
    cudaGetSymbolAddress((void**)&latt, g_latt);
    cudaGetSymbolAddress((void**)&atti, g_atti);
    cudaGetSymbolAddress((void**)&attl, g_attl);
    cudaGetSymbolAddress((void**)&pooli, g_pooli);
    cudaGetSymbolAddress((void**)&pooll, g_pooll);
    cudaGetSymbolAddress((void**)&ih, g_ih);
    cudaGetSymbolAddress((void**)&qh, g_qh);
    cudaGetSymbolAddress((void**)&ihT, g_ihT);
    cudaGetSymbolAddress((void**)&qhT, g_qhT);
    cudaGetSymbolAddress((void**)&P1h, g_P1h);
    cudaGetSymbolAddress((void**)&P2h, g_P2h);
    cudaGetSymbolAddress((void**)&iatth, g_iatth);
    cudaGetSymbolAddress((void**)&latth, g_latth);
    cudaGetSymbolAddress((void**)&WT, g_WT);

    cudaFuncSetAttribute(hgemm<0>, cudaFuncAttributeMaxDynamicSharedMemorySize, HG_SMEM);
    cudaFuncSetAttribute(hgemm<1>, cudaFuncAttributeMaxDynamicSharedMemorySize, HG_SMEM);
    cudaFuncSetAttribute(hgemm<2>, cudaFuncAttributeMaxDynamicSharedMemorySize, HG_SMEM);

    const float SCALE = 0.039528470752104744f;  // 1/sqrt(640)

    // ---- fp16 conversions + per-batch transposes ----
    conv_trans<<<dim3(DD / 32, NI / 32, BB), dim3(32, 8)>>>(i_batch, ih, ihT, NI);
    conv_trans<<<dim3(DD / 32, NQ / 32, BB), dim3(32, 8)>>>(q_batch, qh, qhT, NQ);

    // ---- scores computed ONCE: S = i @ q^T * scale  (S^T serves attention 2) ----
    hgemm<0><<<dim3(NQ / 128, NI / 128, BB), 256, HG_SMEM>>>(
        ih, qh, S, nullptr, NI, NQ, DD,
        (long)NI * DD, (long)NQ * DD, (long)NI * NQ, SCALE, nullptr, nullptr, nullptr);
    transpose_f32<<<dim3(NQ / 32, NI / 32, BB), dim3(32, 8)>>>(S, ST, NI, NQ);

    // ---- attention 1: P1 = softmax(S, q_mask); iatt = P1 @ q ----
    softmax_rows<<<BB * NI, 128>>>(S, q_mask, NI, NQ, P1h, nullptr);
    hgemm<1><<<dim3(DD / 128, NI / 128, BB), 256, HG_SMEM>>>(
        P1h, qhT, iatt, iatth, NI, DD, NQ,
        (long)NI * NQ, (long)DD * NQ, (long)NI * DD, 1.f, nullptr, nullptr, nullptr);

    // ---- attention 2: P2 = softmax(S^T, i_mask); latt = P2 @ i ----
    softmax_rows<<<BB * NQ, 128>>>(ST, i_mask, NQ, NI, P2h, nullptr);
    hgemm<1><<<dim3(DD / 128, NQ / 128, BB), 256, HG_SMEM>>>(
        P2h, ihT, latt, latth, NQ, DD, NI,
        (long)NQ * NI, (long)DD * NI, (long)NQ * DD, 1.f, nullptr, nullptr, nullptr);

    // ---- attflat logits: relu(X @ W1 + b1) @ W2 + b2 ----
    fill_scalar<<<(BB * NI + 255) / 256, 256>>>(atti, BB * NI, lb2);
    fill_scalar<<<(BB * NQ + 255) / 256, 256>>>(attl, BB * NQ, ib2);

    transpose_h<<<dim3(DH / 32, DD / 32), dim3(32, 8)>>>(lW1, WT);
    hgemm<2><<<dim3(DH / 128, (BB * NI) / 128, 1), 256, HG_SMEM>>>(
        iatth, WT, nullptr, nullptr, BB * NI, DH, DD, 0, 0, 0, 1.f, lb1, lW2, atti);

    transpose_h<<<dim3(DH / 32, DD / 32), dim3(32, 8)>>>(iW1, WT);
    hgemm<2><<<dim3(DH / 128, (BB * NQ) / 128, 1), 256, HG_SMEM>>>(
        latth, WT, nullptr, nullptr, BB * NQ, DH, DD, 0, 0, 0, 1.f, ib1, iW2, attl);

    // ---- attflat softmax over sequence (i path emits i_weight) ----
    softmax_rows<<<BB, 128>>>(atti, i_mask, 1, NI, nullptr, out + 2 * BB * DD);
    softmax_rows<<<BB, 128>>>(attl, q_mask, 1, NQ, nullptr, nullptr);

    // ---- pooled = sum_m att * X ----
    pool_kernel<<<dim3(DD / 128, BB), 128>>>(iatt, atti, pooli, NI);
    pool_kernel<<<dim3(DD / 128, BB), 128>>>(latt, attl, pooll, NQ);

    // ---- final linears ----
    gemm128<<<dim3(DD / 128, 1, 1), 256>>>(pooli, lWm, out, BB, DD, DD, lbm);
    gemm128<<<dim3(DD / 128, 1, 1), 256>>>(pooll, iWm, out + BB * DD, BB, DD, DD, ibm);
}

// round 6
// speedup vs baseline: 3.1935x; 1.0358x over previous
#include <cuda_runtime.h>
#include <cuda_fp16.h>
#include <math.h>
#include <stdint.h>

// Problem dims
#define BB 64
#define NI 512
#define NQ 128
#define DD 640
#define DH 1280
#define NEGV (-65504.0f)

// ---------------- scratch (static __device__ arrays; no allocs) ----------------
__device__ float  g_S[BB * NI * NQ];      // raw scores (64,512,128)
__device__ float  g_ST[BB * NQ * NI];     // scores transposed (64,128,512)
__device__ float  g_iatt[BB * NI * DD];
__device__ float  g_latt[BB * NQ * DD];
__device__ float  g_atti[BB * NI];
__device__ float  g_attl[BB * NQ];
__device__ float  g_pooli[BB * DD];
__device__ float  g_pooll[BB * DD];
__device__ __half g_ih[BB * NI * DD];
__device__ __half g_qh[BB * NQ * DD];
__device__ __half g_ihT[BB * DD * NI];
__device__ __half g_qhT[BB * DD * NQ];
__device__ __half g_P1h[BB * NI * NQ];
__device__ __half g_P2h[BB * NQ * NI];
__device__ __half g_iatth[BB * NI * DD];
__device__ __half g_latth[BB * NQ * DD];
__device__ __half g_WT[DH * DD];

__device__ __forceinline__ uint32_t smem_u32(const void* p)
{
    uint32_t a;
    asm("{ .reg .u64 t; cvta.to.shared.u64 t, %1; cvt.u32.u64 %0, t; }" : "=r"(a) : "l"(p));
    return a;
}
__device__ __forceinline__ void ldmx4(uint32_t r[4], uint32_t addr)
{
    asm volatile("ldmatrix.sync.aligned.m8n8.x4.shared.b16 {%0,%1,%2,%3}, [%4];"
                 : "=r"(r[0]), "=r"(r[1]), "=r"(r[2]), "=r"(r[3]) : "r"(addr));
}
__device__ __forceinline__ void mma_f16(float c[4], const uint32_t a[4],
                                        uint32_t b0, uint32_t b1)
{
    asm volatile(
        "mma.sync.aligned.m16n8k16.row.col.f32.f16.f16.f32 "
        "{%0,%1,%2,%3}, {%4,%5,%6,%7}, {%8,%9}, {%0,%1,%2,%3};"
        : "+f"(c[0]), "+f"(c[1]), "+f"(c[2]), "+f"(c[3])
        : "r"(a[0]), "r"(a[1]), "r"(a[2]), "r"(a[3]), "r"(b0), "r"(b1));
}
// L1-caching async copy (tiles are reused across CTAs -> keep them in L1)
__device__ __forceinline__ void cp16(uint32_t dst, const void* src)
{
    asm volatile("cp.async.ca.shared.global [%0], [%1], 16;" :: "r"(dst), "l"(src));
}
#define CP_COMMIT() asm volatile("cp.async.commit_group;" ::: "memory")
#define CP_WAIT1()  asm volatile("cp.async.wait_group 1;" ::: "memory")

// =============== fp16 tensor-core GEMM: C = alpha * A @ BT^T ===============
// A: [M,K] half row-major. BT: [N,K] half row-major. M,N %128==0, K %32==0.
// EPI 0: store Cf (f32 * alpha); EPI 1: store Cf (f32) AND Ch (f16);
// EPI 2: fused attflat logits: attOut[m] += sum_n relu(acc + b1[n]) * w2[n]
#define SSTR 40                      // smem row stride in halves (80B)
#define STAGE_B (128 * SSTR * 2)     // one tile: 10240 B
#define STAGE2_B (2 * STAGE_B)       // A+B per stage: 20480 B
#define HG_SMEM (3 * STAGE2_B)       // 3 stages: 61440 B
template <int EPI>
__global__ __launch_bounds__(256, 2)
void hgemm(const __half* __restrict__ A, const __half* __restrict__ BT,
           float* __restrict__ Cf, __half* __restrict__ Ch,
           int M, int N, int K, long sA, long sB, long sC,
           float alpha,
           const float* __restrict__ b1, const float* __restrict__ w2,
           float* __restrict__ attOut)
{
    extern __shared__ __align__(16) char smx[];
    const uint32_t smb = smem_u32(smx);

    const int zb = blockIdx.z;
    A  += (long)zb * sA;
    BT += (long)zb * sB;

    const int tid  = threadIdx.x;
    const int lane = tid & 31;
    const int wid  = tid >> 5;
    const int gid  = lane >> 2, tig = lane & 3;
    const int warp_m = wid & 1, warp_n = wid >> 1;
    const int m0 = blockIdx.y * 128, n0 = blockIdx.x * 128;

    // per-thread staging coords: rows srow, srow+64; 16B unit skq within 64B chunk row
    const int srow = tid >> 2;
    const int skq  = tid & 3;
    const __half* Ag0 = A + (long)(m0 + srow) * K + skq * 8;
    const __half* Ag1 = A + (long)(m0 + srow + 64) * K + skq * 8;
    const __half* Bg0 = BT + (long)(n0 + srow) * K + skq * 8;
    const __half* Bg1 = BT + (long)(n0 + srow + 64) * K + skq * 8;
    const uint32_t dA0 = srow * (SSTR * 2) + skq * 16;
    const uint32_t dA1 = (srow + 64) * (SSTR * 2) + skq * 16;

    // ldmatrix row offsets (within a stage)
    const uint32_t aRowOff = (warp_m * 64 + (lane & 15)) * (SSTR * 2) + (lane >> 4) * 16;
    const uint32_t bRowOff = STAGE_B + (warp_n * 32 + (lane & 15)) * (SSTR * 2) + (lane >> 4) * 16;

    float acc[4][4][4];
#pragma unroll
    for (int i = 0; i < 4; i++)
#pragma unroll
        for (int j = 0; j < 4; j++)
#pragma unroll
            for (int r = 0; r < 4; r++) acc[i][j][r] = 0.f;

    const int nc = K >> 5;

    // prologue: issue chunks 0 and 1 into stages 0,1
#pragma unroll
    for (int p = 0; p < 2; ++p) {
        const uint32_t sb = smb + p * STAGE2_B;
        cp16(sb + dA0, Ag0 + p * 32);
        cp16(sb + dA1, Ag1 + p * 32);
        cp16(sb + STAGE_B + dA0, Bg0 + p * 32);
        cp16(sb + STAGE_B + dA1, Bg1 + p * 32);
        CP_COMMIT();
    }

#pragma unroll 1
    for (int c = 0; c < nc; ++c) {
        CP_WAIT1();              // chunk c resident
        __syncthreads();         // all threads done reading stage (c+2)%3 (chunk c-1)
        // issue chunk c+2 into stage (c+2)%3 (overwrites chunk c-1's stage - safe)
        if (c + 2 < nc) {
            const int st = (c + 2) % 3;
            const uint32_t sb = smb + st * STAGE2_B;
            cp16(sb + dA0, Ag0 + (c + 2) * 32);
            cp16(sb + dA1, Ag1 + (c + 2) * 32);
            cp16(sb + STAGE_B + dA0, Bg0 + (c + 2) * 32);
            cp16(sb + STAGE_B + dA1, Bg1 + (c + 2) * 32);
        }
        CP_COMMIT();             // keep one group per chunk (may be empty)

        // compute chunk c from stage c%3
        const uint32_t sb = smb + (c % 3) * STAGE2_B;
        const uint32_t aB = sb + aRowOff;
        const uint32_t bB = sb + bRowOff;
#pragma unroll
        for (int ks = 0; ks < 2; ++ks) {
            uint32_t b[2][4];
            ldmx4(b[0], bB + ks * 32);
            ldmx4(b[1], bB + 16 * (SSTR * 2) + ks * 32);
#pragma unroll
            for (int mt = 0; mt < 4; ++mt) {
                uint32_t a[4];
                ldmx4(a, aB + mt * 16 * (SSTR * 2) + ks * 32);
                mma_f16(acc[mt][0], a, b[0][0], b[0][2]);
                mma_f16(acc[mt][1], a, b[0][1], b[0][3]);
                mma_f16(acc[mt][2], a, b[1][0], b[1][2]);
                mma_f16(acc[mt][3], a, b[1][1], b[1][3]);
            }
        }
    }

    if (EPI == 2) {
        float bv[8], wv[8];
#pragma unroll
        for (int nt = 0; nt < 4; nt++)
#pragma unroll
            for (int cc = 0; cc < 2; cc++) {
                int n = n0 + warp_n * 32 + nt * 8 + tig * 2 + cc;
                bv[nt * 2 + cc] = b1[n];
                wv[nt * 2 + cc] = w2[n];
            }
#pragma unroll
        for (int mt = 0; mt < 4; mt++) {
#pragma unroll
            for (int r = 0; r < 2; r++) {
                float s = 0.f;
#pragma unroll
                for (int nt = 0; nt < 4; nt++)
#pragma unroll
                    for (int cc = 0; cc < 2; cc++)
                        s += fmaxf(acc[mt][nt][r * 2 + cc] + bv[nt * 2 + cc], 0.f) * wv[nt * 2 + cc];
                s += __shfl_xor_sync(0xffffffffu, s, 1);
                s += __shfl_xor_sync(0xffffffffu, s, 2);
                if (tig == 0) {
                    int m = m0 + warp_m * 64 + mt * 16 + r * 8 + gid;
                    atomicAdd(attOut + m, s);
                }
            }
        }
    } else {
        Cf += (long)zb * sC;
        if (EPI == 1) Ch += (long)zb * sC;
#pragma unroll
        for (int mt = 0; mt < 4; mt++) {
#pragma unroll
            for (int r = 0; r < 2; r++) {
                long m = m0 + warp_m * 64 + mt * 16 + r * 8 + gid;
#pragma unroll
                for (int nt = 0; nt < 4; nt++) {
                    int n = n0 + warp_n * 32 + nt * 8 + tig * 2;
                    float x = acc[mt][nt][r * 2 + 0] * alpha;
                    float y = acc[mt][nt][r * 2 + 1] * alpha;
                    *(float2*)(Cf + m * N + n) = make_float2(x, y);
                    if (EPI == 1)
                        *(__half2*)(Ch + m * N + n) = __floats2half2_rn(x, y);
                }
            }
        }
    }
}

// ---- f32 [Nseq,DD] -> fp16 same layout + fp16 transposed [DD,Nseq], per batch ----
__global__ void conv_trans(const float* __restrict__ X, __half* __restrict__ Xh,
                           __half* __restrict__ XhT, int Nseq)
{
    __shared__ float t[32][33];
    const long bo = (long)blockIdx.z * Nseq * DD;
    X += bo; Xh += bo; XhT += bo;
    const int d0 = blockIdx.x * 32, s0 = blockIdx.y * 32;
    const int tx = threadIdx.x;
#pragma unroll
    for (int i = threadIdx.y; i < 32; i += 8) {
        float v = X[(long)(s0 + i) * DD + d0 + tx];
        t[i][tx] = v;
        Xh[(long)(s0 + i) * DD + d0 + tx] = __float2half(v);
    }
    __syncthreads();
#pragma unroll
    for (int i = threadIdx.y; i < 32; i += 8)
        XhT[(long)(d0 + i) * Nseq + s0 + tx] = __float2half(t[tx][i]);
}

// ---- per-batch f32 transpose: X [R,C] -> XT [C,R] ----
__global__ void transpose_f32(const float* __restrict__ X, float* __restrict__ XT,
                              int R, int C)
{
    __shared__ float t[32][33];
    const long bo = (long)blockIdx.z * R * C;
    const int c0 = blockIdx.x * 32, r0 = blockIdx.y * 32;
    const int tx = threadIdx.x;
#pragma unroll
    for (int i = threadIdx.y; i < 32; i += 8)
        t[i][tx] = X[bo + (long)(r0 + i) * C + c0 + tx];
    __syncthreads();
#pragma unroll
    for (int i = threadIdx.y; i < 32; i += 8)
        XT[bo + (long)(c0 + i) * R + r0 + tx] = t[tx][i];
}

// ---- W1 (640x1280 f32) -> W1T (1280x640 fp16) ----
__global__ void transpose_h(const float* __restrict__ W, __half* __restrict__ WT)
{
    __shared__ float t[32][33];
    int c0 = blockIdx.x * 32, r0 = blockIdx.y * 32;
#pragma unroll
    for (int i = threadIdx.y; i < 32; i += 8)
        t[i][threadIdx.x] = W[(long)(r0 + i) * DH + c0 + threadIdx.x];
    __syncthreads();
#pragma unroll
    for (int i = threadIdx.y; i < 32; i += 8)
        WT[(long)(c0 + i) * DD + r0 + threadIdx.x] = __float2half(t[threadIdx.x][i]);
}

// ---------------- generic fp32 SGEMM (small final linears only) ----------------
__global__ __launch_bounds__(256, 2)
void gemm128(const float* __restrict__ A, const float* __restrict__ Bm,
             float* __restrict__ C, int M, int N, int K,
             const float* __restrict__ bias)
{
    __shared__ __align__(16) float As[16][128];
    __shared__ __align__(16) float Bs[16][128];

    const int m0  = blockIdx.y * 128;
    const int n0  = blockIdx.x * 128;
    const int tid = threadIdx.x;
    const int tx  = tid & 15;
    const int ty  = tid >> 4;

    float acc[8][8];
#pragma unroll
    for (int i = 0; i < 8; i++)
#pragma unroll
        for (int j = 0; j < 8; j++) acc[i][j] = 0.f;

    for (int k0 = 0; k0 < K; k0 += 16) {
#pragma unroll
        for (int i = 0; i < 2; i++) {
            int f  = tid + i * 256;
            int ml = f >> 2;
            int kl = (f & 3) << 2;
            float4 v = make_float4(0.f, 0.f, 0.f, 0.f);
            if (m0 + ml < M)
                v = *(const float4*)(A + (long)(m0 + ml) * K + (k0 + kl));
            As[kl + 0][ml] = v.x; As[kl + 1][ml] = v.y;
            As[kl + 2][ml] = v.z; As[kl + 3][ml] = v.w;
        }
#pragma unroll
        for (int i = 0; i < 2; i++) {
            int f  = tid + i * 256;
            int kl = f >> 5;
            int nl = (f & 31) << 2;
            float4 v = make_float4(0.f, 0.f, 0.f, 0.f);
            if (n0 + nl < N)
                v = *(const float4*)(Bm + (long)(k0 + kl) * N + (n0 + nl));
            *(float4*)&Bs[kl][nl] = v;
        }
        __syncthreads();

#pragma unroll
        for (int kk = 0; kk < 16; kk++) {
            float a[8], b[8];
            *(float4*)&a[0] = *(const float4*)&As[kk][ty * 4];
            *(float4*)&a[4] = *(const float4*)&As[kk][64 + ty * 4];
            *(float4*)&b[0] = *(const float4*)&Bs[kk][tx * 4];
            *(float4*)&b[4] = *(const float4*)&Bs[kk][64 + tx * 4];
#pragma unroll
            for (int i = 0; i < 8; i++)
#pragma unroll
                for (int j = 0; j < 8; j++)
                    acc[i][j] = fmaf(a[i], b[j], acc[i][j]);
        }
        __syncthreads();
    }

#pragma unroll
    for (int i = 0; i < 8; i++) {
        int m = m0 + ((i < 4) ? (ty * 4 + i) : (64 + ty * 4 + i - 4));
        if (m >= M) continue;
#pragma unroll
        for (int g = 0; g < 2; g++) {
            int n = n0 + g * 64 + tx * 4;
            float4 v;
            v.x = acc[i][g * 4 + 0] + bias[n];
            v.y = acc[i][g * 4 + 1] + bias[n + 1];
            v.z = acc[i][g * 4 + 2] + bias[n + 2];
            v.w = acc[i][g * 4 + 3] + bias[n + 3];
            *(float4*)(C + (long)m * N + n) = v;
        }
    }
}

// ---------------- masked row softmax ----------------
__device__ __forceinline__ float warpMax(float v)
{
#pragma unroll
    for (int o = 16; o > 0; o >>= 1) v = fmaxf(v, __shfl_xor_sync(0xffffffffu, v, o));
    return v;
}
__device__ __forceinline__ float warpSum(float v)
{
#pragma unroll
    for (int o = 16; o > 0; o >>= 1) v += __shfl_xor_sync(0xffffffffu, v, o);
    return v;
}

__global__ void softmax_rows(float* __restrict__ P,
                             const unsigned int* __restrict__ mask,
                             int rowsPerBatch, int N,
                             __half* __restrict__ pout,
                             float* __restrict__ wout)
{
    const int row = blockIdx.x;
    const int bb  = row / rowsPerBatch;
    float* prow = P + (long)row * N;
    const unsigned int* mrow = mask + (long)bb * N;
    const int tid = threadIdx.x;
    const int cnt = N >> 7;

    float v[4];
    float mx = -3.4e38f;
    for (int c = 0; c < cnt; c++) {
        int n = (c << 7) + tid;
        float x = prow[n];
        if (mrow[n] != 0u) x = NEGV;
        v[c] = x;
        mx = fmaxf(mx, x);
    }
    __shared__ float sr[4];
    float wm = warpMax(mx);
    if ((tid & 31) == 0) sr[tid >> 5] = wm;
    __syncthreads();
    mx = fmaxf(fmaxf(sr[0], sr[1]), fmaxf(sr[2], sr[3]));

    float sum = 0.f;
    for (int c = 0; c < cnt; c++) { v[c] = __expf(v[c] - mx); sum += v[c]; }
    __syncthreads();
    float ws = warpSum(sum);
    if ((tid & 31) == 0) sr[tid >> 5] = ws;
    __syncthreads();
    sum = sr[0] + sr[1] + sr[2] + sr[3];

    float inv = 1.f / sum;
    for (int c = 0; c < cnt; c++) {
        int n = (c << 7) + tid;
        float r = v[c] * inv;
        if (pout) pout[(long)row * N + n] = __float2half(r);
        else      prow[n] = r;
        if (wout) wout[(long)row * N + n] = r;
    }
}

// pooled[b, d] = sum_m att[b, m] * X[b, m, d]
__global__ void pool_kernel(const float* __restrict__ X,
                            const float* __restrict__ att,
                            float* __restrict__ pooled, int Nseq)
{
    int bb = blockIdx.y;
    int d  = blockIdx.x * 128 + threadIdx.x;
    const float* Xb = X + (long)bb * Nseq * DD + d;
    const float* ab = att + bb * Nseq;
    float a0 = 0.f, a1 = 0.f, a2 = 0.f, a3 = 0.f;
    for (int m = 0; m < Nseq; m += 4) {
        a0 = fmaf(ab[m + 0], Xb[(long)(m + 0) * DD], a0);
        a1 = fmaf(ab[m + 1], Xb[(long)(m + 1) * DD], a1);
        a2 = fmaf(ab[m + 2], Xb[(long)(m + 2) * DD], a2);
        a3 = fmaf(ab[m + 3], Xb[(long)(m + 3) * DD], a3);
    }
    pooled[bb * DD + d] = (a0 + a1) + (a2 + a3);
}

__global__ void fill_scalar(float* __restrict__ p, int n, const float* __restrict__ s)
{
    int i = blockIdx.x * 256 + threadIdx.x;
    if (i < n) p[i] = *s;
}

// ---------------------------------- launch ----------------------------------
extern "C" void kernel_launch(void* const* d_in, const int* in_sizes, int n_in,
                              void* d_out, int out_size)
{
    const float* i_batch = (const float*)d_in[0];
    const float* q_batch = (const float*)d_in[1];
    const unsigned int* i_mask = (const unsigned int*)d_in[2];
    const unsigned int* q_mask = (const unsigned int*)d_in[3];
    const float* lW1 = (const float*)d_in[4];
    const float* lb1 = (const float*)d_in[5];
    const float* lW2 = (const float*)d_in[6];
    const float* lb2 = (const float*)d_in[7];
    const float* lWm = (const float*)d_in[8];
    const float* lbm = (const float*)d_in[9];
    const float* iW1 = (const float*)d_in[10];
    const float* ib1 = (const float*)d_in[11];
    const float* iW2 = (const float*)d_in[12];
    const float* ib2 = (const float*)d_in[13];
    const float* iWm = (const float*)d_in[14];
    const float* ibm = (const float*)d_in[15];
    float* out = (float*)d_out;

    float *S, *ST, *iatt, *latt, *atti, *attl, *pooli, *pooll;
    __half *ih, *qh, *ihT, *qhT, *P1h, *P2h, *iatth, *latth, *WT;
    cudaGetSymbolAddress((void**)&S, g_S);
    cudaGetSymbolAddress((void**)&ST, g_ST);
    cudaGetSymbolAddress((void**)&iatt, g_iatt);
    cudaGetSymbolAddress((void**)&latt, g_latt);
    cudaGetSymbolAddress((void**)&atti, g_atti);
    cudaGetSymbolAddress((void**)&attl, g_attl);
    cudaGetSymbolAddress((void**)&pooli, g_pooli);
    cudaGetSymbolAddress((void**)&pooll, g_pooll);
    cudaGetSymbolAddress((void**)&ih, g_ih);
    cudaGetSymbolAddress((void**)&qh, g_qh);
    cudaGetSymbolAddress((void**)&ihT, g_ihT);
    cudaGetSymbolAddress((void**)&qhT, g_qhT);
    cudaGetSymbolAddress((void**)&P1h, g_P1h);
    cudaGetSymbolAddress((void**)&P2h, g_P2h);
    cudaGetSymbolAddress((void**)&iatth, g_iatth);
    cudaGetSymbolAddress((void**)&latth, g_latth);
    cudaGetSymbolAddress((void**)&WT, g_WT);

    cudaFuncSetAttribute(hgemm<0>, cudaFuncAttributeMaxDynamicSharedMemorySize, HG_SMEM);
    cudaFuncSetAttribute(hgemm<1>, cudaFuncAttributeMaxDynamicSharedMemorySize, HG_SMEM);
    cudaFuncSetAttribute(hgemm<2>, cudaFuncAttributeMaxDynamicSharedMemorySize, HG_SMEM);

    const float SCALE = 0.039528470752104744f;  // 1/sqrt(640)

    // ---- fp16 conversions + per-batch transposes ----
    conv_trans<<<dim3(DD / 32, NI / 32, BB), dim3(32, 8)>>>(i_batch, ih, ihT, NI);
    conv_trans<<<dim3(DD / 32, NQ / 32, BB), dim3(32, 8)>>>(q_batch, qh, qhT, NQ);

    // ---- scores computed ONCE: S = i @ q^T * scale  (S^T serves attention 2) ----
    hgemm<0><<<dim3(NQ / 128, NI / 128, BB), 256, HG_SMEM>>>(
        ih, qh, S, nullptr, NI, NQ, DD,
        (long)NI * DD, (long)NQ * DD, (long)NI * NQ, SCALE, nullptr, nullptr, nullptr);
    transpose_f32<<<dim3(NQ / 32, NI / 32, BB), dim3(32, 8)>>>(S, ST, NI, NQ);

    // ---- attention 1: P1 = softmax(S, q_mask); iatt = P1 @ q ----
    softmax_rows<<<BB * NI, 128>>>(S, q_mask, NI, NQ, P1h, nullptr);
    hgemm<1><<<dim3(DD / 128, NI / 128, BB), 256, HG_SMEM>>>(
        P1h, qhT, iatt, iatth, NI, DD, NQ,
        (long)NI * NQ, (long)DD * NQ, (long)NI * DD, 1.f, nullptr, nullptr, nullptr);

    // ---- attention 2: P2 = softmax(S^T, i_mask); latt = P2 @ i ----
    softmax_rows<<<BB * NQ, 128>>>(ST, i_mask, NQ, NI, P2h, nullptr);
    hgemm<1><<<dim3(DD / 128, NQ / 128, BB), 256, HG_SMEM>>>(
        P2h, ihT, latt, latth, NQ, DD, NI,
        (long)NQ * NI, (long)DD * NI, (long)NQ * DD, 1.f, nullptr, nullptr, nullptr);

    // ---- attflat logits: relu(X @ W1 + b1) @ W2 + b2 ----
    fill_scalar<<<(BB * NI + 255) / 256, 256>>>(atti, BB * NI, lb2);
    fill_scalar<<<(BB * NQ + 255) / 256, 256>>>(attl, BB * NQ, ib2);

    transpose_h<<<dim3(DH / 32, DD / 32), dim3(32, 8)>>>(lW1, WT);
    hgemm<2><<<dim3(DH / 128, (BB * NI) / 128, 1), 256, HG_SMEM>>>(
        iatth, WT, nullptr, nullptr, BB * NI, DH, DD, 0, 0, 0, 1.f, lb1, lW2, atti);

    transpose_h<<<dim3(DH / 32, DD / 32), dim3(32, 8)>>>(iW1, WT);
    hgemm<2><<<dim3(DH / 128, (BB * NQ) / 128, 1), 256, HG_SMEM>>>(
        latth, WT, nullptr, nullptr, BB * NQ, DH, DD, 0, 0, 0, 1.f, ib1, iW2, attl);

    // ---- attflat softmax over sequence (i path emits i_weight) ----
    softmax_rows<<<BB, 128>>>(atti, i_mask, 1, NI, nullptr, out + 2 * BB * DD);
    softmax_rows<<<BB, 128>>>(attl, q_mask, 1, NQ, nullptr, nullptr);

    // ---- pooled = sum_m att * X ----
    pool_kernel<<<dim3(DD / 128, BB), 128>>>(iatt, atti, pooli, NI);
    pool_kernel<<<dim3(DD / 128, BB), 128>>>(latt, attl, pooll, NQ);

    // ---- final linears ----
    gemm128<<<dim3(DD / 128, 1, 1), 256>>>(pooli, lWm, out, BB, DD, DD, lbm);
    gemm128<<<dim3(DD / 128, 1, 1), 256>>>(pooll, iWm, out + BB * DD, BB, DD, DD, ibm);
}

// round 7
// speedup vs baseline: 3.2505x; 1.0179x over previous
#include <cuda_runtime.h>
#include <cuda_fp16.h>
#include <math.h>
#include <stdint.h>

// Problem dims
#define BB 64
#define NI 512
#define NQ 128
#define DD 640
#define DH 1280
#define NEGV (-65504.0f)

// ---------------- scratch (static __device__ arrays; no allocs) ----------------
__device__ float  g_S[BB * NI * NQ];
__device__ float  g_ST[BB * NQ * NI];
__device__ float  g_iatt[BB * NI * DD];
__device__ float  g_latt[BB * NQ * DD];
__device__ float  g_atti[BB * NI];
__device__ float  g_attl[BB * NQ];
__device__ float  g_pooli[BB * DD];
__device__ float  g_pooll[BB * DD];
__device__ __half g_ih[BB * NI * DD];
__device__ __half g_qh[BB * NQ * DD];
__device__ __half g_ihT[BB * DD * NI];
__device__ __half g_qhT[BB * DD * NQ];
__device__ __half g_P1h[BB * NI * NQ];
__device__ __half g_P2h[BB * NQ * NI];
__device__ __half g_iatth[BB * NI * DD];
__device__ __half g_latth[BB * NQ * DD];
__device__ __half g_WT[DH * DD];

__device__ __forceinline__ uint32_t smem_u32(const void* p)
{
    uint32_t a;
    asm("{ .reg .u64 t; cvta.to.shared.u64 t, %1; cvt.u32.u64 %0, t; }" : "=r"(a) : "l"(p));
    return a;
}
__device__ __forceinline__ void ldmx4(uint32_t r[4], uint32_t addr)
{
    asm volatile("ldmatrix.sync.aligned.m8n8.x4.shared.b16 {%0,%1,%2,%3}, [%4];"
                 : "=r"(r[0]), "=r"(r[1]), "=r"(r[2]), "=r"(r[3]) : "r"(addr));
}
__device__ __forceinline__ void mma_f16(float c[4], const uint32_t a[4],
                                        uint32_t b0, uint32_t b1)
{
    asm volatile(
        "mma.sync.aligned.m16n8k16.row.col.f32.f16.f16.f32 "
        "{%0,%1,%2,%3}, {%4,%5,%6,%7}, {%8,%9}, {%0,%1,%2,%3};"
        : "+f"(c[0]), "+f"(c[1]), "+f"(c[2]), "+f"(c[3])
        : "r"(a[0]), "r"(a[1]), "r"(a[2]), "r"(a[3]), "r"(b0), "r"(b1));
}
__device__ __forceinline__ void cp16(uint32_t dst, const void* src)
{
    asm volatile("cp.async.ca.shared.global [%0], [%1], 16;" :: "r"(dst), "l"(src));
}
#define CP_COMMIT() asm volatile("cp.async.commit_group;" ::: "memory")
#define CP_WAIT0()  asm volatile("cp.async.wait_group 0;" ::: "memory")

// =============== fp16 tensor-core GEMM: C = alpha * A @ BT^T ===============
// A: [M,K] half row-major. BT: [N,K] half row-major. M,N %128==0, K %64==0.
// EPI 0: store Cf (f32 * alpha); EPI 1: store Cf (f32) AND Ch (f16);
// EPI 2: fused attflat logits: attOut[m] += sum_n relu(acc + b1[n]) * w2[n]
// BK = 64 (128B rows), 2-stage cp.async pipeline, 1 barrier + 1 wait per chunk.
#define SSTR 72                      // smem row stride in halves (144B; conflict-free)
#define STAGE_B (128 * SSTR * 2)     // one operand tile: 18432 B
#define STAGE2_B (2 * STAGE_B)       // A+B per stage: 36864 B
#define HG_SMEM (2 * STAGE2_B)       // 2 stages: 73728 B
template <int EPI>
__global__ __launch_bounds__(256, 2)
void hgemm(const __half* __restrict__ A, const __half* __restrict__ BT,
           float* __restrict__ Cf, __half* __restrict__ Ch,
           int M, int N, int K, long sA, long sB, long sC,
           float alpha,
           const float* __restrict__ b1, const float* __restrict__ w2,
           float* __restrict__ attOut)
{
    extern __shared__ __align__(16) char smx[];
    const uint32_t smb = smem_u32(smx);

    const int zb = blockIdx.z;
    A  += (long)zb * sA;
    BT += (long)zb * sB;

    const int tid  = threadIdx.x;
    const int lane = tid & 31;
    const int wid  = tid >> 5;
    const int gid  = lane >> 2, tig = lane & 3;
    const int warp_m = wid & 1, warp_n = wid >> 1;
    const int m0 = blockIdx.y * 128, n0 = blockIdx.x * 128;

    // staging: per operand 128 rows x 128B; thread t -> rows t>>2 and t>>2+64,
    // 32B (2x cp16) at byte offset (t&3)*32 within the row.
    const int srow = tid >> 2;
    const int sco  = (tid & 3) * 16;   // halves offset = (t&3)*32 bytes
    const __half* Ag0 = A + (long)(m0 + srow) * K + sco;
    const __half* Ag1 = A + (long)(m0 + srow + 64) * K + sco;
    const __half* Bg0 = BT + (long)(n0 + srow) * K + sco;
    const __half* Bg1 = BT + (long)(n0 + srow + 64) * K + sco;
    const uint32_t dA0 = srow * (SSTR * 2) + (tid & 3) * 32;
    const uint32_t dA1 = (srow + 64) * (SSTR * 2) + (tid & 3) * 32;

    // ldmatrix offsets within a stage
    const uint32_t aRowOff = (warp_m * 64 + (lane & 15)) * (SSTR * 2) + (lane >> 4) * 16;
    const uint32_t bRowOff = STAGE_B + (warp_n * 32 + (lane & 15)) * (SSTR * 2) + (lane >> 4) * 16;

    float acc[4][4][4];
#pragma unroll
    for (int i = 0; i < 4; i++)
#pragma unroll
        for (int j = 0; j < 4; j++)
#pragma unroll
            for (int r = 0; r < 4; r++) acc[i][j][r] = 0.f;

    const int nc = K >> 6;

    // prologue: chunk 0 -> stage 0
    {
        cp16(smb + dA0, Ag0);            cp16(smb + dA0 + 16, Ag0 + 8);
        cp16(smb + dA1, Ag1);            cp16(smb + dA1 + 16, Ag1 + 8);
        cp16(smb + STAGE_B + dA0, Bg0);  cp16(smb + STAGE_B + dA0 + 16, Bg0 + 8);
        cp16(smb + STAGE_B + dA1, Bg1);  cp16(smb + STAGE_B + dA1 + 16, Bg1 + 8);
        CP_COMMIT();
    }

#pragma unroll 1
    for (int c = 0; c < nc; ++c) {
        CP_WAIT0();              // chunk c fully resident (this thread's view)
        __syncthreads();         // visibility to all warps + stage (c+1)&1 free
        if (c + 1 < nc) {
            const uint32_t sb = smb + ((c + 1) & 1) * STAGE2_B;
            const long ko = (long)(c + 1) * 64;
            cp16(sb + dA0, Ag0 + ko);            cp16(sb + dA0 + 16, Ag0 + ko + 8);
            cp16(sb + dA1, Ag1 + ko);            cp16(sb + dA1 + 16, Ag1 + ko + 8);
            cp16(sb + STAGE_B + dA0, Bg0 + ko);  cp16(sb + STAGE_B + dA0 + 16, Bg0 + ko + 8);
            cp16(sb + STAGE_B + dA1, Bg1 + ko);  cp16(sb + STAGE_B + dA1 + 16, Bg1 + ko + 8);
            CP_COMMIT();
        }

        // compute chunk c (4 k-steps of 16)
        const uint32_t sb = smb + (c & 1) * STAGE2_B;
        const uint32_t aB = sb + aRowOff;
        const uint32_t bB = sb + bRowOff;
#pragma unroll
        for (int ks = 0; ks < 4; ++ks) {
            uint32_t b[2][4];
            ldmx4(b[0], bB + ks * 32);
            ldmx4(b[1], bB + 16 * (SSTR * 2) + ks * 32);
#pragma unroll
            for (int mt = 0; mt < 4; ++mt) {
                uint32_t a[4];
                ldmx4(a, aB + mt * 16 * (SSTR * 2) + ks * 32);
                mma_f16(acc[mt][0], a, b[0][0], b[0][2]);
                mma_f16(acc[mt][1], a, b[0][1], b[0][3]);
                mma_f16(acc[mt][2], a, b[1][0], b[1][2]);
                mma_f16(acc[mt][3], a, b[1][1], b[1][3]);
            }
        }
    }

    if (EPI == 2) {
        float bv[8], wv[8];
#pragma unroll
        for (int nt = 0; nt < 4; nt++)
#pragma unroll
            for (int cc = 0; cc < 2; cc++) {
                int n = n0 + warp_n * 32 + nt * 8 + tig * 2 + cc;
                bv[nt * 2 + cc] = b1[n];
                wv[nt * 2 + cc] = w2[n];
            }
#pragma unroll
        for (int mt = 0; mt < 4; mt++) {
#pragma unroll
            for (int r = 0; r < 2; r++) {
                float s = 0.f;
#pragma unroll
                for (int nt = 0; nt < 4; nt++)
#pragma unroll
                    for (int cc = 0; cc < 2; cc++)
                        s += fmaxf(acc[mt][nt][r * 2 + cc] + bv[nt * 2 + cc], 0.f) * wv[nt * 2 + cc];
                s += __shfl_xor_sync(0xffffffffu, s, 1);
                s += __shfl_xor_sync(0xffffffffu, s, 2);
                if (tig == 0) {
                    int m = m0 + warp_m * 64 + mt * 16 + r * 8 + gid;
                    atomicAdd(attOut + m, s);
                }
            }
        }
    } else {
        Cf += (long)zb * sC;
        if (EPI == 1) Ch += (long)zb * sC;
#pragma unroll
        for (int mt = 0; mt < 4; mt++) {
#pragma unroll
            for (int r = 0; r < 2; r++) {
                long m = m0 + warp_m * 64 + mt * 16 + r * 8 + gid;
#pragma unroll
                for (int nt = 0; nt < 4; nt++) {
                    int n = n0 + warp_n * 32 + nt * 8 + tig * 2;
                    float x = acc[mt][nt][r * 2 + 0] * alpha;
                    float y = acc[mt][nt][r * 2 + 1] * alpha;
                    *(float2*)(Cf + m * N + n) = make_float2(x, y);
                    if (EPI == 1)
                        *(__half2*)(Ch + m * N + n) = __floats2half2_rn(x, y);
                }
            }
        }
    }
}

// ---- f32 [Nseq,DD] -> fp16 same layout + fp16 transposed [DD,Nseq], per batch ----
__global__ void conv_trans(const float* __restrict__ X, __half* __restrict__ Xh,
                           __half* __restrict__ XhT, int Nseq)
{
    __shared__ float t[32][33];
    const long bo = (long)blockIdx.z * Nseq * DD;
    X += bo; Xh += bo; XhT += bo;
    const int d0 = blockIdx.x * 32, s0 = blockIdx.y * 32;
    const int tx = threadIdx.x;
#pragma unroll
    for (int i = threadIdx.y; i < 32; i += 8) {
        float v = X[(long)(s0 + i) * DD + d0 + tx];
        t[i][tx] = v;
        Xh[(long)(s0 + i) * DD + d0 + tx] = __float2half(v);
    }
    __syncthreads();
#pragma unroll
    for (int i = threadIdx.y; i < 32; i += 8)
        XhT[(long)(d0 + i) * Nseq + s0 + tx] = __float2half(t[tx][i]);
}

// ---- per-batch f32 transpose: X [R,C] -> XT [C,R] ----
__global__ void transpose_f32(const float* __restrict__ X, float* __restrict__ XT,
                              int R, int C)
{
    __shared__ float t[32][33];
    const long bo = (long)blockIdx.z * R * C;
    const int c0 = blockIdx.x * 32, r0 = blockIdx.y * 32;
    const int tx = threadIdx.x;
#pragma unroll
    for (int i = threadIdx.y; i < 32; i += 8)
        t[i][tx] = X[bo + (long)(r0 + i) * C + c0 + tx];
    __syncthreads();
#pragma unroll
    for (int i = threadIdx.y; i < 32; i += 8)
        XT[bo + (long)(c0 + i) * R + r0 + tx] = t[tx][i];
}

// ---- W1 (640x1280 f32) -> W1T (1280x640 fp16) ----
__global__ void transpose_h(const float* __restrict__ W, __half* __restrict__ WT)
{
    __shared__ float t[32][33];
    int c0 = blockIdx.x * 32, r0 = blockIdx.y * 32;
#pragma unroll
    for (int i = threadIdx.y; i < 32; i += 8)
        t[i][threadIdx.x] = W[(long)(r0 + i) * DH + c0 + threadIdx.x];
    __syncthreads();
#pragma unroll
    for (int i = threadIdx.y; i < 32; i += 8)
        WT[(long)(c0 + i) * DD + r0 + threadIdx.x] = __float2half(t[threadIdx.x][i]);
}

// ---------------- generic fp32 SGEMM (small final linears only) ----------------
__global__ __launch_bounds__(256, 2)
void gemm128(const float* __restrict__ A, const float* __restrict__ Bm,
             float* __restrict__ C, int M, int N, int K,
             const float* __restrict__ bias)
{
    __shared__ __align__(16) float As[16][128];
    __shared__ __align__(16) float Bs[16][128];

    const int m0  = blockIdx.y * 128;
    const int n0  = blockIdx.x * 128;
    const int tid = threadIdx.x;
    const int tx  = tid & 15;
    const int ty  = tid >> 4;

    float acc[8][8];
#pragma unroll
    for (int i = 0; i < 8; i++)
#pragma unroll
        for (int j = 0; j < 8; j++) acc[i][j] = 0.f;

    for (int k0 = 0; k0 < K; k0 += 16) {
#pragma unroll
        for (int i = 0; i < 2; i++) {
            int f  = tid + i * 256;
            int ml = f >> 2;
            int kl = (f & 3) << 2;
            float4 v = make_float4(0.f, 0.f, 0.f, 0.f);
            if (m0 + ml < M)
                v = *(const float4*)(A + (long)(m0 + ml) * K + (k0 + kl));
            As[kl + 0][ml] = v.x; As[kl + 1][ml] = v.y;
            As[kl + 2][ml] = v.z; As[kl + 3][ml] = v.w;
        }
#pragma unroll
        for (int i = 0; i < 2; i++) {
            int f  = tid + i * 256;
            int kl = f >> 5;
            int nl = (f & 31) << 2;
            float4 v = make_float4(0.f, 0.f, 0.f, 0.f);
            if (n0 + nl < N)
                v = *(const float4*)(Bm + (long)(k0 + kl) * N + (n0 + nl));
            *(float4*)&Bs[kl][nl] = v;
        }
        __syncthreads();

#pragma unroll
        for (int kk = 0; kk < 16; kk++) {
            float a[8], b[8];
            *(float4*)&a[0] = *(const float4*)&As[kk][ty * 4];
            *(float4*)&a[4] = *(const float4*)&As[kk][64 + ty * 4];
            *(float4*)&b[0] = *(const float4*)&Bs[kk][tx * 4];
            *(float4*)&b[4] = *(const float4*)&Bs[kk][64 + tx * 4];
#pragma unroll
            for (int i = 0; i < 8; i++)
#pragma unroll
                for (int j = 0; j < 8; j++)
                    acc[i][j] = fmaf(a[i], b[j], acc[i][j]);
        }
        __syncthreads();
    }

#pragma unroll
    for (int i = 0; i < 8; i++) {
        int m = m0 + ((i < 4) ? (ty * 4 + i) : (64 + ty * 4 + i - 4));
        if (m >= M) continue;
#pragma unroll
        for (int g = 0; g < 2; g++) {
            int n = n0 + g * 64 + tx * 4;
            float4 v;
            v.x = acc[i][g * 4 + 0] + bias[n];
            v.y = acc[i][g * 4 + 1] + bias[n + 1];
            v.z = acc[i][g * 4 + 2] + bias[n + 2];
            v.w = acc[i][g * 4 + 3] + bias[n + 3];
            *(float4*)(C + (long)m * N + n) = v;
        }
    }
}

// ---------------- masked row softmax ----------------
__device__ __forceinline__ float warpMax(float v)
{
#pragma unroll
    for (int o = 16; o > 0; o >>= 1) v = fmaxf(v, __shfl_xor_sync(0xffffffffu, v, o));
    return v;
}
__device__ __forceinline__ float warpSum(float v)
{
#pragma unroll
    for (int o = 16; o > 0; o >>= 1) v += __shfl_xor_sync(0xffffffffu, v, o);
    return v;
}

__global__ void softmax_rows(float* __restrict__ P,
                             const unsigned int* __restrict__ mask,
                             int rowsPerBatch, int N,
                             __half* __restrict__ pout,
                             float* __restrict__ wout)
{
    const int row = blockIdx.x;
    const int bb  = row / rowsPerBatch;
    float* prow = P + (long)row * N;
    const unsigned int* mrow = mask + (long)bb * N;
    const int tid = threadIdx.x;
    const int cnt = N >> 7;

    float v[4];
    float mx = -3.4e38f;
    for (int c = 0; c < cnt; c++) {
        int n = (c << 7) + tid;
        float x = prow[n];
        if (mrow[n] != 0u) x = NEGV;
        v[c] = x;
        mx = fmaxf(mx, x);
    }
    __shared__ float sr[4];
    float wm = warpMax(mx);
    if ((tid & 31) == 0) sr[tid >> 5] = wm;
    __syncthreads();
    mx = fmaxf(fmaxf(sr[0], sr[1]), fmaxf(sr[2], sr[3]));

    float sum = 0.f;
    for (int c = 0; c < cnt; c++) { v[c] = __expf(v[c] - mx); sum += v[c]; }
    __syncthreads();
    float ws = warpSum(sum);
    if ((tid & 31) == 0) sr[tid >> 5] = ws;
    __syncthreads();
    sum = sr[0] + sr[1] + sr[2] + sr[3];

    float inv = 1.f / sum;
    for (int c = 0; c < cnt; c++) {
        int n = (c << 7) + tid;
        float r = v[c] * inv;
        if (pout) pout[(long)row * N + n] = __float2half(r);
        else      prow[n] = r;
        if (wout) wout[(long)row * N + n] = r;
    }
}

// pooled[b, d] = sum_m att[b, m] * X[b, m, d]
__global__ void pool_kernel(const float* __restrict__ X,
                            const float* __restrict__ att,
                            float* __restrict__ pooled, int Nseq)
{
    int bb = blockIdx.y;
    int d  = blockIdx.x * 128 + threadIdx.x;
    const float* Xb = X + (long)bb * Nseq * DD + d;
    const float* ab = att + bb * Nseq;
    float a0 = 0.f, a1 = 0.f, a2 = 0.f, a3 = 0.f;
    for (int m = 0; m < Nseq; m += 4) {
        a0 = fmaf(ab[m + 0], Xb[(long)(m + 0) * DD], a0);
        a1 = fmaf(ab[m + 1], Xb[(long)(m + 1) * DD], a1);
        a2 = fmaf(ab[m + 2], Xb[(long)(m + 2) * DD], a2);
        a3 = fmaf(ab[m + 3], Xb[(long)(m + 3) * DD], a3);
    }
    pooled[bb * DD + d] = (a0 + a1) + (a2 + a3);
}

__global__ void fill_scalar(float* __restrict__ p, int n, const float* __restrict__ s)
{
    int i = blockIdx.x * 256 + threadIdx.x;
    if (i < n) p[i] = *s;
}

// ---------------------------------- launch ----------------------------------
extern "C" void kernel_launch(void* const* d_in, const int* in_sizes, int n_in,
                              void* d_out, int out_size)
{
    const float* i_batch = (const float*)d_in[0];
    const float* q_batch = (const float*)d_in[1];
    const unsigned int* i_mask = (const unsigned int*)d_in[2];
    const unsigned int* q_mask = (const unsigned int*)d_in[3];
    const float* lW1 = (const float*)d_in[4];
    const float* lb1 = (const float*)d_in[5];
    const float* lW2 = (const float*)d_in[6];
    const float* lb2 = (const float*)d_in[7];
    const float* lWm = (const float*)d_in[8];
    const float* lbm = (const float*)d_in[9];
    const float* iW1 = (const float*)d_in[10];
    const float* ib1 = (const float*)d_in[11];
    const float* iW2 = (const float*)d_in[12];
    const float* ib2 = (const float*)d_in[13];
    const float* iWm = (const float*)d_in[14];
    const float* ibm = (const float*)d_in[15];
    float* out = (float*)d_out;

    float *S, *ST, *iatt, *latt, *atti, *attl, *pooli, *pooll;
    __half *ih, *qh, *ihT, *qhT, *P1h, *P2h, *iatth, *latth, *WT;
    cudaGetSymbolAddress((void**)&S, g_S);
    cudaGetSymbolAddress((void**)&ST, g_ST);
    cudaGetSymbolAddress((void**)&iatt, g_iatt);
    cudaGetSymbolAddress((void**)&latt, g_latt);
    cudaGetSymbolAddress((void**)&atti, g_atti);
    cudaGetSymbolAddress((void**)&attl, g_attl);
    cudaGetSymbolAddress((void**)&pooli, g_pooli);
    cudaGetSymbolAddress((void**)&pooll, g_pooll);
    cudaGetSymbolAddress((void**)&ih, g_ih);
    cudaGetSymbolAddress((void**)&qh, g_qh);
    cudaGetSymbolAddress((void**)&ihT, g_ihT);
    cudaGetSymbolAddress((void**)&qhT, g_qhT);
    cudaGetSymbolAddress((void**)&P1h, g_P1h);
    cudaGetSymbolAddress((void**)&P2h, g_P2h);
    cudaGetSymbolAddress((void**)&iatth, g_iatth);
    cudaGetSymbolAddress((void**)&latth, g_latth);
    cudaGetSymbolAddress((void**)&WT, g_WT);

    cudaFuncSetAttribute(hgemm<0>, cudaFuncAttributeMaxDynamicSharedMemorySize, HG_SMEM);
    cudaFuncSetAttribute(hgemm<1>, cudaFuncAttributeMaxDynamicSharedMemorySize, HG_SMEM);
    cudaFuncSetAttribute(hgemm<2>, cudaFuncAttributeMaxDynamicSharedMemorySize, HG_SMEM);

    const float SCALE = 0.039528470752104744f;  // 1/sqrt(640)

    // ---- fp16 conversions + per-batch transposes ----
    conv_trans<<<dim3(DD / 32, NI / 32, BB), dim3(32, 8)>>>(i_batch, ih, ihT, NI);
    conv_trans<<<dim3(DD / 32, NQ / 32, BB), dim3(32, 8)>>>(q_batch, qh, qhT, NQ);

    // ---- scores computed ONCE: S = i @ q^T * scale  (S^T serves attention 2) ----
    hgemm<0><<<dim3(NQ / 128, NI / 128, BB), 256, HG_SMEM>>>(
        ih, qh, S, nullptr, NI, NQ, DD,
        (long)NI * DD, (long)NQ * DD, (long)NI * NQ, SCALE, nullptr, nullptr, nullptr);
    transpose_f32<<<dim3(NQ / 32, NI / 32, BB), dim3(32, 8)>>>(S, ST, NI, NQ);

    // ---- attention 1: P1 = softmax(S, q_mask); iatt = P1 @ q ----
    softmax_rows<<<BB * NI, 128>>>(S, q_mask, NI, NQ, P1h, nullptr);
    hgemm<1><<<dim3(DD / 128, NI / 128, BB), 256, HG_SMEM>>>(
        P1h, qhT, iatt, iatth, NI, DD, NQ,
        (long)NI * NQ, (long)DD * NQ, (long)NI * DD, 1.f, nullptr, nullptr, nullptr);

    // ---- attention 2: P2 = softmax(S^T, i_mask); latt = P2 @ i ----
    softmax_rows<<<BB * NQ, 128>>>(ST, i_mask, NQ, NI, P2h, nullptr);
    hgemm<1><<<dim3(DD / 128, NQ / 128, BB), 256, HG_SMEM>>>(
        P2h, ihT, latt, latth, NQ, DD, NI,
        (long)NQ * NI, (long)DD * NI, (long)NQ * DD, 1.f, nullptr, nullptr, nullptr);

    // ---- attflat logits: relu(X @ W1 + b1) @ W2 + b2 ----
    fill_scalar<<<(BB * NI + 255) / 256, 256>>>(atti, BB * NI, lb2);
    fill_scalar<<<(BB * NQ + 255) / 256, 256>>>(attl, BB * NQ, ib2);

    transpose_h<<<dim3(DH / 32, DD / 32), dim3(32, 8)>>>(lW1, WT);
    hgemm<2><<<dim3(DH / 128, (BB * NI) / 128, 1), 256, HG_SMEM>>>(
        iatth, WT, nullptr, nullptr, BB * NI, DH, DD, 0, 0, 0, 1.f, lb1, lW2, atti);

    transpose_h<<<dim3(DH / 32, DD / 32), dim3(32, 8)>>>(iW1, WT);
    hgemm<2><<<dim3(DH / 128, (BB * NQ) / 128, 1), 256, HG_SMEM>>>(
        latth, WT, nullptr, nullptr, BB * NQ, DH, DD, 0, 0, 0, 1.f, ib1, iW2, attl);

    // ---- attflat softmax over sequence (i path emits i_weight) ----
    softmax_rows<<<BB, 128>>>(atti, i_mask, 1, NI, nullptr, out + 2 * BB * DD);
    softmax_rows<<<BB, 128>>>(attl, q_mask, 1, NQ, nullptr, nullptr);

    // ---- pooled = sum_m att * X ----
    pool_kernel<<<dim3(DD / 128, BB), 128>>>(iatt, atti, pooli, NI);
    pool_kernel<<<dim3(DD / 128, BB), 128>>>(latt, attl, pooll, NQ);

    // ---- final linears ----
    gemm128<<<dim3(DD / 128, 1, 1), 256>>>(pooli, lWm, out, BB, DD, DD, lbm);
    gemm128<<<dim3(DD / 128, 1, 1), 256>>>(pooll, iWm, out + BB * DD, BB, DD, DD, ibm);
}

// round 8
// speedup vs baseline: 3.6789x; 1.1318x over previous
#include <cuda_runtime.h>
#include <cuda_fp16.h>
#include <math.h>
#include <stdint.h>

// Problem dims
#define BB 64
#define NI 512
#define NQ 128
#define DD 640
#define DH 1280
#define NEGV (-65504.0f)

// ---------------- scratch (static __device__ arrays; no allocs) ----------------
__device__ float  g_S[BB * NI * NQ];
__device__ float  g_ST[BB * NQ * NI];
__device__ float  g_iatt[BB * NI * DD];
__device__ float  g_latt[BB * NQ * DD];
__device__ float  g_atti[BB * NI];
__device__ float  g_attl[BB * NQ];
__device__ float  g_pooli[BB * DD];
__device__ float  g_pooll[BB * DD];
__device__ __half g_ih[BB * NI * DD];
__device__ __half g_qh[BB * NQ * DD];
__device__ __half g_ihT[BB * DD * NI];
__device__ __half g_qhT[BB * DD * NQ];
__device__ __half g_P1h[BB * NI * NQ];
__device__ __half g_P2h[BB * NQ * NI];
__device__ __half g_latth[BB * NQ * DD];
__device__ __half g_qW1T[BB * DH * NQ];   // per-batch (q @ W1)^T  [1280,128] fp16
__device__ __half g_WT[DH * DD];

__device__ __forceinline__ uint32_t smem_u32(const void* p)
{
    uint32_t a;
    asm("{ .reg .u64 t; cvta.to.shared.u64 t, %1; cvt.u32.u64 %0, t; }" : "=r"(a) : "l"(p));
    return a;
}
__device__ __forceinline__ void ldmx4(uint32_t r[4], uint32_t addr)
{
    asm volatile("ldmatrix.sync.aligned.m8n8.x4.shared.b16 {%0,%1,%2,%3}, [%4];"
                 : "=r"(r[0]), "=r"(r[1]), "=r"(r[2]), "=r"(r[3]) : "r"(addr));
}
__device__ __forceinline__ void mma_f16(float c[4], const uint32_t a[4],
                                        uint32_t b0, uint32_t b1)
{
    asm volatile(
        "mma.sync.aligned.m16n8k16.row.col.f32.f16.f16.f32 "
        "{%0,%1,%2,%3}, {%4,%5,%6,%7}, {%8,%9}, {%0,%1,%2,%3};"
        : "+f"(c[0]), "+f"(c[1]), "+f"(c[2]), "+f"(c[3])
        : "r"(a[0]), "r"(a[1]), "r"(a[2]), "r"(a[3]), "r"(b0), "r"(b1));
}
__device__ __forceinline__ void cp16(uint32_t dst, const void* src)
{
    asm volatile("cp.async.ca.shared.global [%0], [%1], 16;" :: "r"(dst), "l"(src));
}
#define CP_COMMIT() asm volatile("cp.async.commit_group;" ::: "memory")
#define CP_WAIT0()  asm volatile("cp.async.wait_group 0;" ::: "memory")

// =============== fp16 tensor-core GEMM: C = alpha * A @ BT^T ===============
// A: [M,K] half row-major (stride sA per batch). BT: [N,K] half row-major (sB).
// EPI 0: store Cf (f32 * alpha)
// EPI 1: store Cf (f32) AND Ch (f16)
// EPI 2: fused attflat logits: attOut[zb*sC + m] += sum_n relu(acc+b1[n])*w2[n]
// EPI 3: store Ch (f16) only
// M,N %128==0, K %64==0. BK=64, 2-stage cp.async pipeline.
#define SSTR 72
#define STAGE_B (128 * SSTR * 2)
#define STAGE2_B (2 * STAGE_B)
#define HG_SMEM (2 * STAGE2_B)
template <int EPI>
__global__ __launch_bounds__(256, 2)
void hgemm(const __half* __restrict__ A, const __half* __restrict__ BT,
           float* __restrict__ Cf, __half* __restrict__ Ch,
           int M, int N, int K, long sA, long sB, long sC,
           float alpha,
           const float* __restrict__ b1, const float* __restrict__ w2,
           float* __restrict__ attOut)
{
    extern __shared__ __align__(16) char smx[];
    const uint32_t smb = smem_u32(smx);

    const int zb = blockIdx.z;
    A  += (long)zb * sA;
    BT += (long)zb * sB;

    const int tid  = threadIdx.x;
    const int lane = tid & 31;
    const int wid  = tid >> 5;
    const int gid  = lane >> 2, tig = lane & 3;
    const int warp_m = wid & 1, warp_n = wid >> 1;
    const int m0 = blockIdx.y * 128, n0 = blockIdx.x * 128;

    const int srow = tid >> 2;
    const int sco  = (tid & 3) * 16;
    const __half* Ag0 = A + (long)(m0 + srow) * K + sco;
    const __half* Ag1 = A + (long)(m0 + srow + 64) * K + sco;
    const __half* Bg0 = BT + (long)(n0 + srow) * K + sco;
    const __half* Bg1 = BT + (long)(n0 + srow + 64) * K + sco;
    const uint32_t dA0 = srow * (SSTR * 2) + (tid & 3) * 32;
    const uint32_t dA1 = (srow + 64) * (SSTR * 2) + (tid & 3) * 32;

    const uint32_t aRowOff = (warp_m * 64 + (lane & 15)) * (SSTR * 2) + (lane >> 4) * 16;
    const uint32_t bRowOff = STAGE_B + (warp_n * 32 + (lane & 15)) * (SSTR * 2) + (lane >> 4) * 16;

    float acc[4][4][4];
#pragma unroll
    for (int i = 0; i < 4; i++)
#pragma unroll
        for (int j = 0; j < 4; j++)
#pragma unroll
            for (int r = 0; r < 4; r++) acc[i][j][r] = 0.f;

    const int nc = K >> 6;

    {
        cp16(smb + dA0, Ag0);            cp16(smb + dA0 + 16, Ag0 + 8);
        cp16(smb + dA1, Ag1);            cp16(smb + dA1 + 16, Ag1 + 8);
        cp16(smb + STAGE_B + dA0, Bg0);  cp16(smb + STAGE_B + dA0 + 16, Bg0 + 8);
        cp16(smb + STAGE_B + dA1, Bg1);  cp16(smb + STAGE_B + dA1 + 16, Bg1 + 8);
        CP_COMMIT();
    }

#pragma unroll 1
    for (int c = 0; c < nc; ++c) {
        CP_WAIT0();
        __syncthreads();
        if (c + 1 < nc) {
            const uint32_t sb = smb + ((c + 1) & 1) * STAGE2_B;
            const long ko = (long)(c + 1) * 64;
            cp16(sb + dA0, Ag0 + ko);            cp16(sb + dA0 + 16, Ag0 + ko + 8);
            cp16(sb + dA1, Ag1 + ko);            cp16(sb + dA1 + 16, Ag1 + ko + 8);
            cp16(sb + STAGE_B + dA0, Bg0 + ko);  cp16(sb + STAGE_B + dA0 + 16, Bg0 + ko + 8);
            cp16(sb + STAGE_B + dA1, Bg1 + ko);  cp16(sb + STAGE_B + dA1 + 16, Bg1 + ko + 8);
            CP_COMMIT();
        }

        const uint32_t sb = smb + (c & 1) * STAGE2_B;
        const uint32_t aB = sb + aRowOff;
        const uint32_t bB = sb + bRowOff;
#pragma unroll
        for (int ks = 0; ks < 4; ++ks) {
            uint32_t b[2][4];
            ldmx4(b[0], bB + ks * 32);
            ldmx4(b[1], bB + 16 * (SSTR * 2) + ks * 32);
#pragma unroll
            for (int mt = 0; mt < 4; ++mt) {
                uint32_t a[4];
                ldmx4(a, aB + mt * 16 * (SSTR * 2) + ks * 32);
                mma_f16(acc[mt][0], a, b[0][0], b[0][2]);
                mma_f16(acc[mt][1], a, b[0][1], b[0][3]);
                mma_f16(acc[mt][2], a, b[1][0], b[1][2]);
                mma_f16(acc[mt][3], a, b[1][1], b[1][3]);
            }
        }
    }

    if (EPI == 2) {
        attOut += (long)zb * sC;
        float bv[8], wv[8];
#pragma unroll
        for (int nt = 0; nt < 4; nt++)
#pragma unroll
            for (int cc = 0; cc < 2; cc++) {
                int n = n0 + warp_n * 32 + nt * 8 + tig * 2 + cc;
                bv[nt * 2 + cc] = b1[n];
                wv[nt * 2 + cc] = w2[n];
            }
#pragma unroll
        for (int mt = 0; mt < 4; mt++) {
#pragma unroll
            for (int r = 0; r < 2; r++) {
                float s = 0.f;
#pragma unroll
                for (int nt = 0; nt < 4; nt++)
#pragma unroll
                    for (int cc = 0; cc < 2; cc++)
                        s += fmaxf(acc[mt][nt][r * 2 + cc] + bv[nt * 2 + cc], 0.f) * wv[nt * 2 + cc];
                s += __shfl_xor_sync(0xffffffffu, s, 1);
                s += __shfl_xor_sync(0xffffffffu, s, 2);
                if (tig == 0) {
                    int m = m0 + warp_m * 64 + mt * 16 + r * 8 + gid;
                    atomicAdd(attOut + m, s);
                }
            }
        }
    } else {
        if (EPI != 3) Cf += (long)zb * sC;
        if (EPI == 1 || EPI == 3) Ch += (long)zb * sC;
#pragma unroll
        for (int mt = 0; mt < 4; mt++) {
#pragma unroll
            for (int r = 0; r < 2; r++) {
                long m = m0 + warp_m * 64 + mt * 16 + r * 8 + gid;
#pragma unroll
                for (int nt = 0; nt < 4; nt++) {
                    int n = n0 + warp_n * 32 + nt * 8 + tig * 2;
                    float x = acc[mt][nt][r * 2 + 0] * alpha;
                    float y = acc[mt][nt][r * 2 + 1] * alpha;
                    if (EPI != 3)
                        *(float2*)(Cf + m * N + n) = make_float2(x, y);
                    if (EPI == 1 || EPI == 3)
                        *(__half2*)(Ch + m * N + n) = __floats2half2_rn(x, y);
                }
            }
        }
    }
}

// ---- f32 [Nseq,DD] -> fp16 same layout + fp16 transposed [DD,Nseq], per batch ----
__global__ void conv_trans(const float* __restrict__ X, __half* __restrict__ Xh,
                           __half* __restrict__ XhT, int Nseq)
{
    __shared__ float t[32][33];
    const long bo = (long)blockIdx.z * Nseq * DD;
    X += bo; Xh += bo; XhT += bo;
    const int d0 = blockIdx.x * 32, s0 = blockIdx.y * 32;
    const int tx = threadIdx.x;
#pragma unroll
    for (int i = threadIdx.y; i < 32; i += 8) {
        float v = X[(long)(s0 + i) * DD + d0 + tx];
        t[i][tx] = v;
        Xh[(long)(s0 + i) * DD + d0 + tx] = __float2half(v);
    }
    __syncthreads();
#pragma unroll
    for (int i = threadIdx.y; i < 32; i += 8)
        XhT[(long)(d0 + i) * Nseq + s0 + tx] = __float2half(t[tx][i]);
}

// ---- per-batch f32 transpose: X [R,C] -> XT [C,R] ----
__global__ void transpose_f32(const float* __restrict__ X, float* __restrict__ XT,
                              int R, int C)
{
    __shared__ float t[32][33];
    const long bo = (long)blockIdx.z * R * C;
    const int c0 = blockIdx.x * 32, r0 = blockIdx.y * 32;
    const int tx = threadIdx.x;
#pragma unroll
    for (int i = threadIdx.y; i < 32; i += 8)
        t[i][tx] = X[bo + (long)(r0 + i) * C + c0 + tx];
    __syncthreads();
#pragma unroll
    for (int i = threadIdx.y; i < 32; i += 8)
        XT[bo + (long)(c0 + i) * R + r0 + tx] = t[tx][i];
}

// ---- W1 (640x1280 f32) -> W1T (1280x640 fp16) ----
__global__ void transpose_h(const float* __restrict__ W, __half* __restrict__ WT)
{
    __shared__ float t[32][33];
    int c0 = blockIdx.x * 32, r0 = blockIdx.y * 32;
#pragma unroll
    for (int i = threadIdx.y; i < 32; i += 8)
        t[i][threadIdx.x] = W[(long)(r0 + i) * DH + c0 + threadIdx.x];
    __syncthreads();
#pragma unroll
    for (int i = threadIdx.y; i < 32; i += 8)
        WT[(long)(c0 + i) * DD + r0 + threadIdx.x] = __float2half(t[threadIdx.x][i]);
}

// ---------------- generic fp32 SGEMM (small final linears only) ----------------
__global__ __launch_bounds__(256, 2)
void gemm128(const float* __restrict__ A, const float* __restrict__ Bm,
             float* __restrict__ C, int M, int N, int K,
             const float* __restrict__ bias)
{
    __shared__ __align__(16) float As[16][128];
    __shared__ __align__(16) float Bs[16][128];

    const int m0  = blockIdx.y * 128;
    const int n0  = blockIdx.x * 128;
    const int tid = threadIdx.x;
    const int tx  = tid & 15;
    const int ty  = tid >> 4;

    float acc[8][8];
#pragma unroll
    for (int i = 0; i < 8; i++)
#pragma unroll
        for (int j = 0; j < 8; j++) acc[i][j] = 0.f;

    for (int k0 = 0; k0 < K; k0 += 16) {
#pragma unroll
        for (int i = 0; i < 2; i++) {
            int f  = tid + i * 256;
            int ml = f >> 2;
            int kl = (f & 3) << 2;
            float4 v = make_float4(0.f, 0.f, 0.f, 0.f);
            if (m0 + ml < M)
                v = *(const float4*)(A + (long)(m0 + ml) * K + (k0 + kl));
            As[kl + 0][ml] = v.x; As[kl + 1][ml] = v.y;
            As[kl + 2][ml] = v.z; As[kl + 3][ml] = v.w;
        }
#pragma unroll
        for (int i = 0; i < 2; i++) {
            int f  = tid + i * 256;
            int kl = f >> 5;
            int nl = (f & 31) << 2;
            float4 v = make_float4(0.f, 0.f, 0.f, 0.f);
            if (n0 + nl < N)
                v = *(const float4*)(Bm + (long)(k0 + kl) * N + (n0 + nl));
            *(float4*)&Bs[kl][nl] = v;
        }
        __syncthreads();

#pragma unroll
        for (int kk = 0; kk < 16; kk++) {
            float a[8], b[8];
            *(float4*)&a[0] = *(const float4*)&As[kk][ty * 4];
            *(float4*)&a[4] = *(const float4*)&As[kk][64 + ty * 4];
            *(float4*)&b[0] = *(const float4*)&Bs[kk][tx * 4];
            *(float4*)&b[4] = *(const float4*)&Bs[kk][64 + tx * 4];
#pragma unroll
            for (int i = 0; i < 8; i++)
#pragma unroll
                for (int j = 0; j < 8; j++)
                    acc[i][j] = fmaf(a[i], b[j], acc[i][j]);
        }
        __syncthreads();
    }

#pragma unroll
    for (int i = 0; i < 8; i++) {
        int m = m0 + ((i < 4) ? (ty * 4 + i) : (64 + ty * 4 + i - 4));
        if (m >= M) continue;
#pragma unroll
        for (int g = 0; g < 2; g++) {
            int n = n0 + g * 64 + tx * 4;
            float4 v;
            v.x = acc[i][g * 4 + 0] + bias[n];
            v.y = acc[i][g * 4 + 1] + bias[n + 1];
            v.z = acc[i][g * 4 + 2] + bias[n + 2];
            v.w = acc[i][g * 4 + 3] + bias[n + 3];
            *(float4*)(C + (long)m * N + n) = v;
        }
    }
}

// ---------------- masked row softmax ----------------
__device__ __forceinline__ float warpMax(float v)
{
#pragma unroll
    for (int o = 16; o > 0; o >>= 1) v = fmaxf(v, __shfl_xor_sync(0xffffffffu, v, o));
    return v;
}
__device__ __forceinline__ float warpSum(float v)
{
#pragma unroll
    for (int o = 16; o > 0; o >>= 1) v += __shfl_xor_sync(0xffffffffu, v, o);
    return v;
}

__global__ void softmax_rows(float* __restrict__ P,
                             const unsigned int* __restrict__ mask,
                             int rowsPerBatch, int N,
                             __half* __restrict__ pout,
                             float* __restrict__ wout)
{
    const int row = blockIdx.x;
    const int bb  = row / rowsPerBatch;
    float* prow = P + (long)row * N;
    const unsigned int* mrow = mask + (long)bb * N;
    const int tid = threadIdx.x;
    const int cnt = N >> 7;

    float v[4];
    float mx = -3.4e38f;
    for (int c = 0; c < cnt; c++) {
        int n = (c << 7) + tid;
        float x = prow[n];
        if (mrow[n] != 0u) x = NEGV;
        v[c] = x;
        mx = fmaxf(mx, x);
    }
    __shared__ float sr[4];
    float wm = warpMax(mx);
    if ((tid & 31) == 0) sr[tid >> 5] = wm;
    __syncthreads();
    mx = fmaxf(fmaxf(sr[0], sr[1]), fmaxf(sr[2], sr[3]));

    float sum = 0.f;
    for (int c = 0; c < cnt; c++) { v[c] = __expf(v[c] - mx); sum += v[c]; }
    __syncthreads();
    float ws = warpSum(sum);
    if ((tid & 31) == 0) sr[tid >> 5] = ws;
    __syncthreads();
    sum = sr[0] + sr[1] + sr[2] + sr[3];

    float inv = 1.f / sum;
    for (int c = 0; c < cnt; c++) {
        int n = (c << 7) + tid;
        float r = v[c] * inv;
        if (pout) pout[(long)row * N + n] = __float2half(r);
        else      prow[n] = r;
        if (wout) wout[(long)row * N + n] = r;
    }
}

// pooled[b, d] = sum_m att[b, m] * X[b, m, d]
__global__ void pool_kernel(const float* __restrict__ X,
                            const float* __restrict__ att,
                            float* __restrict__ pooled, int Nseq)
{
    int bb = blockIdx.y;
    int d  = blockIdx.x * 128 + threadIdx.x;
    const float* Xb = X + (long)bb * Nseq * DD + d;
    const float* ab = att + bb * Nseq;
    float a0 = 0.f, a1 = 0.f, a2 = 0.f, a3 = 0.f;
    for (int m = 0; m < Nseq; m += 4) {
        a0 = fmaf(ab[m + 0], Xb[(long)(m + 0) * DD], a0);
        a1 = fmaf(ab[m + 1], Xb[(long)(m + 1) * DD], a1);
        a2 = fmaf(ab[m + 2], Xb[(long)(m + 2) * DD], a2);
        a3 = fmaf(ab[m + 3], Xb[(long)(m + 3) * DD], a3);
    }
    pooled[bb * DD + d] = (a0 + a1) + (a2 + a3);
}

__global__ void fill_scalar(float* __restrict__ p, int n, const float* __restrict__ s)
{
    int i = blockIdx.x * 256 + threadIdx.x;
    if (i < n) p[i] = *s;
}

// ---------------------------------- launch ----------------------------------
extern "C" void kernel_launch(void* const* d_in, const int* in_sizes, int n_in,
                              void* d_out, int out_size)
{
    const float* i_batch = (const float*)d_in[0];
    const float* q_batch = (const float*)d_in[1];
    const unsigned int* i_mask = (const unsigned int*)d_in[2];
    const unsigned int* q_mask = (const unsigned int*)d_in[3];
    const float* lW1 = (const float*)d_in[4];
    const float* lb1 = (const float*)d_in[5];
    const float* lW2 = (const float*)d_in[6];
    const float* lb2 = (const float*)d_in[7];
    const float* lWm = (const float*)d_in[8];
    const float* lbm = (const float*)d_in[9];
    const float* iW1 = (const float*)d_in[10];
    const float* ib1 = (const float*)d_in[11];
    const float* iW2 = (const float*)d_in[12];
    const float* ib2 = (const float*)d_in[13];
    const float* iWm = (const float*)d_in[14];
    const float* ibm = (const float*)d_in[15];
    float* out = (float*)d_out;

    float *S, *ST, *iatt, *latt, *atti, *attl, *pooli, *pooll;
    __half *ih, *qh, *ihT, *qhT, *P1h, *P2h, *latth, *qW1T, *WT;
    cudaGetSymbolAddress((void**)&S, g_S);
    cudaGetSymbolAddress((void**)&ST, g_ST);
    cudaGetSymbolAddress((void**)&iatt, g_iatt);
    cudaGetSymbolAddress((void**)&latt, g_latt);
    cudaGetSymbolAddress((void**)&atti, g_atti);
    cudaGetSymbolAddress((void**)&attl, g_attl);
    cudaGetSymbolAddress((void**)&pooli, g_pooli);
    cudaGetSymbolAddress((void**)&pooll, g_pooll);
    cudaGetSymbolAddress((void**)&ih, g_ih);
    cudaGetSymbolAddress((void**)&qh, g_qh);
    cudaGetSymbolAddress((void**)&ihT, g_ihT);
    cudaGetSymbolAddress((void**)&qhT, g_qhT);
    cudaGetSymbolAddress((void**)&P1h, g_P1h);
    cudaGetSymbolAddress((void**)&P2h, g_P2h);
    cudaGetSymbolAddress((void**)&latth, g_latth);
    cudaGetSymbolAddress((void**)&qW1T, g_qW1T);
    cudaGetSymbolAddress((void**)&WT, g_WT);

    cudaFuncSetAttribute(hgemm<0>, cudaFuncAttributeMaxDynamicSharedMemorySize, HG_SMEM);
    cudaFuncSetAttribute(hgemm<1>, cudaFuncAttributeMaxDynamicSharedMemorySize, HG_SMEM);
    cudaFuncSetAttribute(hgemm<2>, cudaFuncAttributeMaxDynamicSharedMemorySize, HG_SMEM);
    cudaFuncSetAttribute(hgemm<3>, cudaFuncAttributeMaxDynamicSharedMemorySize, HG_SMEM);

    const float SCALE = 0.039528470752104744f;  // 1/sqrt(640)

    // ---- fp16 conversions + per-batch transposes ----
    conv_trans<<<dim3(DD / 32, NI / 32, BB), dim3(32, 8)>>>(i_batch, ih, ihT, NI);
    conv_trans<<<dim3(DD / 32, NQ / 32, BB), dim3(32, 8)>>>(q_batch, qh, qhT, NQ);

    // ---- scores computed ONCE: S = i @ q^T * scale (S^T serves attention 2) ----
    hgemm<0><<<dim3(NQ / 128, NI / 128, BB), 256, HG_SMEM>>>(
        ih, qh, S, nullptr, NI, NQ, DD,
        (long)NI * DD, (long)NQ * DD, (long)NI * NQ, SCALE, nullptr, nullptr, nullptr);
    transpose_f32<<<dim3(NQ / 32, NI / 32, BB), dim3(32, 8)>>>(S, ST, NI, NQ);

    // ---- attention 1: P1 = softmax(S, q_mask); iatt = P1 @ q (f32 for pooling) ----
    softmax_rows<<<BB * NI, 128>>>(S, q_mask, NI, NQ, P1h, nullptr);
    hgemm<0><<<dim3(DD / 128, NI / 128, BB), 256, HG_SMEM>>>(
        P1h, qhT, iatt, nullptr, NI, DD, NQ,
        (long)NI * NQ, (long)DD * NQ, (long)NI * DD, 1.f, nullptr, nullptr, nullptr);

    // ---- attention 2: P2 = softmax(S^T, i_mask); latt = P2 @ i (f32 + f16) ----
    softmax_rows<<<BB * NQ, 128>>>(ST, i_mask, NQ, NI, P2h, nullptr);
    hgemm<1><<<dim3(DD / 128, NQ / 128, BB), 256, HG_SMEM>>>(
        P2h, ihT, latt, latth, NQ, DD, NI,
        (long)NQ * NI, (long)DD * NI, (long)NQ * DD, 1.f, nullptr, nullptr, nullptr);

    // ---- attflat logits ----
    fill_scalar<<<(BB * NI + 255) / 256, 256>>>(atti, BB * NI, lb2);
    fill_scalar<<<(BB * NQ + 255) / 256, 256>>>(attl, BB * NQ, ib2);

    // i-path (FACTORED): logits = relu(P1 @ (q@lW1) + b1) @ lW2
    //   G1': qW1T[b] = lW1^T @ q[b]^T   [1280 x 128] fp16
    transpose_h<<<dim3(DH / 32, DD / 32), dim3(32, 8)>>>(lW1, WT);
    hgemm<3><<<dim3(NQ / 128, DH / 128, BB), 256, HG_SMEM>>>(
        WT, qh, nullptr, qW1T, DH, NQ, DD,
        0, (long)NQ * DD, (long)DH * NQ, 1.f, nullptr, nullptr, nullptr);
    //   G2: logits_i[b,m] += sum_n relu((P1h @ qW1)[m,n] + lb1[n]) * lW2[n]
    hgemm<2><<<dim3(DH / 128, NI / 128, BB), 256, HG_SMEM>>>(
        P1h, qW1T, nullptr, nullptr, NI, DH, NQ,
        (long)NI * NQ, (long)DH * NQ, NI, 1.f, lb1, lW2, atti);

    // l-path (direct): logits_l = relu(latt @ iW1 + ib1) @ iW2
    transpose_h<<<dim3(DH / 32, DD / 32), dim3(32, 8)>>>(iW1, WT);
    hgemm<2><<<dim3(DH / 128, (BB * NQ) / 128, 1), 256, HG_SMEM>>>(
        latth, WT, nullptr, nullptr, BB * NQ, DH, DD, 0, 0, 0, 1.f, ib1, iW2, attl);

    // ---- attflat softmax over sequence (i path emits i_weight) ----
    softmax_rows<<<BB, 128>>>(atti, i_mask, 1, NI, nullptr, out + 2 * BB * DD);
    softmax_rows<<<BB, 128>>>(attl, q_mask, 1, NQ, nullptr, nullptr);

    // ---- pooled = sum_m att * X ----
    pool_kernel<<<dim3(DD / 128, BB), 128>>>(iatt, atti, pooli, NI);
    pool_kernel<<<dim3(DD / 128, BB), 128>>>(latt, attl, pooll, NQ);

    // ---- final linears ----
    gemm128<<<dim3(DD / 128, 1, 1), 256>>>(pooli, lWm, out, BB, DD, DD, lbm);
    gemm128<<<dim3(DD / 128, 1, 1), 256>>>(pooll, iWm, out + BB * DD, BB, DD, DD, ibm);
}

// round 9
// speedup vs baseline: 4.1690x; 1.1332x over previous
#include <cuda_runtime.h>
#include <cuda_fp16.h>
#include <math.h>
#include <stdint.h>

// Problem dims
#define BB 64
#define NI 512
#define NQ 128
#define DD 640
#define DH 1280
#define NEGV (-65504.0f)

// ---------------- scratch (static __device__ arrays; no allocs) ----------------
__device__ float  g_S[BB * NI * NQ];
__device__ float  g_ST[BB * NQ * NI];
__device__ float  g_latt[BB * NQ * DD];
__device__ float  g_atti[BB * NI];
__device__ float  g_attl[BB * NQ];
__device__ float  g_w1[BB * NQ];
__device__ float  g_pooli[BB * DD];
__device__ float  g_pooll[BB * DD];
__device__ __half g_ih[BB * NI * DD];
__device__ __half g_qh[BB * NQ * DD];
__device__ __half g_ihT[BB * DD * NI];
__device__ __half g_qhT[BB * DD * NQ];
__device__ __half g_P1h[BB * NI * NQ];
__device__ __half g_P2h[BB * NQ * NI];
__device__ __half g_latth[BB * NQ * DD];
__device__ __half g_qW1T[BB * DH * NQ];   // per-batch (q @ lW1)^T [1280,128] fp16
__device__ __half g_WT[DH * DD];

__device__ __forceinline__ uint32_t smem_u32(const void* p)
{
    uint32_t a;
    asm("{ .reg .u64 t; cvta.to.shared.u64 t, %1; cvt.u32.u64 %0, t; }" : "=r"(a) : "l"(p));
    return a;
}
__device__ __forceinline__ void ldmx4(uint32_t r[4], uint32_t addr)
{
    asm volatile("ldmatrix.sync.aligned.m8n8.x4.shared.b16 {%0,%1,%2,%3}, [%4];"
                 : "=r"(r[0]), "=r"(r[1]), "=r"(r[2]), "=r"(r[3]) : "r"(addr));
}
__device__ __forceinline__ void mma_f16(float c[4], const uint32_t a[4],
                                        uint32_t b0, uint32_t b1)
{
    asm volatile(
        "mma.sync.aligned.m16n8k16.row.col.f32.f16.f16.f32 "
        "{%0,%1,%2,%3}, {%4,%5,%6,%7}, {%8,%9}, {%0,%1,%2,%3};"
        : "+f"(c[0]), "+f"(c[1]), "+f"(c[2]), "+f"(c[3])
        : "r"(a[0]), "r"(a[1]), "r"(a[2]), "r"(a[3]), "r"(b0), "r"(b1));
}
__device__ __forceinline__ void cp16(uint32_t dst, const void* src)
{
    asm volatile("cp.async.ca.shared.global [%0], [%1], 16;" :: "r"(dst), "l"(src));
}
#define CP_COMMIT() asm volatile("cp.async.commit_group;" ::: "memory")
#define CP_WAIT0()  asm volatile("cp.async.wait_group 0;" ::: "memory")

// =============== fp16 tensor-core GEMM: C = alpha * A @ BT^T ===============
// EPI 0: store Cf (f32 * alpha)
// EPI 1: store Cf (f32) AND Ch (f16)
// EPI 2: fused attflat logits: attOut[zb*sC + m] += sum_n relu(acc+b1[n])*w2[n]
// EPI 3: store Ch (f16) only
#define SSTR 72
#define STAGE_B (128 * SSTR * 2)
#define STAGE2_B (2 * STAGE_B)
#define HG_SMEM (2 * STAGE2_B)
template <int EPI>
__global__ __launch_bounds__(256, 2)
void hgemm(const __half* __restrict__ A, const __half* __restrict__ BT,
           float* __restrict__ Cf, __half* __restrict__ Ch,
           int M, int N, int K, long sA, long sB, long sC,
           float alpha,
           const float* __restrict__ b1, const float* __restrict__ w2,
           float* __restrict__ attOut)
{
    extern __shared__ __align__(16) char smx[];
    const uint32_t smb = smem_u32(smx);

    const int zb = blockIdx.z;
    A  += (long)zb * sA;
    BT += (long)zb * sB;

    const int tid  = threadIdx.x;
    const int lane = tid & 31;
    const int wid  = tid >> 5;
    const int gid  = lane >> 2, tig = lane & 3;
    const int warp_m = wid & 1, warp_n = wid >> 1;
    const int m0 = blockIdx.y * 128, n0 = blockIdx.x * 128;

    const int srow = tid >> 2;
    const int sco  = (tid & 3) * 16;
    const __half* Ag0 = A + (long)(m0 + srow) * K + sco;
    const __half* Ag1 = A + (long)(m0 + srow + 64) * K + sco;
    const __half* Bg0 = BT + (long)(n0 + srow) * K + sco;
    const __half* Bg1 = BT + (long)(n0 + srow + 64) * K + sco;
    const uint32_t dA0 = srow * (SSTR * 2) + (tid & 3) * 32;
    const uint32_t dA1 = (srow + 64) * (SSTR * 2) + (tid & 3) * 32;

    const uint32_t aRowOff = (warp_m * 64 + (lane & 15)) * (SSTR * 2) + (lane >> 4) * 16;
    const uint32_t bRowOff = STAGE_B + (warp_n * 32 + (lane & 15)) * (SSTR * 2) + (lane >> 4) * 16;

    float acc[4][4][4];
#pragma unroll
    for (int i = 0; i < 4; i++)
#pragma unroll
        for (int j = 0; j < 4; j++)
#pragma unroll
            for (int r = 0; r < 4; r++) acc[i][j][r] = 0.f;

    const int nc = K >> 6;

    {
        cp16(smb + dA0, Ag0);            cp16(smb + dA0 + 16, Ag0 + 8);
        cp16(smb + dA1, Ag1);            cp16(smb + dA1 + 16, Ag1 + 8);
        cp16(smb + STAGE_B + dA0, Bg0);  cp16(smb + STAGE_B + dA0 + 16, Bg0 + 8);
        cp16(smb + STAGE_B + dA1, Bg1);  cp16(smb + STAGE_B + dA1 + 16, Bg1 + 8);
        CP_COMMIT();
    }

#pragma unroll 1
    for (int c = 0; c < nc; ++c) {
        CP_WAIT0();
        __syncthreads();
        if (c + 1 < nc) {
            const uint32_t sb = smb + ((c + 1) & 1) * STAGE2_B;
            const long ko = (long)(c + 1) * 64;
            cp16(sb + dA0, Ag0 + ko);            cp16(sb + dA0 + 16, Ag0 + ko + 8);
            cp16(sb + dA1, Ag1 + ko);            cp16(sb + dA1 + 16, Ag1 + ko + 8);
            cp16(sb + STAGE_B + dA0, Bg0 + ko);  cp16(sb + STAGE_B + dA0 + 16, Bg0 + ko + 8);
            cp16(sb + STAGE_B + dA1, Bg1 + ko);  cp16(sb + STAGE_B + dA1 + 16, Bg1 + ko + 8);
            CP_COMMIT();
        }

        const uint32_t sb = smb + (c & 1) * STAGE2_B;
        const uint32_t aB = sb + aRowOff;
        const uint32_t bB = sb + bRowOff;
#pragma unroll
        for (int ks = 0; ks < 4; ++ks) {
            uint32_t b[2][4];
            ldmx4(b[0], bB + ks * 32);
            ldmx4(b[1], bB + 16 * (SSTR * 2) + ks * 32);
#pragma unroll
            for (int mt = 0; mt < 4; ++mt) {
                uint32_t a[4];
                ldmx4(a, aB + mt * 16 * (SSTR * 2) + ks * 32);
                mma_f16(acc[mt][0], a, b[0][0], b[0][2]);
                mma_f16(acc[mt][1], a, b[0][1], b[0][3]);
                mma_f16(acc[mt][2], a, b[1][0], b[1][2]);
                mma_f16(acc[mt][3], a, b[1][1], b[1][3]);
            }
        }
    }

    if (EPI == 2) {
        attOut += (long)zb * sC;
        float bv[8], wv[8];
#pragma unroll
        for (int nt = 0; nt < 4; nt++)
#pragma unroll
            for (int cc = 0; cc < 2; cc++) {
                int n = n0 + warp_n * 32 + nt * 8 + tig * 2 + cc;
                bv[nt * 2 + cc] = b1[n];
                wv[nt * 2 + cc] = w2[n];
            }
#pragma unroll
        for (int mt = 0; mt < 4; mt++) {
#pragma unroll
            for (int r = 0; r < 2; r++) {
                float s = 0.f;
#pragma unroll
                for (int nt = 0; nt < 4; nt++)
#pragma unroll
                    for (int cc = 0; cc < 2; cc++)
                        s += fmaxf(acc[mt][nt][r * 2 + cc] + bv[nt * 2 + cc], 0.f) * wv[nt * 2 + cc];
                s += __shfl_xor_sync(0xffffffffu, s, 1);
                s += __shfl_xor_sync(0xffffffffu, s, 2);
                if (tig == 0) {
                    int m = m0 + warp_m * 64 + mt * 16 + r * 8 + gid;
                    atomicAdd(attOut + m, s);
                }
            }
        }
    } else {
        if (EPI != 3) Cf += (long)zb * sC;
        if (EPI == 1 || EPI == 3) Ch += (long)zb * sC;
#pragma unroll
        for (int mt = 0; mt < 4; mt++) {
#pragma unroll
            for (int r = 0; r < 2; r++) {
                long m = m0 + warp_m * 64 + mt * 16 + r * 8 + gid;
#pragma unroll
                for (int nt = 0; nt < 4; nt++) {
                    int n = n0 + warp_n * 32 + nt * 8 + tig * 2;
                    float x = acc[mt][nt][r * 2 + 0] * alpha;
                    float y = acc[mt][nt][r * 2 + 1] * alpha;
                    if (EPI != 3)
                        *(float2*)(Cf + m * N + n) = make_float2(x, y);
                    if (EPI == 1 || EPI == 3)
                        *(__half2*)(Ch + m * N + n) = __floats2half2_rn(x, y);
                }
            }
        }
    }
}

// ---- f32 [Nseq,DD] -> fp16 same layout + fp16 transposed [DD,Nseq], per batch ----
__global__ void conv_trans(const float* __restrict__ X, __half* __restrict__ Xh,
                           __half* __restrict__ XhT, int Nseq)
{
    __shared__ float t[32][33];
    const long bo = (long)blockIdx.z * Nseq * DD;
    X += bo; Xh += bo; XhT += bo;
    const int d0 = blockIdx.x * 32, s0 = blockIdx.y * 32;
    const int tx = threadIdx.x;
#pragma unroll
    for (int i = threadIdx.y; i < 32; i += 8) {
        float v = X[(long)(s0 + i) * DD + d0 + tx];
        t[i][tx] = v;
        Xh[(long)(s0 + i) * DD + d0 + tx] = __float2half(v);
    }
    __syncthreads();
#pragma unroll
    for (int i = threadIdx.y; i < 32; i += 8)
        XhT[(long)(d0 + i) * Nseq + s0 + tx] = __float2half(t[tx][i]);
}

// ---- per-batch f32 transpose: X [R,C] -> XT [C,R] ----
__global__ void transpose_f32(const float* __restrict__ X, float* __restrict__ XT,
                              int R, int C)
{
    __shared__ float t[32][33];
    const long bo = (long)blockIdx.z * R * C;
    const int c0 = blockIdx.x * 32, r0 = blockIdx.y * 32;
    const int tx = threadIdx.x;
#pragma unroll
    for (int i = threadIdx.y; i < 32; i += 8)
        t[i][tx] = X[bo + (long)(r0 + i) * C + c0 + tx];
    __syncthreads();
#pragma unroll
    for (int i = threadIdx.y; i < 32; i += 8)
        XT[bo + (long)(c0 + i) * R + r0 + tx] = t[tx][i];
}

// ---- W1 (640x1280 f32) -> W1T (1280x640 fp16) ----
__global__ void transpose_h(const float* __restrict__ W, __half* __restrict__ WT)
{
    __shared__ float t[32][33];
    int c0 = blockIdx.x * 32, r0 = blockIdx.y * 32;
#pragma unroll
    for (int i = threadIdx.y; i < 32; i += 8)
        t[i][threadIdx.x] = W[(long)(r0 + i) * DH + c0 + threadIdx.x];
    __syncthreads();
#pragma unroll
    for (int i = threadIdx.y; i < 32; i += 8)
        WT[(long)(c0 + i) * DD + r0 + threadIdx.x] = __float2half(t[threadIdx.x][i]);
}

// ---------------- generic fp32 SGEMM (small final linears only) ----------------
__global__ __launch_bounds__(256, 2)
void gemm128(const float* __restrict__ A, const float* __restrict__ Bm,
             float* __restrict__ C, int M, int N, int K,
             const float* __restrict__ bias)
{
    __shared__ __align__(16) float As[16][128];
    __shared__ __align__(16) float Bs[16][128];

    const int m0  = blockIdx.y * 128;
    const int n0  = blockIdx.x * 128;
    const int tid = threadIdx.x;
    const int tx  = tid & 15;
    const int ty  = tid >> 4;

    float acc[8][8];
#pragma unroll
    for (int i = 0; i < 8; i++)
#pragma unroll
        for (int j = 0; j < 8; j++) acc[i][j] = 0.f;

    for (int k0 = 0; k0 < K; k0 += 16) {
#pragma unroll
        for (int i = 0; i < 2; i++) {
            int f  = tid + i * 256;
            int ml = f >> 2;
            int kl = (f & 3) << 2;
            float4 v = make_float4(0.f, 0.f, 0.f, 0.f);
            if (m0 + ml < M)
                v = *(const float4*)(A + (long)(m0 + ml) * K + (k0 + kl));
            As[kl + 0][ml] = v.x; As[kl + 1][ml] = v.y;
            As[kl + 2][ml] = v.z; As[kl + 3][ml] = v.w;
        }
#pragma unroll
        for (int i = 0; i < 2; i++) {
            int f  = tid + i * 256;
            int kl = f >> 5;
            int nl = (f & 31) << 2;
            float4 v = make_float4(0.f, 0.f, 0.f, 0.f);
            if (n0 + nl < N)
                v = *(const float4*)(Bm + (long)(k0 + kl) * N + (n0 + nl));
            *(float4*)&Bs[kl][nl] = v;
        }
        __syncthreads();

#pragma unroll
        for (int kk = 0; kk < 16; kk++) {
            float a[8], b[8];
            *(float4*)&a[0] = *(const float4*)&As[kk][ty * 4];
            *(float4*)&a[4] = *(const float4*)&As[kk][64 + ty * 4];
            *(float4*)&b[0] = *(const float4*)&Bs[kk][tx * 4];
            *(float4*)&b[4] = *(const float4*)&Bs[kk][64 + tx * 4];
#pragma unroll
            for (int i = 0; i < 8; i++)
#pragma unroll
                for (int j = 0; j < 8; j++)
                    acc[i][j] = fmaf(a[i], b[j], acc[i][j]);
        }
        __syncthreads();
    }

#pragma unroll
    for (int i = 0; i < 8; i++) {
        int m = m0 + ((i < 4) ? (ty * 4 + i) : (64 + ty * 4 + i - 4));
        if (m >= M) continue;
#pragma unroll
        for (int g = 0; g < 2; g++) {
            int n = n0 + g * 64 + tx * 4;
            float4 v;
            v.x = acc[i][g * 4 + 0] + bias[n];
            v.y = acc[i][g * 4 + 1] + bias[n + 1];
            v.z = acc[i][g * 4 + 2] + bias[n + 2];
            v.w = acc[i][g * 4 + 3] + bias[n + 3];
            *(float4*)(C + (long)m * N + n) = v;
        }
    }
}

// ---------------- masked row softmax ----------------
__device__ __forceinline__ float warpMax(float v)
{
#pragma unroll
    for (int o = 16; o > 0; o >>= 1) v = fmaxf(v, __shfl_xor_sync(0xffffffffu, v, o));
    return v;
}
__device__ __forceinline__ float warpSum(float v)
{
#pragma unroll
    for (int o = 16; o > 0; o >>= 1) v += __shfl_xor_sync(0xffffffffu, v, o);
    return v;
}

__global__ void softmax_rows(float* __restrict__ P,
                             const unsigned int* __restrict__ mask,
                             int rowsPerBatch, int N,
                             __half* __restrict__ pout,
                             float* __restrict__ wout)
{
    const int row = blockIdx.x;
    const int bb  = row / rowsPerBatch;
    float* prow = P + (long)row * N;
    const unsigned int* mrow = mask + (long)bb * N;
    const int tid = threadIdx.x;
    const int cnt = N >> 7;

    float v[4];
    float mx = -3.4e38f;
    for (int c = 0; c < cnt; c++) {
        int n = (c << 7) + tid;
        float x = prow[n];
        if (mrow[n] != 0u) x = NEGV;
        v[c] = x;
        mx = fmaxf(mx, x);
    }
    __shared__ float sr[4];
    float wm = warpMax(mx);
    if ((tid & 31) == 0) sr[tid >> 5] = wm;
    __syncthreads();
    mx = fmaxf(fmaxf(sr[0], sr[1]), fmaxf(sr[2], sr[3]));

    float sum = 0.f;
    for (int c = 0; c < cnt; c++) { v[c] = __expf(v[c] - mx); sum += v[c]; }
    __syncthreads();
    float ws = warpSum(sum);
    if ((tid & 31) == 0) sr[tid >> 5] = ws;
    __syncthreads();
    sum = sr[0] + sr[1] + sr[2] + sr[3];

    float inv = 1.f / sum;
    for (int c = 0; c < cnt; c++) {
        int n = (c << 7) + tid;
        float r = v[c] * inv;
        if (pout) pout[(long)row * N + n] = __float2half(r);
        else      prow[n] = r;
        if (wout) wout[(long)row * N + n] = r;
    }
}

// ---- w1[b,k] = sum_m atti[b,m] * P1h[b,m,k]   (128 threads per batch) ----
__global__ void gemv_attP(const __half* __restrict__ P1h,
                          const float* __restrict__ atti,
                          float* __restrict__ w1)
{
    const int b = blockIdx.x;
    const int k = threadIdx.x;
    const __half* P = P1h + (long)b * NI * NQ + k;
    const float* a = atti + b * NI;
    float s0 = 0.f, s1 = 0.f, s2 = 0.f, s3 = 0.f;
#pragma unroll 4
    for (int m = 0; m < NI; m += 4) {
        s0 = fmaf(a[m + 0], __half2float(P[(long)(m + 0) * NQ]), s0);
        s1 = fmaf(a[m + 1], __half2float(P[(long)(m + 1) * NQ]), s1);
        s2 = fmaf(a[m + 2], __half2float(P[(long)(m + 2) * NQ]), s2);
        s3 = fmaf(a[m + 3], __half2float(P[(long)(m + 3) * NQ]), s3);
    }
    w1[b * NQ + k] = (s0 + s1) + (s2 + s3);
}

// ---- pooled_i[b,d] = sum_k w1[b,k] * qh[b,k,d] ----
__global__ void gemv_pool(const __half* __restrict__ qh,
                          const float* __restrict__ w1,
                          float* __restrict__ pooled)
{
    const int b = blockIdx.y;
    const int d = blockIdx.x * 128 + threadIdx.x;
    const __half* Q = qh + (long)b * NQ * DD + d;
    const float* w = w1 + b * NQ;
    float s0 = 0.f, s1 = 0.f, s2 = 0.f, s3 = 0.f;
#pragma unroll 4
    for (int k = 0; k < NQ; k += 4) {
        s0 = fmaf(w[k + 0], __half2float(Q[(long)(k + 0) * DD]), s0);
        s1 = fmaf(w[k + 1], __half2float(Q[(long)(k + 1) * DD]), s1);
        s2 = fmaf(w[k + 2], __half2float(Q[(long)(k + 2) * DD]), s2);
        s3 = fmaf(w[k + 3], __half2float(Q[(long)(k + 3) * DD]), s3);
    }
    pooled[b * DD + d] = (s0 + s1) + (s2 + s3);
}

// pooled[b, d] = sum_m att[b, m] * X[b, m, d]  (l-path only)
__global__ void pool_kernel(const float* __restrict__ X,
                            const float* __restrict__ att,
                            float* __restrict__ pooled, int Nseq)
{
    int bb = blockIdx.y;
    int d  = blockIdx.x * 128 + threadIdx.x;
    const float* Xb = X + (long)bb * Nseq * DD + d;
    const float* ab = att + bb * Nseq;
    float a0 = 0.f, a1 = 0.f, a2 = 0.f, a3 = 0.f;
    for (int m = 0; m < Nseq; m += 4) {
        a0 = fmaf(ab[m + 0], Xb[(long)(m + 0) * DD], a0);
        a1 = fmaf(ab[m + 1], Xb[(long)(m + 1) * DD], a1);
        a2 = fmaf(ab[m + 2], Xb[(long)(m + 2) * DD], a2);
        a3 = fmaf(ab[m + 3], Xb[(long)(m + 3) * DD], a3);
    }
    pooled[bb * DD + d] = (a0 + a1) + (a2 + a3);
}

__global__ void fill_scalar(float* __restrict__ p, int n, const float* __restrict__ s)
{
    int i = blockIdx.x * 256 + threadIdx.x;
    if (i < n) p[i] = *s;
}

// ---------------------------------- launch ----------------------------------
extern "C" void kernel_launch(void* const* d_in, const int* in_sizes, int n_in,
                              void* d_out, int out_size)
{
    const float* i_batch = (const float*)d_in[0];
    const float* q_batch = (const float*)d_in[1];
    const unsigned int* i_mask = (const unsigned int*)d_in[2];
    const unsigned int* q_mask = (const unsigned int*)d_in[3];
    const float* lW1 = (const float*)d_in[4];
    const float* lb1 = (const float*)d_in[5];
    const float* lW2 = (const float*)d_in[6];
    const float* lb2 = (const float*)d_in[7];
    const float* lWm = (const float*)d_in[8];
    const float* lbm = (const float*)d_in[9];
    const float* iW1 = (const float*)d_in[10];
    const float* ib1 = (const float*)d_in[11];
    const float* iW2 = (const float*)d_in[12];
    const float* ib2 = (const float*)d_in[13];
    const float* iWm = (const float*)d_in[14];
    const float* ibm = (const float*)d_in[15];
    float* out = (float*)d_out;

    float *S, *ST, *latt, *atti, *attl, *w1, *pooli, *pooll;
    __half *ih, *qh, *ihT, *qhT, *P1h, *P2h, *latth, *qW1T, *WT;
    cudaGetSymbolAddress((void**)&S, g_S);
    cudaGetSymbolAddress((void**)&ST, g_ST);
    cudaGetSymbolAddress((void**)&latt, g_latt);
    cudaGetSymbolAddress((void**)&atti, g_atti);
    cudaGetSymbolAddress((void**)&attl, g_attl);
    cudaGetSymbolAddress((void**)&w1, g_w1);
    cudaGetSymbolAddress((void**)&pooli, g_pooli);
    cudaGetSymbolAddress((void**)&pooll, g_pooll);
    cudaGetSymbolAddress((void**)&ih, g_ih);
    cudaGetSymbolAddress((void**)&qh, g_qh);
    cudaGetSymbolAddress((void**)&ihT, g_ihT);
    cudaGetSymbolAddress((void**)&qhT, g_qhT);
    cudaGetSymbolAddress((void**)&P1h, g_P1h);
    cudaGetSymbolAddress((void**)&P2h, g_P2h);
    cudaGetSymbolAddress((void**)&latth, g_latth);
    cudaGetSymbolAddress((void**)&qW1T, g_qW1T);
    cudaGetSymbolAddress((void**)&WT, g_WT);

    cudaFuncSetAttribute(hgemm<0>, cudaFuncAttributeMaxDynamicSharedMemorySize, HG_SMEM);
    cudaFuncSetAttribute(hgemm<1>, cudaFuncAttributeMaxDynamicSharedMemorySize, HG_SMEM);
    cudaFuncSetAttribute(hgemm<2>, cudaFuncAttributeMaxDynamicSharedMemorySize, HG_SMEM);
    cudaFuncSetAttribute(hgemm<3>, cudaFuncAttributeMaxDynamicSharedMemorySize, HG_SMEM);

    const float SCALE = 0.039528470752104744f;  // 1/sqrt(640)

    // ---- fp16 conversions + per-batch transposes ----
    conv_trans<<<dim3(DD / 32, NI / 32, BB), dim3(32, 8)>>>(i_batch, ih, ihT, NI);
    conv_trans<<<dim3(DD / 32, NQ / 32, BB), dim3(32, 8)>>>(q_batch, qh, qhT, NQ);

    // ---- scores computed ONCE: S = i @ q^T * scale (S^T serves attention 2) ----
    hgemm<0><<<dim3(NQ / 128, NI / 128, BB), 256, HG_SMEM>>>(
        ih, qh, S, nullptr, NI, NQ, DD,
        (long)NI * DD, (long)NQ * DD, (long)NI * NQ, SCALE, nullptr, nullptr, nullptr);
    transpose_f32<<<dim3(NQ / 32, NI / 32, BB), dim3(32, 8)>>>(S, ST, NI, NQ);

    // ---- P1 = softmax(S, q_mask) -> fp16 only (iatt never materialized) ----
    softmax_rows<<<BB * NI, 128>>>(S, q_mask, NI, NQ, P1h, nullptr);

    // ---- attention 2: P2 = softmax(S^T, i_mask); latt = P2 @ i (f32 + f16) ----
    softmax_rows<<<BB * NQ, 128>>>(ST, i_mask, NQ, NI, P2h, nullptr);
    hgemm<1><<<dim3(DD / 128, NQ / 128, BB), 256, HG_SMEM>>>(
        P2h, ihT, latt, latth, NQ, DD, NI,
        (long)NQ * NI, (long)DD * NI, (long)NQ * DD, 1.f, nullptr, nullptr, nullptr);

    // ---- attflat logits ----
    fill_scalar<<<(BB * NI + 255) / 256, 256>>>(atti, BB * NI, lb2);
    fill_scalar<<<(BB * NQ + 255) / 256, 256>>>(attl, BB * NQ, ib2);

    // i-path (FACTORED): logits_i = relu(P1 @ (q@lW1) + lb1) @ lW2
    transpose_h<<<dim3(DH / 32, DD / 32), dim3(32, 8)>>>(lW1, WT);
    hgemm<3><<<dim3(NQ / 128, DH / 128, BB), 256, HG_SMEM>>>(
        WT, qh, nullptr, qW1T, DH, NQ, DD,
        0, (long)NQ * DD, (long)DH * NQ, 1.f, nullptr, nullptr, nullptr);
    hgemm<2><<<dim3(DH / 128, NI / 128, BB), 256, HG_SMEM>>>(
        P1h, qW1T, nullptr, nullptr, NI, DH, NQ,
        (long)NI * NQ, (long)DH * NQ, NI, 1.f, lb1, lW2, atti);

    // l-path (direct): logits_l = relu(latt @ iW1 + ib1) @ iW2
    transpose_h<<<dim3(DH / 32, DD / 32), dim3(32, 8)>>>(iW1, WT);
    hgemm<2><<<dim3(DH / 128, (BB * NQ) / 128, 1), 256, HG_SMEM>>>(
        latth, WT, nullptr, nullptr, BB * NQ, DH, DD, 0, 0, 0, 1.f, ib1, iW2, attl);

    // ---- attflat softmax over sequence (i path emits i_weight) ----
    softmax_rows<<<BB, 128>>>(atti, i_mask, 1, NI, nullptr, out + 2 * BB * DD);
    softmax_rows<<<BB, 128>>>(attl, q_mask, 1, NQ, nullptr, nullptr);

    // ---- pooled_i = (atti @ P1) @ q   (factored through P1; no iatt) ----
    gemv_attP<<<BB, NQ>>>(P1h, atti, w1);
    gemv_pool<<<dim3(DD / 128, BB), 128>>>(qh, w1, pooli);

    // ---- pooled_l = attl @ latt ----
    pool_kernel<<<dim3(DD / 128, BB), 128>>>(latt, attl, pooll, NQ);

    // ---- final linears ----
    gemm128<<<dim3(DD / 128, 1, 1), 256>>>(pooli, lWm, out, BB, DD, DD, lbm);
    gemm128<<<dim3(DD / 128, 1, 1), 256>>>(pooll, iWm, out + BB * DD, BB, DD, DD, ibm);
}

// round 10
// speedup vs baseline: 4.2042x; 1.0084x over previous
#include <cuda_runtime.h>
#include <cuda_fp16.h>
#include <math.h>
#include <stdint.h>

// Problem dims
#define BB 64
#define NI 512
#define NQ 128
#define DD 640
#define DH 1280
#define NEGV (-65504.0f)

// ---------------- scratch (static __device__ arrays; no allocs) ----------------
__device__ float  g_S[BB * NI * NQ];
__device__ float  g_ST[BB * NQ * NI];
__device__ float  g_latt[BB * NQ * DD];
__device__ float  g_atti[BB * NI];
__device__ float  g_attl[BB * NQ];
__device__ float  g_w1[BB * NQ];
__device__ float  g_pooli[BB * DD];
__device__ float  g_pooll[BB * DD];
__device__ __half g_ih[BB * NI * DD];
__device__ __half g_qh[BB * NQ * DD];
__device__ __half g_ihT[BB * DD * NI];
__device__ __half g_qhT[BB * DD * NQ];
__device__ __half g_P1h[BB * NI * NQ];
__device__ __half g_P2h[BB * NQ * NI];
__device__ __half g_latth[BB * NQ * DD];
__device__ __half g_qW1T[BB * DH * NQ];
__device__ __half g_WT[DH * DD];

__device__ __forceinline__ uint32_t smem_u32(const void* p)
{
    uint32_t a;
    asm("{ .reg .u64 t; cvta.to.shared.u64 t, %1; cvt.u32.u64 %0, t; }" : "=r"(a) : "l"(p));
    return a;
}
__device__ __forceinline__ void ldmx4(uint32_t r[4], uint32_t addr)
{
    asm volatile("ldmatrix.sync.aligned.m8n8.x4.shared.b16 {%0,%1,%2,%3}, [%4];"
                 : "=r"(r[0]), "=r"(r[1]), "=r"(r[2]), "=r"(r[3]) : "r"(addr));
}
__device__ __forceinline__ void mma_f16(float c[4], const uint32_t a[4],
                                        uint32_t b0, uint32_t b1)
{
    asm volatile(
        "mma.sync.aligned.m16n8k16.row.col.f32.f16.f16.f32 "
        "{%0,%1,%2,%3}, {%4,%5,%6,%7}, {%8,%9}, {%0,%1,%2,%3};"
        : "+f"(c[0]), "+f"(c[1]), "+f"(c[2]), "+f"(c[3])
        : "r"(a[0]), "r"(a[1]), "r"(a[2]), "r"(a[3]), "r"(b0), "r"(b1));
}
__device__ __forceinline__ void mma_h16(uint32_t d[2], const uint32_t a[4],
                                        uint32_t b0, uint32_t b1)
{
    asm volatile(
        "mma.sync.aligned.m16n8k16.row.col.f16.f16.f16.f16 "
        "{%0,%1}, {%2,%3,%4,%5}, {%6,%7}, {%0,%1};"
        : "+r"(d[0]), "+r"(d[1])
        : "r"(a[0]), "r"(a[1]), "r"(a[2]), "r"(a[3]), "r"(b0), "r"(b1));
}
__device__ __forceinline__ void cp16(uint32_t dst, const void* src)
{
    asm volatile("cp.async.ca.shared.global [%0], [%1], 16;" :: "r"(dst), "l"(src));
}
#define CP_COMMIT() asm volatile("cp.async.commit_group;" ::: "memory")
#define CP_WAIT0()  asm volatile("cp.async.wait_group 0;" ::: "memory")

#define SSTR 72
#define STAGE_B (128 * SSTR * 2)
#define STAGE2_B (2 * STAGE_B)
#define HG_SMEM (2 * STAGE2_B)

// ---- shared mainloop macro body helpers (kept as code duplication for clarity) ----

// =============== fp32-accum fp16 GEMM: C = alpha * A @ BT^T ===============
// EPI 0: store Cf (f32 * alpha);  EPI 1: store Cf (f32) AND Ch (f16)
template <int EPI>
__global__ __launch_bounds__(256, 2)
void hgemm(const __half* __restrict__ A, const __half* __restrict__ BT,
           float* __restrict__ Cf, __half* __restrict__ Ch,
           int M, int N, int K, long sA, long sB, long sC,
           float alpha)
{
    extern __shared__ __align__(16) char smx[];
    const uint32_t smb = smem_u32(smx);

    const int zb = blockIdx.z;
    A  += (long)zb * sA;
    BT += (long)zb * sB;

    const int tid  = threadIdx.x;
    const int lane = tid & 31;
    const int wid  = tid >> 5;
    const int gid  = lane >> 2, tig = lane & 3;
    const int warp_m = wid & 1, warp_n = wid >> 1;
    const int m0 = blockIdx.y * 128, n0 = blockIdx.x * 128;

    const int srow = tid >> 2;
    const int sco  = (tid & 3) * 16;
    const __half* Ag0 = A + (long)(m0 + srow) * K + sco;
    const __half* Ag1 = A + (long)(m0 + srow + 64) * K + sco;
    const __half* Bg0 = BT + (long)(n0 + srow) * K + sco;
    const __half* Bg1 = BT + (long)(n0 + srow + 64) * K + sco;
    const uint32_t dA0 = srow * (SSTR * 2) + (tid & 3) * 32;
    const uint32_t dA1 = (srow + 64) * (SSTR * 2) + (tid & 3) * 32;

    const uint32_t aRowOff = (warp_m * 64 + (lane & 15)) * (SSTR * 2) + (lane >> 4) * 16;
    const uint32_t bRowOff = STAGE_B + (warp_n * 32 + (lane & 15)) * (SSTR * 2) + (lane >> 4) * 16;

    float acc[4][4][4];
#pragma unroll
    for (int i = 0; i < 4; i++)
#pragma unroll
        for (int j = 0; j < 4; j++)
#pragma unroll
            for (int r = 0; r < 4; r++) acc[i][j][r] = 0.f;

    const int nc = K >> 6;

    {
        cp16(smb + dA0, Ag0);            cp16(smb + dA0 + 16, Ag0 + 8);
        cp16(smb + dA1, Ag1);            cp16(smb + dA1 + 16, Ag1 + 8);
        cp16(smb + STAGE_B + dA0, Bg0);  cp16(smb + STAGE_B + dA0 + 16, Bg0 + 8);
        cp16(smb + STAGE_B + dA1, Bg1);  cp16(smb + STAGE_B + dA1 + 16, Bg1 + 8);
        CP_COMMIT();
    }

#pragma unroll 1
    for (int c = 0; c < nc; ++c) {
        CP_WAIT0();
        __syncthreads();
        if (c + 1 < nc) {
            const uint32_t sb = smb + ((c + 1) & 1) * STAGE2_B;
            const long ko = (long)(c + 1) * 64;
            cp16(sb + dA0, Ag0 + ko);            cp16(sb + dA0 + 16, Ag0 + ko + 8);
            cp16(sb + dA1, Ag1 + ko);            cp16(sb + dA1 + 16, Ag1 + ko + 8);
            cp16(sb + STAGE_B + dA0, Bg0 + ko);  cp16(sb + STAGE_B + dA0 + 16, Bg0 + ko + 8);
            cp16(sb + STAGE_B + dA1, Bg1 + ko);  cp16(sb + STAGE_B + dA1 + 16, Bg1 + ko + 8);
            CP_COMMIT();
        }

        const uint32_t sb = smb + (c & 1) * STAGE2_B;
        const uint32_t aB = sb + aRowOff;
        const uint32_t bB = sb + bRowOff;
#pragma unroll
        for (int ks = 0; ks < 4; ++ks) {
            uint32_t b[2][4];
            ldmx4(b[0], bB + ks * 32);
            ldmx4(b[1], bB + 16 * (SSTR * 2) + ks * 32);
#pragma unroll
            for (int mt = 0; mt < 4; ++mt) {
                uint32_t a[4];
                ldmx4(a, aB + mt * 16 * (SSTR * 2) + ks * 32);
                mma_f16(acc[mt][0], a, b[0][0], b[0][2]);
                mma_f16(acc[mt][1], a, b[0][1], b[0][3]);
                mma_f16(acc[mt][2], a, b[1][0], b[1][2]);
                mma_f16(acc[mt][3], a, b[1][1], b[1][3]);
            }
        }
    }

    Cf += (long)zb * sC;
    if (EPI == 1) Ch += (long)zb * sC;
#pragma unroll
    for (int mt = 0; mt < 4; mt++) {
#pragma unroll
        for (int r = 0; r < 2; r++) {
            long m = m0 + warp_m * 64 + mt * 16 + r * 8 + gid;
#pragma unroll
            for (int nt = 0; nt < 4; nt++) {
                int n = n0 + warp_n * 32 + nt * 8 + tig * 2;
                float x = acc[mt][nt][r * 2 + 0] * alpha;
                float y = acc[mt][nt][r * 2 + 1] * alpha;
                *(float2*)(Cf + m * N + n) = make_float2(x, y);
                if (EPI == 1)
                    *(__half2*)(Ch + m * N + n) = __floats2half2_rn(x, y);
            }
        }
    }
}

// =============== fp16-accum fp16 GEMM (2x HMMA rate) ===============
// EPI 2: fused attflat logits: attOut[zb*sC + m] += sum_n relu(acc+b1[n])*w2[n]
// EPI 3: store Ch (f16) only
template <int EPI>
__global__ __launch_bounds__(256, 2)
void hgemm_h(const __half* __restrict__ A, const __half* __restrict__ BT,
             __half* __restrict__ Ch,
             int M, int N, int K, long sA, long sB, long sC,
             const float* __restrict__ b1, const float* __restrict__ w2,
             float* __restrict__ attOut)
{
    extern __shared__ __align__(16) char smx[];
    const uint32_t smb = smem_u32(smx);

    const int zb = blockIdx.z;
    A  += (long)zb * sA;
    BT += (long)zb * sB;

    const int tid  = threadIdx.x;
    const int lane = tid & 31;
    const int wid  = tid >> 5;
    const int gid  = lane >> 2, tig = lane & 3;
    const int warp_m = wid & 1, warp_n = wid >> 1;
    const int m0 = blockIdx.y * 128, n0 = blockIdx.x * 128;

    const int srow = tid >> 2;
    const int sco  = (tid & 3) * 16;
    const __half* Ag0 = A + (long)(m0 + srow) * K + sco;
    const __half* Ag1 = A + (long)(m0 + srow + 64) * K + sco;
    const __half* Bg0 = BT + (long)(n0 + srow) * K + sco;
    const __half* Bg1 = BT + (long)(n0 + srow + 64) * K + sco;
    const uint32_t dA0 = srow * (SSTR * 2) + (tid & 3) * 32;
    const uint32_t dA1 = (srow + 64) * (SSTR * 2) + (tid & 3) * 32;

    const uint32_t aRowOff = (warp_m * 64 + (lane & 15)) * (SSTR * 2) + (lane >> 4) * 16;
    const uint32_t bRowOff = STAGE_B + (warp_n * 32 + (lane & 15)) * (SSTR * 2) + (lane >> 4) * 16;

    uint32_t hacc[4][4][2];
#pragma unroll
    for (int i = 0; i < 4; i++)
#pragma unroll
        for (int j = 0; j < 4; j++) { hacc[i][j][0] = 0u; hacc[i][j][1] = 0u; }

    const int nc = K >> 6;

    {
        cp16(smb + dA0, Ag0);            cp16(smb + dA0 + 16, Ag0 + 8);
        cp16(smb + dA1, Ag1);            cp16(smb + dA1 + 16, Ag1 + 8);
        cp16(smb + STAGE_B + dA0, Bg0);  cp16(smb + STAGE_B + dA0 + 16, Bg0 + 8);
        cp16(smb + STAGE_B + dA1, Bg1);  cp16(smb + STAGE_B + dA1 + 16, Bg1 + 8);
        CP_COMMIT();
    }

#pragma unroll 1
    for (int c = 0; c < nc; ++c) {
        CP_WAIT0();
        __syncthreads();
        if (c + 1 < nc) {
            const uint32_t sb = smb + ((c + 1) & 1) * STAGE2_B;
            const long ko = (long)(c + 1) * 64;
            cp16(sb + dA0, Ag0 + ko);            cp16(sb + dA0 + 16, Ag0 + ko + 8);
            cp16(sb + dA1, Ag1 + ko);            cp16(sb + dA1 + 16, Ag1 + ko + 8);
            cp16(sb + STAGE_B + dA0, Bg0 + ko);  cp16(sb + STAGE_B + dA0 + 16, Bg0 + ko + 8);
            cp16(sb + STAGE_B + dA1, Bg1 + ko);  cp16(sb + STAGE_B + dA1 + 16, Bg1 + ko + 8);
            CP_COMMIT();
        }

        const uint32_t sb = smb + (c & 1) * STAGE2_B;
        const uint32_t aB = sb + aRowOff;
        const uint32_t bB = sb + bRowOff;
#pragma unroll
        for (int ks = 0; ks < 4; ++ks) {
            uint32_t b[2][4];
            ldmx4(b[0], bB + ks * 32);
            ldmx4(b[1], bB + 16 * (SSTR * 2) + ks * 32);
#pragma unroll
            for (int mt = 0; mt < 4; ++mt) {
                uint32_t a[4];
                ldmx4(a, aB + mt * 16 * (SSTR * 2) + ks * 32);
                mma_h16(hacc[mt][0], a, b[0][0], b[0][2]);
                mma_h16(hacc[mt][1], a, b[0][1], b[0][3]);
                mma_h16(hacc[mt][2], a, b[1][0], b[1][2]);
                mma_h16(hacc[mt][3], a, b[1][1], b[1][3]);
            }
        }
    }

    if (EPI == 2) {
        attOut += (long)zb * sC;
        float bv[8], wv[8];
#pragma unroll
        for (int nt = 0; nt < 4; nt++)
#pragma unroll
            for (int cc = 0; cc < 2; cc++) {
                int n = n0 + warp_n * 32 + nt * 8 + tig * 2 + cc;
                bv[nt * 2 + cc] = b1[n];
                wv[nt * 2 + cc] = w2[n];
            }
#pragma unroll
        for (int mt = 0; mt < 4; mt++) {
#pragma unroll
            for (int r = 0; r < 2; r++) {
                float s = 0.f;
#pragma unroll
                for (int nt = 0; nt < 4; nt++) {
                    float2 v = __half22float2(*(__half2*)&hacc[mt][nt][r]);
                    s += fmaxf(v.x + bv[nt * 2 + 0], 0.f) * wv[nt * 2 + 0];
                    s += fmaxf(v.y + bv[nt * 2 + 1], 0.f) * wv[nt * 2 + 1];
                }
                s += __shfl_xor_sync(0xffffffffu, s, 1);
                s += __shfl_xor_sync(0xffffffffu, s, 2);
                if (tig == 0) {
                    int m = m0 + warp_m * 64 + mt * 16 + r * 8 + gid;
                    atomicAdd(attOut + m, s);
                }
            }
        }
    } else {
        Ch += (long)zb * sC;
#pragma unroll
        for (int mt = 0; mt < 4; mt++) {
#pragma unroll
            for (int r = 0; r < 2; r++) {
                long m = m0 + warp_m * 64 + mt * 16 + r * 8 + gid;
#pragma unroll
                for (int nt = 0; nt < 4; nt++) {
                    int n = n0 + warp_n * 32 + nt * 8 + tig * 2;
                    *(uint32_t*)(Ch + m * N + n) = hacc[mt][nt][r];
                }
            }
        }
    }
}

// ---- f32 [Nseq,DD] -> fp16 same layout + fp16 transposed [DD,Nseq], per batch ----
__global__ void conv_trans(const float* __restrict__ X, __half* __restrict__ Xh,
                           __half* __restrict__ XhT, int Nseq)
{
    __shared__ float t[32][33];
    const long bo = (long)blockIdx.z * Nseq * DD;
    X += bo; Xh += bo; XhT += bo;
    const int d0 = blockIdx.x * 32, s0 = blockIdx.y * 32;
    const int tx = threadIdx.x;
#pragma unroll
    for (int i = threadIdx.y; i < 32; i += 8) {
        float v = X[(long)(s0 + i) * DD + d0 + tx];
        t[i][tx] = v;
        Xh[(long)(s0 + i) * DD + d0 + tx] = __float2half(v);
    }
    __syncthreads();
#pragma unroll
    for (int i = threadIdx.y; i < 32; i += 8)
        XhT[(long)(d0 + i) * Nseq + s0 + tx] = __float2half(t[tx][i]);
}

// ---- per-batch f32 transpose: X [R,C] -> XT [C,R] ----
__global__ void transpose_f32(const float* __restrict__ X, float* __restrict__ XT,
                              int R, int C)
{
    __shared__ float t[32][33];
    const long bo = (long)blockIdx.z * R * C;
    const int c0 = blockIdx.x * 32, r0 = blockIdx.y * 32;
    const int tx = threadIdx.x;
#pragma unroll
    for (int i = threadIdx.y; i < 32; i += 8)
        t[i][tx] = X[bo + (long)(r0 + i) * C + c0 + tx];
    __syncthreads();
#pragma unroll
    for (int i = threadIdx.y; i < 32; i += 8)
        XT[bo + (long)(c0 + i) * R + r0 + tx] = t[tx][i];
}

// ---- W1 (640x1280 f32) -> W1T (1280x640 fp16) ----
__global__ void transpose_h(const float* __restrict__ W, __half* __restrict__ WT)
{
    __shared__ float t[32][33];
    int c0 = blockIdx.x * 32, r0 = blockIdx.y * 32;
#pragma unroll
    for (int i = threadIdx.y; i < 32; i += 8)
        t[i][threadIdx.x] = W[(long)(r0 + i) * DH + c0 + threadIdx.x];
    __syncthreads();
#pragma unroll
    for (int i = threadIdx.y; i < 32; i += 8)
        WT[(long)(c0 + i) * DD + r0 + threadIdx.x] = __float2half(t[threadIdx.x][i]);
}

// ---------------- generic fp32 SGEMM (small final linears only) ----------------
__global__ __launch_bounds__(256, 2)
void gemm128(const float* __restrict__ A, const float* __restrict__ Bm,
             float* __restrict__ C, int M, int N, int K,
             const float* __restrict__ bias)
{
    __shared__ __align__(16) float As[16][128];
    __shared__ __align__(16) float Bs[16][128];

    const int m0  = blockIdx.y * 128;
    const int n0  = blockIdx.x * 128;
    const int tid = threadIdx.x;
    const int tx  = tid & 15;
    const int ty  = tid >> 4;

    float acc[8][8];
#pragma unroll
    for (int i = 0; i < 8; i++)
#pragma unroll
        for (int j = 0; j < 8; j++) acc[i][j] = 0.f;

    for (int k0 = 0; k0 < K; k0 += 16) {
#pragma unroll
        for (int i = 0; i < 2; i++) {
            int f  = tid + i * 256;
            int ml = f >> 2;
            int kl = (f & 3) << 2;
            float4 v = make_float4(0.f, 0.f, 0.f, 0.f);
            if (m0 + ml < M)
                v = *(const float4*)(A + (long)(m0 + ml) * K + (k0 + kl));
            As[kl + 0][ml] = v.x; As[kl + 1][ml] = v.y;
            As[kl + 2][ml] = v.z; As[kl + 3][ml] = v.w;
        }
#pragma unroll
        for (int i = 0; i < 2; i++) {
            int f  = tid + i * 256;
            int kl = f >> 5;
            int nl = (f & 31) << 2;
            float4 v = make_float4(0.f, 0.f, 0.f, 0.f);
            if (n0 + nl < N)
                v = *(const float4*)(Bm + (long)(k0 + kl) * N + (n0 + nl));
            *(float4*)&Bs[kl][nl] = v;
        }
        __syncthreads();

#pragma unroll
        for (int kk = 0; kk < 16; kk++) {
            float a[8], b[8];
            *(float4*)&a[0] = *(const float4*)&As[kk][ty * 4];
            *(float4*)&a[4] = *(const float4*)&As[kk][64 + ty * 4];
            *(float4*)&b[0] = *(const float4*)&Bs[kk][tx * 4];
            *(float4*)&b[4] = *(const float4*)&Bs[kk][64 + tx * 4];
#pragma unroll
            for (int i = 0; i < 8; i++)
#pragma unroll
                for (int j = 0; j < 8; j++)
                    acc[i][j] = fmaf(a[i], b[j], acc[i][j]);
        }
        __syncthreads();
    }

#pragma unroll
    for (int i = 0; i < 8; i++) {
        int m = m0 + ((i < 4) ? (ty * 4 + i) : (64 + ty * 4 + i - 4));
        if (m >= M) continue;
#pragma unroll
        for (int g = 0; g < 2; g++) {
            int n = n0 + g * 64 + tx * 4;
            float4 v;
            v.x = acc[i][g * 4 + 0] + bias[n];
            v.y = acc[i][g * 4 + 1] + bias[n + 1];
            v.z = acc[i][g * 4 + 2] + bias[n + 2];
            v.w = acc[i][g * 4 + 3] + bias[n + 3];
            *(float4*)(C + (long)m * N + n) = v;
        }
    }
}

// ---------------- masked row softmax ----------------
__device__ __forceinline__ float warpMax(float v)
{
#pragma unroll
    for (int o = 16; o > 0; o >>= 1) v = fmaxf(v, __shfl_xor_sync(0xffffffffu, v, o));
    return v;
}
__device__ __forceinline__ float warpSum(float v)
{
#pragma unroll
    for (int o = 16; o > 0; o >>= 1) v += __shfl_xor_sync(0xffffffffu, v, o);
    return v;
}

__global__ void softmax_rows(float* __restrict__ P,
                             const unsigned int* __restrict__ mask,
                             int rowsPerBatch, int N,
                             __half* __restrict__ pout,
                             float* __restrict__ wout)
{
    const int row = blockIdx.x;
    const int bb  = row / rowsPerBatch;
    float* prow = P + (long)row * N;
    const unsigned int* mrow = mask + (long)bb * N;
    const int tid = threadIdx.x;
    const int cnt = N >> 7;

    float v[4];
    float mx = -3.4e38f;
    for (int c = 0; c < cnt; c++) {
        int n = (c << 7) + tid;
        float x = prow[n];
        if (mrow[n] != 0u) x = NEGV;
        v[c] = x;
        mx = fmaxf(mx, x);
    }
    __shared__ float sr[4];
    float wm = warpMax(mx);
    if ((tid & 31) == 0) sr[tid >> 5] = wm;
    __syncthreads();
    mx = fmaxf(fmaxf(sr[0], sr[1]), fmaxf(sr[2], sr[3]));

    float sum = 0.f;
    for (int c = 0; c < cnt; c++) { v[c] = __expf(v[c] - mx); sum += v[c]; }
    __syncthreads();
    float ws = warpSum(sum);
    if ((tid & 31) == 0) sr[tid >> 5] = ws;
    __syncthreads();
    sum = sr[0] + sr[1] + sr[2] + sr[3];

    float inv = 1.f / sum;
    for (int c = 0; c < cnt; c++) {
        int n = (c << 7) + tid;
        float r = v[c] * inv;
        if (pout) pout[(long)row * N + n] = __float2half(r);
        else      prow[n] = r;
        if (wout) wout[(long)row * N + n] = r;
    }
}

// ---- w1[b,k] = sum_m atti[b,m] * P1h[b,m,k] ----
__global__ void gemv_attP(const __half* __restrict__ P1h,
                          const float* __restrict__ atti,
                          float* __restrict__ w1)
{
    const int b = blockIdx.x;
    const int k = threadIdx.x;
    const __half* P = P1h + (long)b * NI * NQ + k;
    const float* a = atti + b * NI;
    float s0 = 0.f, s1 = 0.f, s2 = 0.f, s3 = 0.f;
#pragma unroll 4
    for (int m = 0; m < NI; m += 4) {
        s0 = fmaf(a[m + 0], __half2float(P[(long)(m + 0) * NQ]), s0);
        s1 = fmaf(a[m + 1], __half2float(P[(long)(m + 1) * NQ]), s1);
        s2 = fmaf(a[m + 2], __half2float(P[(long)(m + 2) * NQ]), s2);
        s3 = fmaf(a[m + 3], __half2float(P[(long)(m + 3) * NQ]), s3);
    }
    w1[b * NQ + k] = (s0 + s1) + (s2 + s3);
}

// ---- pooled_i[b,d] = sum_k w1[b,k] * qh[b,k,d] ----
__global__ void gemv_pool(const __half* __restrict__ qh,
                          const float* __restrict__ w1,
                          float* __restrict__ pooled)
{
    const int b = blockIdx.y;
    const int d = blockIdx.x * 128 + threadIdx.x;
    const __half* Q = qh + (long)b * NQ * DD + d;
    const float* w = w1 + b * NQ;
    float s0 = 0.f, s1 = 0.f, s2 = 0.f, s3 = 0.f;
#pragma unroll 4
    for (int k = 0; k < NQ; k += 4) {
        s0 = fmaf(w[k + 0], __half2float(Q[(long)(k + 0) * DD]), s0);
        s1 = fmaf(w[k + 1], __half2float(Q[(long)(k + 1) * DD]), s1);
        s2 = fmaf(w[k + 2], __half2float(Q[(long)(k + 2) * DD]), s2);
        s3 = fmaf(w[k + 3], __half2float(Q[(long)(k + 3) * DD]), s3);
    }
    pooled[b * DD + d] = (s0 + s1) + (s2 + s3);
}

// pooled[b, d] = sum_m att[b, m] * X[b, m, d]  (l-path only)
__global__ void pool_kernel(const float* __restrict__ X,
                            const float* __restrict__ att,
                            float* __restrict__ pooled, int Nseq)
{
    int bb = blockIdx.y;
    int d  = blockIdx.x * 128 + threadIdx.x;
    const float* Xb = X + (long)bb * Nseq * DD + d;
    const float* ab = att + bb * Nseq;
    float a0 = 0.f, a1 = 0.f, a2 = 0.f, a3 = 0.f;
    for (int m = 0; m < Nseq; m += 4) {
        a0 = fmaf(ab[m + 0], Xb[(long)(m + 0) * DD], a0);
        a1 = fmaf(ab[m + 1], Xb[(long)(m + 1) * DD], a1);
        a2 = fmaf(ab[m + 2], Xb[(long)(m + 2) * DD], a2);
        a3 = fmaf(ab[m + 3], Xb[(long)(m + 3) * DD], a3);
    }
    pooled[bb * DD + d] = (a0 + a1) + (a2 + a3);
}

__global__ void fill_scalar(float* __restrict__ p, int n, const float* __restrict__ s)
{
    int i = blockIdx.x * 256 + threadIdx.x;
    if (i < n) p[i] = *s;
}

// ---------------------------------- launch ----------------------------------
extern "C" void kernel_launch(void* const* d_in, const int* in_sizes, int n_in,
                              void* d_out, int out_size)
{
    const float* i_batch = (const float*)d_in[0];
    const float* q_batch = (const float*)d_in[1];
    const unsigned int* i_mask = (const unsigned int*)d_in[2];
    const unsigned int* q_mask = (const unsigned int*)d_in[3];
    const float* lW1 = (const float*)d_in[4];
    const float* lb1 = (const float*)d_in[5];
    const float* lW2 = (const float*)d_in[6];
    const float* lb2 = (const float*)d_in[7];
    const float* lWm = (const float*)d_in[8];
    const float* lbm = (const float*)d_in[9];
    const float* iW1 = (const float*)d_in[10];
    const float* ib1 = (const float*)d_in[11];
    const float* iW2 = (const float*)d_in[12];
    const float* ib2 = (const float*)d_in[13];
    const float* iWm = (const float*)d_in[14];
    const float* ibm = (const float*)d_in[15];
    float* out = (float*)d_out;

    float *S, *ST, *latt, *atti, *attl, *w1, *pooli, *pooll;
    __half *ih, *qh, *ihT, *qhT, *P1h, *P2h, *latth, *qW1T, *WT;
    cudaGetSymbolAddress((void**)&S, g_S);
    cudaGetSymbolAddress((void**)&ST, g_ST);
    cudaGetSymbolAddress((void**)&latt, g_latt);
    cudaGetSymbolAddress((void**)&atti, g_atti);
    cudaGetSymbolAddress((void**)&attl, g_attl);
    cudaGetSymbolAddress((void**)&w1, g_w1);
    cudaGetSymbolAddress((void**)&pooli, g_pooli);
    cudaGetSymbolAddress((void**)&pooll, g_pooll);
    cudaGetSymbolAddress((void**)&ih, g_ih);
    cudaGetSymbolAddress((void**)&qh, g_qh);
    cudaGetSymbolAddress((void**)&ihT, g_ihT);
    cudaGetSymbolAddress((void**)&qhT, g_qhT);
    cudaGetSymbolAddress((void**)&P1h, g_P1h);
    cudaGetSymbolAddress((void**)&P2h, g_P2h);
    cudaGetSymbolAddress((void**)&latth, g_latth);
    cudaGetSymbolAddress((void**)&qW1T, g_qW1T);
    cudaGetSymbolAddress((void**)&WT, g_WT);

    cudaFuncSetAttribute(hgemm<0>, cudaFuncAttributeMaxDynamicSharedMemorySize, HG_SMEM);
    cudaFuncSetAttribute(hgemm<1>, cudaFuncAttributeMaxDynamicSharedMemorySize, HG_SMEM);
    cudaFuncSetAttribute(hgemm_h<2>, cudaFuncAttributeMaxDynamicSharedMemorySize, HG_SMEM);
    cudaFuncSetAttribute(hgemm_h<3>, cudaFuncAttributeMaxDynamicSharedMemorySize, HG_SMEM);

    const float SCALE = 0.039528470752104744f;  // 1/sqrt(640)

    // ---- fp16 conversions + per-batch transposes ----
    conv_trans<<<dim3(DD / 32, NI / 32, BB), dim3(32, 8)>>>(i_batch, ih, ihT, NI);
    conv_trans<<<dim3(DD / 32, NQ / 32, BB), dim3(32, 8)>>>(q_batch, qh, qhT, NQ);

    // ---- scores ONCE (fp32 accum - direct output path) ----
    hgemm<0><<<dim3(NQ / 128, NI / 128, BB), 256, HG_SMEM>>>(
        ih, qh, S, nullptr, NI, NQ, DD,
        (long)NI * DD, (long)NQ * DD, (long)NI * NQ, SCALE);
    transpose_f32<<<dim3(NQ / 32, NI / 32, BB), dim3(32, 8)>>>(S, ST, NI, NQ);

    // ---- P1 = softmax(S, q_mask) -> fp16 ----
    softmax_rows<<<BB * NI, 128>>>(S, q_mask, NI, NQ, P1h, nullptr);

    // ---- attention 2: P2 = softmax(S^T, i_mask); latt = P2 @ i (fp32 accum) ----
    softmax_rows<<<BB * NQ, 128>>>(ST, i_mask, NQ, NI, P2h, nullptr);
    hgemm<1><<<dim3(DD / 128, NQ / 128, BB), 256, HG_SMEM>>>(
        P2h, ihT, latt, latth, NQ, DD, NI,
        (long)NQ * NI, (long)DD * NI, (long)NQ * DD, 1.f);

    // ---- attflat logits ----
    fill_scalar<<<(BB * NI + 255) / 256, 256>>>(atti, BB * NI, lb2);
    fill_scalar<<<(BB * NQ + 255) / 256, 256>>>(attl, BB * NQ, ib2);

    // i-path (FACTORED, f16-accum): logits_i = relu(P1 @ (q@lW1) + lb1) @ lW2
    transpose_h<<<dim3(DH / 32, DD / 32), dim3(32, 8)>>>(lW1, WT);
    hgemm_h<3><<<dim3(NQ / 128, DH / 128, BB), 256, HG_SMEM>>>(
        WT, qh, qW1T, DH, NQ, DD,
        0, (long)NQ * DD, (long)DH * NQ, nullptr, nullptr, nullptr);
    hgemm_h<2><<<dim3(DH / 128, NI / 128, BB), 256, HG_SMEM>>>(
        P1h, qW1T, nullptr, NI, DH, NQ,
        (long)NI * NQ, (long)DH * NQ, NI, lb1, lW2, atti);

    // l-path (direct, f16-accum): logits_l = relu(latt @ iW1 + ib1) @ iW2
    transpose_h<<<dim3(DH / 32, DD / 32), dim3(32, 8)>>>(iW1, WT);
    hgemm_h<2><<<dim3(DH / 128, (BB * NQ) / 128, 1), 256, HG_SMEM>>>(
        latth, WT, nullptr, BB * NQ, DH, DD, 0, 0, 0, ib1, iW2, attl);

    // ---- attflat softmax over sequence (i path emits i_weight) ----
    softmax_rows<<<BB, 128>>>(atti, i_mask, 1, NI, nullptr, out + 2 * BB * DD);
    softmax_rows<<<BB, 128>>>(attl, q_mask, 1, NQ, nullptr, nullptr);

    // ---- pooled_i = (atti @ P1) @ q ----
    gemv_attP<<<BB, NQ>>>(P1h, atti, w1);
    gemv_pool<<<dim3(DD / 128, BB), 128>>>(qh, w1, pooli);

    // ---- pooled_l = attl @ latt ----
    pool_kernel<<<dim3(DD / 128, BB), 128>>>(latt, attl, pooll, NQ);

    // ---- final linears ----
    gemm128<<<dim3(DD / 128, 1, 1), 256>>>(pooli, lWm, out, BB, DD, DD, lbm);
    gemm128<<<dim3(DD / 128, 1, 1), 256>>>(pooll, iWm, out + BB * DD, BB, DD, DD, ibm);
}

// round 11
// speedup vs baseline: 4.3887x; 1.0439x over previous
#include <cuda_runtime.h>
#include <cuda_fp16.h>
#include <math.h>
#include <stdint.h>

// Problem dims
#define BB 64
#define NI 512
#define NQ 128
#define DD 640
#define DH 1280
#define NEGV (-65504.0f)

// ---------------- scratch (static __device__ arrays; no allocs) ----------------
__device__ float  g_ST[BB * NQ * NI];     // raw scaled scores, transposed (64,128,512)
__device__ float  g_latt[BB * NQ * DD];
__device__ float  g_atti[BB * NI];
__device__ float  g_attl[BB * NQ];
__device__ float  g_w1[BB * NQ];
__device__ float  g_pooli[BB * DD];
__device__ float  g_pooll[BB * DD];
__device__ __half g_ih[BB * NI * DD];
__device__ __half g_qh[BB * NQ * DD];
__device__ __half g_ihT[BB * DD * NI];
__device__ __half g_P1h[BB * NI * NQ];
__device__ __half g_P2h[BB * NQ * NI];
__device__ __half g_latth[BB * NQ * DD];
__device__ __half g_qW1T[BB * DH * NQ];
__device__ __half g_WT[DH * DD];

__device__ __forceinline__ uint32_t smem_u32(const void* p)
{
    uint32_t a;
    asm("{ .reg .u64 t; cvta.to.shared.u64 t, %1; cvt.u32.u64 %0, t; }" : "=r"(a) : "l"(p));
    return a;
}
__device__ __forceinline__ void ldmx4(uint32_t r[4], uint32_t addr)
{
    asm volatile("ldmatrix.sync.aligned.m8n8.x4.shared.b16 {%0,%1,%2,%3}, [%4];"
                 : "=r"(r[0]), "=r"(r[1]), "=r"(r[2]), "=r"(r[3]) : "r"(addr));
}
__device__ __forceinline__ void mma_f16(float c[4], const uint32_t a[4],
                                        uint32_t b0, uint32_t b1)
{
    asm volatile(
        "mma.sync.aligned.m16n8k16.row.col.f32.f16.f16.f32 "
        "{%0,%1,%2,%3}, {%4,%5,%6,%7}, {%8,%9}, {%0,%1,%2,%3};"
        : "+f"(c[0]), "+f"(c[1]), "+f"(c[2]), "+f"(c[3])
        : "r"(a[0]), "r"(a[1]), "r"(a[2]), "r"(a[3]), "r"(b0), "r"(b1));
}
__device__ __forceinline__ void mma_h16(uint32_t d[2], const uint32_t a[4],
                                        uint32_t b0, uint32_t b1)
{
    asm volatile(
        "mma.sync.aligned.m16n8k16.row.col.f16.f16.f16.f16 "
        "{%0,%1}, {%2,%3,%4,%5}, {%6,%7}, {%0,%1};"
        : "+r"(d[0]), "+r"(d[1])
        : "r"(a[0]), "r"(a[1]), "r"(a[2]), "r"(a[3]), "r"(b0), "r"(b1));
}
__device__ __forceinline__ void cp16(uint32_t dst, const void* src)
{
    asm volatile("cp.async.ca.shared.global [%0], [%1], 16;" :: "r"(dst), "l"(src));
}
#define CP_COMMIT() asm volatile("cp.async.commit_group;" ::: "memory")
#define CP_WAIT0()  asm volatile("cp.async.wait_group 0;" ::: "memory")

#define SSTR 72
#define STAGE_B (128 * SSTR * 2)
#define STAGE2_B (2 * STAGE_B)
#define HG_SMEM (2 * STAGE2_B)

// ---- common 2-stage cp.async mainloop (macro to share between kernels) ----
#define HG_PROLOG_AND_VARS(Aptr, BTptr, Kdim)                                           \
    extern __shared__ __align__(16) char smx[];                                         \
    const uint32_t smb = smem_u32(smx);                                                 \
    const int tid  = threadIdx.x;                                                       \
    const int lane = tid & 31;                                                          \
    const int wid  = tid >> 5;                                                          \
    const int gid  = lane >> 2, tig = lane & 3;                                         \
    const int warp_m = wid & 1, warp_n = wid >> 1;                                      \
    const int m0 = blockIdx.y * 128, n0 = blockIdx.x * 128;                             \
    const int srow = tid >> 2;                                                          \
    const int sco  = (tid & 3) * 16;                                                    \
    const __half* Ag0 = (Aptr) + (long)(m0 + srow) * (Kdim) + sco;                      \
    const __half* Ag1 = (Aptr) + (long)(m0 + srow + 64) * (Kdim) + sco;                 \
    const __half* Bg0 = (BTptr) + (long)(n0 + srow) * (Kdim) + sco;                     \
    const __half* Bg1 = (BTptr) + (long)(n0 + srow + 64) * (Kdim) + sco;                \
    const uint32_t dA0 = srow * (SSTR * 2) + (tid & 3) * 32;                            \
    const uint32_t dA1 = (srow + 64) * (SSTR * 2) + (tid & 3) * 32;                     \
    const uint32_t aRowOff = (warp_m * 64 + (lane & 15)) * (SSTR * 2) + (lane >> 4) * 16;\
    const uint32_t bRowOff = STAGE_B + (warp_n * 32 + (lane & 15)) * (SSTR * 2) + (lane >> 4) * 16;

#define HG_ISSUE(sb, ko)                                                                 \
    do {                                                                                 \
        cp16((sb) + dA0, Ag0 + (ko));            cp16((sb) + dA0 + 16, Ag0 + (ko) + 8);  \
        cp16((sb) + dA1, Ag1 + (ko));            cp16((sb) + dA1 + 16, Ag1 + (ko) + 8);  \
        cp16((sb) + STAGE_B + dA0, Bg0 + (ko));  cp16((sb) + STAGE_B + dA0 + 16, Bg0 + (ko) + 8); \
        cp16((sb) + STAGE_B + dA1, Bg1 + (ko));  cp16((sb) + STAGE_B + dA1 + 16, Bg1 + (ko) + 8); \
        CP_COMMIT();                                                                     \
    } while (0)

// =============== fp32-accum fp16 GEMM: store Cf (f32) AND Ch (f16) ===============
__global__ __launch_bounds__(256, 2)
void hgemm_latt(const __half* __restrict__ A, const __half* __restrict__ BT,
                float* __restrict__ Cf, __half* __restrict__ Ch,
                int M, int N, int K, long sA, long sB, long sC)
{
    const int zb = blockIdx.z;
    A  += (long)zb * sA;
    BT += (long)zb * sB;
    HG_PROLOG_AND_VARS(A, BT, K)

    float acc[4][4][4];
#pragma unroll
    for (int i = 0; i < 4; i++)
#pragma unroll
        for (int j = 0; j < 4; j++)
#pragma unroll
            for (int r = 0; r < 4; r++) acc[i][j][r] = 0.f;

    const int nc = K >> 6;
    HG_ISSUE(smb, 0);
#pragma unroll 1
    for (int c = 0; c < nc; ++c) {
        CP_WAIT0();
        __syncthreads();
        if (c + 1 < nc) HG_ISSUE(smb + ((c + 1) & 1) * STAGE2_B, (long)(c + 1) * 64);
        const uint32_t sb = smb + (c & 1) * STAGE2_B;
        const uint32_t aB = sb + aRowOff;
        const uint32_t bB = sb + bRowOff;
#pragma unroll
        for (int ks = 0; ks < 4; ++ks) {
            uint32_t b[2][4];
            ldmx4(b[0], bB + ks * 32);
            ldmx4(b[1], bB + 16 * (SSTR * 2) + ks * 32);
#pragma unroll
            for (int mt = 0; mt < 4; ++mt) {
                uint32_t a[4];
                ldmx4(a, aB + mt * 16 * (SSTR * 2) + ks * 32);
                mma_f16(acc[mt][0], a, b[0][0], b[0][2]);
                mma_f16(acc[mt][1], a, b[0][1], b[0][3]);
                mma_f16(acc[mt][2], a, b[1][0], b[1][2]);
                mma_f16(acc[mt][3], a, b[1][1], b[1][3]);
            }
        }
    }

    Cf += (long)zb * sC;
    Ch += (long)zb * sC;
#pragma unroll
    for (int mt = 0; mt < 4; mt++) {
#pragma unroll
        for (int r = 0; r < 2; r++) {
            long m = m0 + warp_m * 64 + mt * 16 + r * 8 + gid;
#pragma unroll
            for (int nt = 0; nt < 4; nt++) {
                int n = n0 + warp_n * 32 + nt * 8 + tig * 2;
                float x = acc[mt][nt][r * 2 + 0];
                float y = acc[mt][nt][r * 2 + 1];
                *(float2*)(Cf + m * N + n) = make_float2(x, y);
                *(__half2*)(Ch + m * N + n) = __floats2half2_rn(x, y);
            }
        }
    }
}

// ========= scores GEMM with FUSED P1 softmax + transposed raw-score store =========
// grid (1, NI/128, BB). A = ih [NI,DD], BT = qh [NQ,DD].
// Writes: ST[b][n][m] = raw scaled score (for the P2 path),
//         P1h[b][m][n] = softmax_n(masked scaled score) in fp16.
__global__ __launch_bounds__(256, 2)
void hgemm_score(const __half* __restrict__ ihp, const __half* __restrict__ qhp,
                 float* __restrict__ ST, __half* __restrict__ P1h,
                 const unsigned int* __restrict__ qmask, float alpha)
{
    const int zb = blockIdx.z;
    const __half* A  = ihp + (long)zb * NI * DD;
    const __half* BT = qhp + (long)zb * NQ * DD;
    HG_PROLOG_AND_VARS(A, BT, DD)

    float acc[4][4][4];
#pragma unroll
    for (int i = 0; i < 4; i++)
#pragma unroll
        for (int j = 0; j < 4; j++)
#pragma unroll
            for (int r = 0; r < 4; r++) acc[i][j][r] = 0.f;

    const int nc = DD >> 6;
    HG_ISSUE(smb, 0);
#pragma unroll 1
    for (int c = 0; c < nc; ++c) {
        CP_WAIT0();
        __syncthreads();
        if (c + 1 < nc) HG_ISSUE(smb + ((c + 1) & 1) * STAGE2_B, (long)(c + 1) * 64);
        const uint32_t sb = smb + (c & 1) * STAGE2_B;
        const uint32_t aB = sb + aRowOff;
        const uint32_t bB = sb + bRowOff;
#pragma unroll
        for (int ks = 0; ks < 4; ++ks) {
            uint32_t b[2][4];
            ldmx4(b[0], bB + ks * 32);
            ldmx4(b[1], bB + 16 * (SSTR * 2) + ks * 32);
#pragma unroll
            for (int mt = 0; mt < 4; ++mt) {
                uint32_t a[4];
                ldmx4(a, aB + mt * 16 * (SSTR * 2) + ks * 32);
                mma_f16(acc[mt][0], a, b[0][0], b[0][2]);
                mma_f16(acc[mt][1], a, b[0][1], b[0][3]);
                mma_f16(acc[mt][2], a, b[1][0], b[1][2]);
                mma_f16(acc[mt][3], a, b[1][1], b[1][3]);
            }
        }
    }

    // ---- fused epilogue: reuse pipeline smem as a 128x128 f32 score tile ----
    __syncthreads();   // all warps done reading stage buffers
    float* Ssm = (float*)smx;                         // stride 129 (conflict-free)
    uint32_t* mkS = (uint32_t*)(smx + 128 * 129 * 4); // 128 mask words

#pragma unroll
    for (int mt = 0; mt < 4; mt++)
#pragma unroll
        for (int r = 0; r < 2; r++) {
            int m = warp_m * 64 + mt * 16 + r * 8 + gid;
#pragma unroll
            for (int nt = 0; nt < 4; nt++) {
                int n = warp_n * 32 + nt * 8 + tig * 2;
                Ssm[m * 129 + n]     = acc[mt][nt][r * 2 + 0] * alpha;
                Ssm[m * 129 + n + 1] = acc[mt][nt][r * 2 + 1] * alpha;
            }
        }
    if (tid < NQ) mkS[tid] = qmask[zb * NQ + tid];
    __syncthreads();

    // (a) transposed raw-score store: ST[b][n][m0+m]
    {
        float* STb = ST + (long)zb * NQ * NI + m0;
        for (int idx = tid; idx < 128 * 128; idx += 256) {
            int n = idx >> 7, m = idx & 127;
            STb[(long)n * NI + m] = Ssm[m * 129 + n];
        }
    }
    __syncthreads();

    // (b) row softmax over n (masked), write P1h fp16. 2 threads per row.
    {
        const int m = tid >> 1;
        const int h = (tid & 1) * 64;
        float* row = Ssm + m * 129;
        float mx = -3.4e38f;
#pragma unroll 8
        for (int j = 0; j < 64; j++) {
            int n = h + j;
            float x = (mkS[n] != 0u) ? NEGV : row[n];
            row[n] = x;
            mx = fmaxf(mx, x);
        }
        mx = fmaxf(mx, __shfl_xor_sync(0xffffffffu, mx, 1));
        float sum = 0.f;
#pragma unroll 8
        for (int j = 0; j < 64; j++) {
            float e = __expf(row[h + j] - mx);
            row[h + j] = e;
            sum += e;
        }
        sum += __shfl_xor_sync(0xffffffffu, sum, 1);
        float inv = 1.f / sum;
        __half2* P = (__half2*)(P1h + (long)zb * NI * NQ + (long)(m0 + m) * NQ + h);
#pragma unroll 8
        for (int j = 0; j < 32; j++)
            P[j] = __floats2half2_rn(row[h + 2 * j] * inv, row[h + 2 * j + 1] * inv);
    }
}

// =============== fp16-accum fp16 GEMM (logit-only paths) ===============
// EPI 2: fused attflat logits: attOut[zb*sC + m] += sum_n relu(acc+b1[n])*w2[n]
// EPI 3: store Ch (f16) only
template <int EPI>
__global__ __launch_bounds__(256, 2)
void hgemm_h(const __half* __restrict__ A, const __half* __restrict__ BT,
             __half* __restrict__ Ch,
             int M, int N, int K, long sA, long sB, long sC,
             const float* __restrict__ b1, const float* __restrict__ w2,
             float* __restrict__ attOut)
{
    const int zb = blockIdx.z;
    A  += (long)zb * sA;
    BT += (long)zb * sB;
    HG_PROLOG_AND_VARS(A, BT, K)

    uint32_t hacc[4][4][2];
#pragma unroll
    for (int i = 0; i < 4; i++)
#pragma unroll
        for (int j = 0; j < 4; j++) { hacc[i][j][0] = 0u; hacc[i][j][1] = 0u; }

    const int nc = K >> 6;
    HG_ISSUE(smb, 0);
#pragma unroll 1
    for (int c = 0; c < nc; ++c) {
        CP_WAIT0();
        __syncthreads();
        if (c + 1 < nc) HG_ISSUE(smb + ((c + 1) & 1) * STAGE2_B, (long)(c + 1) * 64);
        const uint32_t sb = smb + (c & 1) * STAGE2_B;
        const uint32_t aB = sb + aRowOff;
        const uint32_t bB = sb + bRowOff;
#pragma unroll
        for (int ks = 0; ks < 4; ++ks) {
            uint32_t b[2][4];
            ldmx4(b[0], bB + ks * 32);
            ldmx4(b[1], bB + 16 * (SSTR * 2) + ks * 32);
#pragma unroll
            for (int mt = 0; mt < 4; ++mt) {
                uint32_t a[4];
                ldmx4(a, aB + mt * 16 * (SSTR * 2) + ks * 32);
                mma_h16(hacc[mt][0], a, b[0][0], b[0][2]);
                mma_h16(hacc[mt][1], a, b[0][1], b[0][3]);
                mma_h16(hacc[mt][2], a, b[1][0], b[1][2]);
                mma_h16(hacc[mt][3], a, b[1][1], b[1][3]);
            }
        }
    }

    if (EPI == 2) {
        attOut += (long)zb * sC;
        float bv[8], wv[8];
#pragma unroll
        for (int nt = 0; nt < 4; nt++)
#pragma unroll
            for (int cc = 0; cc < 2; cc++) {
                int n = n0 + warp_n * 32 + nt * 8 + tig * 2 + cc;
                bv[nt * 2 + cc] = b1[n];
                wv[nt * 2 + cc] = w2[n];
            }
#pragma unroll
        for (int mt = 0; mt < 4; mt++) {
#pragma unroll
            for (int r = 0; r < 2; r++) {
                float s = 0.f;
#pragma unroll
                for (int nt = 0; nt < 4; nt++) {
                    float2 v = __half22float2(*(__half2*)&hacc[mt][nt][r]);
                    s += fmaxf(v.x + bv[nt * 2 + 0], 0.f) * wv[nt * 2 + 0];
                    s += fmaxf(v.y + bv[nt * 2 + 1], 0.f) * wv[nt * 2 + 1];
                }
                s += __shfl_xor_sync(0xffffffffu, s, 1);
                s += __shfl_xor_sync(0xffffffffu, s, 2);
                if (tig == 0) {
                    int m = m0 + warp_m * 64 + mt * 16 + r * 8 + gid;
                    atomicAdd(attOut + m, s);
                }
            }
        }
    } else {
        Ch += (long)zb * sC;
#pragma unroll
        for (int mt = 0; mt < 4; mt++) {
#pragma unroll
            for (int r = 0; r < 2; r++) {
                long m = m0 + warp_m * 64 + mt * 16 + r * 8 + gid;
#pragma unroll
                for (int nt = 0; nt < 4; nt++) {
                    int n = n0 + warp_n * 32 + nt * 8 + tig * 2;
                    *(uint32_t*)(Ch + m * N + n) = hacc[mt][nt][r];
                }
            }
        }
    }
}

// ---- f32 [Nseq,DD] -> fp16 same layout + fp16 transposed [DD,Nseq], per batch ----
__global__ void conv_trans(const float* __restrict__ X, __half* __restrict__ Xh,
                           __half* __restrict__ XhT, int Nseq)
{
    __shared__ float t[32][33];
    const long bo = (long)blockIdx.z * Nseq * DD;
    X += bo; Xh += bo; XhT += bo;
    const int d0 = blockIdx.x * 32, s0 = blockIdx.y * 32;
    const int tx = threadIdx.x;
#pragma unroll
    for (int i = threadIdx.y; i < 32; i += 8) {
        float v = X[(long)(s0 + i) * DD + d0 + tx];
        t[i][tx] = v;
        Xh[(long)(s0 + i) * DD + d0 + tx] = __float2half(v);
    }
    __syncthreads();
#pragma unroll
    for (int i = threadIdx.y; i < 32; i += 8)
        XhT[(long)(d0 + i) * Nseq + s0 + tx] = __float2half(t[tx][i]);
}

// ---- plain f32 -> fp16 convert (q path needs no transpose) ----
__global__ void conv_h(const float4* __restrict__ in, __half2* __restrict__ out, int n4)
{
    int i = blockIdx.x * 256 + threadIdx.x;
    if (i < n4) {
        float4 v = in[i];
        out[2 * i]     = __floats2half2_rn(v.x, v.y);
        out[2 * i + 1] = __floats2half2_rn(v.z, v.w);
    }
}

// ---- W1 (640x1280 f32) -> W1T (1280x640 fp16) ----
__global__ void transpose_h(const float* __restrict__ W, __half* __restrict__ WT)
{
    __shared__ float t[32][33];
    int c0 = blockIdx.x * 32, r0 = blockIdx.y * 32;
#pragma unroll
    for (int i = threadIdx.y; i < 32; i += 8)
        t[i][threadIdx.x] = W[(long)(r0 + i) * DH + c0 + threadIdx.x];
    __syncthreads();
#pragma unroll
    for (int i = threadIdx.y; i < 32; i += 8)
        WT[(long)(c0 + i) * DD + r0 + threadIdx.x] = __float2half(t[threadIdx.x][i]);
}

// ---------------- generic fp32 SGEMM (small final linears only) ----------------
__global__ __launch_bounds__(256, 2)
void gemm128(const float* __restrict__ A, const float* __restrict__ Bm,
             float* __restrict__ C, int M, int N, int K,
             const float* __restrict__ bias)
{
    __shared__ __align__(16) float As[16][128];
    __shared__ __align__(16) float Bs[16][128];

    const int m0  = blockIdx.y * 128;
    const int n0  = blockIdx.x * 128;
    const int tid = threadIdx.x;
    const int tx  = tid & 15;
    const int ty  = tid >> 4;

    float acc[8][8];
#pragma unroll
    for (int i = 0; i < 8; i++)
#pragma unroll
        for (int j = 0; j < 8; j++) acc[i][j] = 0.f;

    for (int k0 = 0; k0 < K; k0 += 16) {
#pragma unroll
        for (int i = 0; i < 2; i++) {
            int f  = tid + i * 256;
            int ml = f >> 2;
            int kl = (f & 3) << 2;
            float4 v = make_float4(0.f, 0.f, 0.f, 0.f);
            if (m0 + ml < M)
                v = *(const float4*)(A + (long)(m0 + ml) * K + (k0 + kl));
            As[kl + 0][ml] = v.x; As[kl + 1][ml] = v.y;
            As[kl + 2][ml] = v.z; As[kl + 3][ml] = v.w;
        }
#pragma unroll
        for (int i = 0; i < 2; i++) {
            int f  = tid + i * 256;
            int kl = f >> 5;
            int nl = (f & 31) << 2;
            float4 v = make_float4(0.f, 0.f, 0.f, 0.f);
            if (n0 + nl < N)
                v = *(const float4*)(Bm + (long)(k0 + kl) * N + (n0 + nl));
            *(float4*)&Bs[kl][nl] = v;
        }
        __syncthreads();

#pragma unroll
        for (int kk = 0; kk < 16; kk++) {
            float a[8], b[8];
            *(float4*)&a[0] = *(const float4*)&As[kk][ty * 4];
            *(float4*)&a[4] = *(const float4*)&As[kk][64 + ty * 4];
            *(float4*)&b[0] = *(const float4*)&Bs[kk][tx * 4];
            *(float4*)&b[4] = *(const float4*)&Bs[kk][64 + tx * 4];
#pragma unroll
            for (int i = 0; i < 8; i++)
#pragma unroll
                for (int j = 0; j < 8; j++)
                    acc[i][j] = fmaf(a[i], b[j], acc[i][j]);
        }
        __syncthreads();
    }

#pragma unroll
    for (int i = 0; i < 8; i++) {
        int m = m0 + ((i < 4) ? (ty * 4 + i) : (64 + ty * 4 + i - 4));
        if (m >= M) continue;
#pragma unroll
        for (int g = 0; g < 2; g++) {
            int n = n0 + g * 64 + tx * 4;
            float4 v;
            v.x = acc[i][g * 4 + 0] + bias[n];
            v.y = acc[i][g * 4 + 1] + bias[n + 1];
            v.z = acc[i][g * 4 + 2] + bias[n + 2];
            v.w = acc[i][g * 4 + 3] + bias[n + 3];
            *(float4*)(C + (long)m * N + n) = v;
        }
    }
}

// ---------------- masked row softmax ----------------
__device__ __forceinline__ float warpMax(float v)
{
#pragma unroll
    for (int o = 16; o > 0; o >>= 1) v = fmaxf(v, __shfl_xor_sync(0xffffffffu, v, o));
    return v;
}
__device__ __forceinline__ float warpSum(float v)
{
#pragma unroll
    for (int o = 16; o > 0; o >>= 1) v += __shfl_xor_sync(0xffffffffu, v, o);
    return v;
}

__global__ void softmax_rows(float* __restrict__ P,
                             const unsigned int* __restrict__ mask,
                             int rowsPerBatch, int N,
                             __half* __restrict__ pout,
                             float* __restrict__ wout)
{
    const int row = blockIdx.x;
    const int bb  = row / rowsPerBatch;
    float* prow = P + (long)row * N;
    const unsigned int* mrow = mask + (long)bb * N;
    const int tid = threadIdx.x;
    const int cnt = N >> 7;

    float v[4];
    float mx = -3.4e38f;
    for (int c = 0; c < cnt; c++) {
        int n = (c << 7) + tid;
        float x = prow[n];
        if (mrow[n] != 0u) x = NEGV;
        v[c] = x;
        mx = fmaxf(mx, x);
    }
    __shared__ float sr[4];
    float wm = warpMax(mx);
    if ((tid & 31) == 0) sr[tid >> 5] = wm;
    __syncthreads();
    mx = fmaxf(fmaxf(sr[0], sr[1]), fmaxf(sr[2], sr[3]));

    float sum = 0.f;
    for (int c = 0; c < cnt; c++) { v[c] = __expf(v[c] - mx); sum += v[c]; }
    __syncthreads();
    float ws = warpSum(sum);
    if ((tid & 31) == 0) sr[tid >> 5] = ws;
    __syncthreads();
    sum = sr[0] + sr[1] + sr[2] + sr[3];

    float inv = 1.f / sum;
    for (int c = 0; c < cnt; c++) {
        int n = (c << 7) + tid;
        float r = v[c] * inv;
        if (pout) pout[(long)row * N + n] = __float2half(r);
        else      prow[n] = r;
        if (wout) wout[(long)row * N + n] = r;
    }
}

// ---- w1[b,k] = sum_m atti[b,m] * P1h[b,m,k] ----
__global__ void gemv_attP(const __half* __restrict__ P1h,
                          const float* __restrict__ atti,
                          float* __restrict__ w1)
{
    const int b = blockIdx.x;
    const int k = threadIdx.x;
    const __half* P = P1h + (long)b * NI * NQ + k;
    const float* a = atti + b * NI;
    float s0 = 0.f, s1 = 0.f, s2 = 0.f, s3 = 0.f;
#pragma unroll 4
    for (int m = 0; m < NI; m += 4) {
        s0 = fmaf(a[m + 0], __half2float(P[(long)(m + 0) * NQ]), s0);
        s1 = fmaf(a[m + 1], __half2float(P[(long)(m + 1) * NQ]), s1);
        s2 = fmaf(a[m + 2], __half2float(P[(long)(m + 2) * NQ]), s2);
        s3 = fmaf(a[m + 3], __half2float(P[(long)(m + 3) * NQ]), s3);
    }
    w1[b * NQ + k] = (s0 + s1) + (s2 + s3);
}

// ---- pooled_i[b,d] = sum_k w1[b,k] * qh[b,k,d] ----
__global__ void gemv_pool(const __half* __restrict__ qh,
                          const float* __restrict__ w1,
                          float* __restrict__ pooled)
{
    const int b = blockIdx.y;
    const int d = blockIdx.x * 128 + threadIdx.x;
    const __half* Q = qh + (long)b * NQ * DD + d;
    const float* w = w1 + b * NQ;
    float s0 = 0.f, s1 = 0.f, s2 = 0.f, s3 = 0.f;
#pragma unroll 4
    for (int k = 0; k < NQ; k += 4) {
        s0 = fmaf(w[k + 0], __half2float(Q[(long)(k + 0) * DD]), s0);
        s1 = fmaf(w[k + 1], __half2float(Q[(long)(k + 1) * DD]), s1);
        s2 = fmaf(w[k + 2], __half2float(Q[(long)(k + 2) * DD]), s2);
        s3 = fmaf(w[k + 3], __half2float(Q[(long)(k + 3) * DD]), s3);
    }
    pooled[b * DD + d] = (s0 + s1) + (s2 + s3);
}

// pooled[b, d] = sum_m att[b, m] * X[b, m, d]  (l-path only)
__global__ void pool_kernel(const float* __restrict__ X,
                            const float* __restrict__ att,
                            float* __restrict__ pooled, int Nseq)
{
    int bb = blockIdx.y;
    int d  = blockIdx.x * 128 + threadIdx.x;
    const float* Xb = X + (long)bb * Nseq * DD + d;
    const float* ab = att + bb * Nseq;
    float a0 = 0.f, a1 = 0.f, a2 = 0.f, a3 = 0.f;
    for (int m = 0; m < Nseq; m += 4) {
        a0 = fmaf(ab[m + 0], Xb[(long)(m + 0) * DD], a0);
        a1 = fmaf(ab[m + 1], Xb[(long)(m + 1) * DD], a1);
        a2 = fmaf(ab[m + 2], Xb[(long)(m + 2) * DD], a2);
        a3 = fmaf(ab[m + 3], Xb[(long)(m + 3) * DD], a3);
    }
    pooled[bb * DD + d] = (a0 + a1) + (a2 + a3);
}

// ---------------------------------- launch ----------------------------------
extern "C" void kernel_launch(void* const* d_in, const int* in_sizes, int n_in,
                              void* d_out, int out_size)
{
    const float* i_batch = (const float*)d_in[0];
    const float* q_batch = (const float*)d_in[1];
    const unsigned int* i_mask = (const unsigned int*)d_in[2];
    const unsigned int* q_mask = (const unsigned int*)d_in[3];
    const float* lW1 = (const float*)d_in[4];
    const float* lb1 = (const float*)d_in[5];
    const float* lW2 = (const float*)d_in[6];
    const float* lbm = (const float*)d_in[9];
    const float* lWm = (const float*)d_in[8];
    const float* iW1 = (const float*)d_in[10];
    const float* ib1 = (const float*)d_in[11];
    const float* iW2 = (const float*)d_in[12];
    const float* iWm = (const float*)d_in[14];
    const float* ibm = (const float*)d_in[15];
    float* out = (float*)d_out;

    float *ST, *latt, *atti, *attl, *w1, *pooli, *pooll;
    __half *ih, *qh, *ihT, *P1h, *P2h, *latth, *qW1T, *WT;
    cudaGetSymbolAddress((void**)&ST, g_ST);
    cudaGetSymbolAddress((void**)&latt, g_latt);
    cudaGetSymbolAddress((void**)&atti, g_atti);
    cudaGetSymbolAddress((void**)&attl, g_attl);
    cudaGetSymbolAddress((void**)&w1, g_w1);
    cudaGetSymbolAddress((void**)&pooli, g_pooli);
    cudaGetSymbolAddress((void**)&pooll, g_pooll);
    cudaGetSymbolAddress((void**)&ih, g_ih);
    cudaGetSymbolAddress((void**)&qh, g_qh);
    cudaGetSymbolAddress((void**)&ihT, g_ihT);
    cudaGetSymbolAddress((void**)&P1h, g_P1h);
    cudaGetSymbolAddress((void**)&P2h, g_P2h);
    cudaGetSymbolAddress((void**)&latth, g_latth);
    cudaGetSymbolAddress((void**)&qW1T, g_qW1T);
    cudaGetSymbolAddress((void**)&WT, g_WT);

    cudaFuncSetAttribute(hgemm_score, cudaFuncAttributeMaxDynamicSharedMemorySize, HG_SMEM);
    cudaFuncSetAttribute(hgemm_latt, cudaFuncAttributeMaxDynamicSharedMemorySize, HG_SMEM);
    cudaFuncSetAttribute(hgemm_h<2>, cudaFuncAttributeMaxDynamicSharedMemorySize, HG_SMEM);
    cudaFuncSetAttribute(hgemm_h<3>, cudaFuncAttributeMaxDynamicSharedMemorySize, HG_SMEM);

    const float SCALE = 0.039528470752104744f;  // 1/sqrt(640)

    // ---- fp16 conversions (i also transposed) ----
    conv_trans<<<dim3(DD / 32, NI / 32, BB), dim3(32, 8)>>>(i_batch, ih, ihT, NI);
    conv_h<<<(BB * NQ * DD / 4 + 255) / 256, 256>>>(
        (const float4*)q_batch, (__half2*)qh, BB * NQ * DD / 4);

    // ---- scores ONCE with fused P1 softmax + transposed raw store ----
    hgemm_score<<<dim3(1, NI / 128, BB), 256, HG_SMEM>>>(
        ih, qh, ST, P1h, q_mask, SCALE);

    // ---- attention 2: P2 = softmax(ST, i_mask); latt = P2 @ i ----
    softmax_rows<<<BB * NQ, 128>>>(ST, i_mask, NQ, NI, P2h, nullptr);
    hgemm_latt<<<dim3(DD / 128, NQ / 128, BB), 256, HG_SMEM>>>(
        P2h, ihT, latt, latth, NQ, DD, NI,
        (long)NQ * NI, (long)DD * NI, (long)NQ * DD);

    // ---- attflat logits (b2 dropped: softmax is shift-invariant) ----
    cudaMemsetAsync(atti, 0, BB * NI * sizeof(float));
    cudaMemsetAsync(attl, 0, BB * NQ * sizeof(float));

    // i-path (factored): logits_i = relu(P1 @ (q@lW1) + lb1) @ lW2
    transpose_h<<<dim3(DH / 32, DD / 32), dim3(32, 8)>>>(lW1, WT);
    hgemm_h<3><<<dim3(NQ / 128, DH / 128, BB), 256, HG_SMEM>>>(
        WT, qh, qW1T, DH, NQ, DD,
        0, (long)NQ * DD, (long)DH * NQ, nullptr, nullptr, nullptr);
    hgemm_h<2><<<dim3(DH / 128, NI / 128, BB), 256, HG_SMEM>>>(
        P1h, qW1T, nullptr, NI, DH, NQ,
        (long)NI * NQ, (long)DH * NQ, NI, lb1, lW2, atti);

    // l-path (direct): logits_l = relu(latt @ iW1 + ib1) @ iW2
    transpose_h<<<dim3(DH / 32, DD / 32), dim3(32, 8)>>>(iW1, WT);
    hgemm_h<2><<<dim3(DH / 128, (BB * NQ) / 128, 1), 256, HG_SMEM>>>(
        latth, WT, nullptr, BB * NQ, DH, DD, 0, 0, 0, ib1, iW2, attl);

    // ---- attflat softmax over sequence (i path emits i_weight) ----
    softmax_rows<<<BB, 128>>>(atti, i_mask, 1, NI, nullptr, out + 2 * BB * DD);
    softmax_rows<<<BB, 128>>>(attl, q_mask, 1, NQ, nullptr, nullptr);

    // ---- pooled_i = (atti @ P1) @ q ----
    gemv_attP<<<BB, NQ>>>(P1h, atti, w1);
    gemv_pool<<<dim3(DD / 128, BB), 128>>>(qh, w1, pooli);

    // ---- pooled_l = attl @ latt ----
    pool_kernel<<<dim3(DD / 128, BB), 128>>>(latt, attl, pooll, NQ);

    // ---- final linears ----
    gemm128<<<dim3(DD / 128, 1, 1), 256>>>(pooli, lWm, out, BB, DD, DD, lbm);
    gemm128<<<dim3(DD / 128, 1, 1), 256>>>(pooll, iWm, out + BB * DD, BB, DD, DD, ibm);
}

// round 12
// speedup vs baseline: 4.6892x; 1.0685x over previous
#include <cuda_runtime.h>
#include <cuda_fp16.h>
#include <math.h>
#include <stdint.h>

// Problem dims
#define BB 64
#define NI 512
#define NQ 128
#define DD 640
#define DH 1280
#define NEGV (-65504.0f)

// ---------------- scratch (static __device__ arrays; no allocs) ----------------
__device__ float  g_ST[BB * NQ * NI];     // raw scaled scores, transposed
__device__ float  g_atti[BB * NI];
__device__ float  g_attl[BB * NQ];
__device__ float  g_w1[BB * NQ];          // atti @ P1
__device__ float  g_w2v[BB * NI];         // attl @ P2
__device__ float  g_pool[2 * BB * DD];    // [pooled_i | pooled_l]
__device__ __half g_ih[BB * NI * DD];
__device__ __half g_qh[BB * NQ * DD];
__device__ __half g_ihT[BB * DD * NI];
__device__ __half g_P1h[BB * NI * NQ];
__device__ __half g_P2h[BB * NQ * NI];
__device__ __half g_latth[BB * NQ * DD];
__device__ __half g_qW1T[BB * DH * NQ];
__device__ __half g_WT0[DH * DD];
__device__ __half g_WT1[DH * DD];

__device__ __forceinline__ uint32_t smem_u32(const void* p)
{
    uint32_t a;
    asm("{ .reg .u64 t; cvta.to.shared.u64 t, %1; cvt.u32.u64 %0, t; }" : "=r"(a) : "l"(p));
    return a;
}
__device__ __forceinline__ void ldmx4(uint32_t r[4], uint32_t addr)
{
    asm volatile("ldmatrix.sync.aligned.m8n8.x4.shared.b16 {%0,%1,%2,%3}, [%4];"
                 : "=r"(r[0]), "=r"(r[1]), "=r"(r[2]), "=r"(r[3]) : "r"(addr));
}
__device__ __forceinline__ void mma_f16(float c[4], const uint32_t a[4],
                                        uint32_t b0, uint32_t b1)
{
    asm volatile(
        "mma.sync.aligned.m16n8k16.row.col.f32.f16.f16.f32 "
        "{%0,%1,%2,%3}, {%4,%5,%6,%7}, {%8,%9}, {%0,%1,%2,%3};"
        : "+f"(c[0]), "+f"(c[1]), "+f"(c[2]), "+f"(c[3])
        : "r"(a[0]), "r"(a[1]), "r"(a[2]), "r"(a[3]), "r"(b0), "r"(b1));
}
__device__ __forceinline__ void mma_h16(uint32_t d[2], const uint32_t a[4],
                                        uint32_t b0, uint32_t b1)
{
    asm volatile(
        "mma.sync.aligned.m16n8k16.row.col.f16.f16.f16.f16 "
        "{%0,%1}, {%2,%3,%4,%5}, {%6,%7}, {%0,%1};"
        : "+r"(d[0]), "+r"(d[1])
        : "r"(a[0]), "r"(a[1]), "r"(a[2]), "r"(a[3]), "r"(b0), "r"(b1));
}
__device__ __forceinline__ void cp16(uint32_t dst, const void* src)
{
    asm volatile("cp.async.ca.shared.global [%0], [%1], 16;" :: "r"(dst), "l"(src));
}
#define CP_COMMIT() asm volatile("cp.async.commit_group;" ::: "memory")
#define CP_WAIT0()  asm volatile("cp.async.wait_group 0;" ::: "memory")

#define SSTR 72
#define STAGE_B (128 * SSTR * 2)
#define STAGE2_B (2 * STAGE_B)
#define HG_SMEM (2 * STAGE2_B)

#define HG_PROLOG_AND_VARS(Aptr, BTptr, Kdim)                                           \
    extern __shared__ __align__(16) char smx[];                                         \
    const uint32_t smb = smem_u32(smx);                                                 \
    const int tid  = threadIdx.x;                                                       \
    const int lane = tid & 31;                                                          \
    const int wid  = tid >> 5;                                                          \
    const int gid  = lane >> 2, tig = lane & 3;                                         \
    const int warp_m = wid & 1, warp_n = wid >> 1;                                      \
    const int m0 = blockIdx.y * 128, n0 = blockIdx.x * 128;                             \
    const int srow = tid >> 2;                                                          \
    const int sco  = (tid & 3) * 16;                                                    \
    const __half* Ag0 = (Aptr) + (long)(m0 + srow) * (Kdim) + sco;                      \
    const __half* Ag1 = (Aptr) + (long)(m0 + srow + 64) * (Kdim) + sco;                 \
    const __half* Bg0 = (BTptr) + (long)(n0 + srow) * (Kdim) + sco;                     \
    const __half* Bg1 = (BTptr) + (long)(n0 + srow + 64) * (Kdim) + sco;                \
    const uint32_t dA0 = srow * (SSTR * 2) + (tid & 3) * 32;                            \
    const uint32_t dA1 = (srow + 64) * (SSTR * 2) + (tid & 3) * 32;                     \
    const uint32_t aRowOff = (warp_m * 64 + (lane & 15)) * (SSTR * 2) + (lane >> 4) * 16;\
    const uint32_t bRowOff = STAGE_B + (warp_n * 32 + (lane & 15)) * (SSTR * 2) + (lane >> 4) * 16;

#define HG_ISSUE(sb, ko)                                                                 \
    do {                                                                                 \
        cp16((sb) + dA0, Ag0 + (ko));            cp16((sb) + dA0 + 16, Ag0 + (ko) + 8);  \
        cp16((sb) + dA1, Ag1 + (ko));            cp16((sb) + dA1 + 16, Ag1 + (ko) + 8);  \
        cp16((sb) + STAGE_B + dA0, Bg0 + (ko));  cp16((sb) + STAGE_B + dA0 + 16, Bg0 + (ko) + 8); \
        cp16((sb) + STAGE_B + dA1, Bg1 + (ko));  cp16((sb) + STAGE_B + dA1 + 16, Bg1 + (ko) + 8); \
        CP_COMMIT();                                                                     \
    } while (0)

// =============== fp32-accum fp16 GEMM, f16 output only (latt path) ===============
__global__ __launch_bounds__(256, 2)
void hgemm_latt(const __half* __restrict__ A, const __half* __restrict__ BT,
                __half* __restrict__ Ch,
                int M, int N, int K, long sA, long sB, long sC)
{
    const int zb = blockIdx.z;
    A  += (long)zb * sA;
    BT += (long)zb * sB;
    HG_PROLOG_AND_VARS(A, BT, K)

    float acc[4][4][4];
#pragma unroll
    for (int i = 0; i < 4; i++)
#pragma unroll
        for (int j = 0; j < 4; j++)
#pragma unroll
            for (int r = 0; r < 4; r++) acc[i][j][r] = 0.f;

    const int nc = K >> 6;
    HG_ISSUE(smb, 0);
#pragma unroll 1
    for (int c = 0; c < nc; ++c) {
        CP_WAIT0();
        __syncthreads();
        if (c + 1 < nc) HG_ISSUE(smb + ((c + 1) & 1) * STAGE2_B, (long)(c + 1) * 64);
        const uint32_t sb = smb + (c & 1) * STAGE2_B;
        const uint32_t aB = sb + aRowOff;
        const uint32_t bB = sb + bRowOff;
#pragma unroll
        for (int ks = 0; ks < 4; ++ks) {
            uint32_t b[2][4];
            ldmx4(b[0], bB + ks * 32);
            ldmx4(b[1], bB + 16 * (SSTR * 2) + ks * 32);
#pragma unroll
            for (int mt = 0; mt < 4; ++mt) {
                uint32_t a[4];
                ldmx4(a, aB + mt * 16 * (SSTR * 2) + ks * 32);
                mma_f16(acc[mt][0], a, b[0][0], b[0][2]);
                mma_f16(acc[mt][1], a, b[0][1], b[0][3]);
                mma_f16(acc[mt][2], a, b[1][0], b[1][2]);
                mma_f16(acc[mt][3], a, b[1][1], b[1][3]);
            }
        }
    }

    Ch += (long)zb * sC;
#pragma unroll
    for (int mt = 0; mt < 4; mt++) {
#pragma unroll
        for (int r = 0; r < 2; r++) {
            long m = m0 + warp_m * 64 + mt * 16 + r * 8 + gid;
#pragma unroll
            for (int nt = 0; nt < 4; nt++) {
                int n = n0 + warp_n * 32 + nt * 8 + tig * 2;
                *(__half2*)(Ch + m * N + n) =
                    __floats2half2_rn(acc[mt][nt][r * 2 + 0], acc[mt][nt][r * 2 + 1]);
            }
        }
    }
}

// ========= scores GEMM with FUSED P1 softmax + transposed raw-score store =========
__global__ __launch_bounds__(256, 2)
void hgemm_score(const __half* __restrict__ ihp, const __half* __restrict__ qhp,
                 float* __restrict__ ST, __half* __restrict__ P1h,
                 const unsigned int* __restrict__ qmask, float alpha)
{
    const int zb = blockIdx.z;
    const __half* A  = ihp + (long)zb * NI * DD;
    const __half* BT = qhp + (long)zb * NQ * DD;
    HG_PROLOG_AND_VARS(A, BT, DD)

    float acc[4][4][4];
#pragma unroll
    for (int i = 0; i < 4; i++)
#pragma unroll
        for (int j = 0; j < 4; j++)
#pragma unroll
            for (int r = 0; r < 4; r++) acc[i][j][r] = 0.f;

    const int nc = DD >> 6;
    HG_ISSUE(smb, 0);
#pragma unroll 1
    for (int c = 0; c < nc; ++c) {
        CP_WAIT0();
        __syncthreads();
        if (c + 1 < nc) HG_ISSUE(smb + ((c + 1) & 1) * STAGE2_B, (long)(c + 1) * 64);
        const uint32_t sb = smb + (c & 1) * STAGE2_B;
        const uint32_t aB = sb + aRowOff;
        const uint32_t bB = sb + bRowOff;
#pragma unroll
        for (int ks = 0; ks < 4; ++ks) {
            uint32_t b[2][4];
            ldmx4(b[0], bB + ks * 32);
            ldmx4(b[1], bB + 16 * (SSTR * 2) + ks * 32);
#pragma unroll
            for (int mt = 0; mt < 4; ++mt) {
                uint32_t a[4];
                ldmx4(a, aB + mt * 16 * (SSTR * 2) + ks * 32);
                mma_f16(acc[mt][0], a, b[0][0], b[0][2]);
                mma_f16(acc[mt][1], a, b[0][1], b[0][3]);
                mma_f16(acc[mt][2], a, b[1][0], b[1][2]);
                mma_f16(acc[mt][3], a, b[1][1], b[1][3]);
            }
        }
    }

    __syncthreads();
    float* Ssm = (float*)smx;                         // stride 129 (conflict-free)
    uint32_t* mkS = (uint32_t*)(smx + 128 * 129 * 4); // 128 mask words

#pragma unroll
    for (int mt = 0; mt < 4; mt++)
#pragma unroll
        for (int r = 0; r < 2; r++) {
            int m = warp_m * 64 + mt * 16 + r * 8 + gid;
#pragma unroll
            for (int nt = 0; nt < 4; nt++) {
                int n = warp_n * 32 + nt * 8 + tig * 2;
                Ssm[m * 129 + n]     = acc[mt][nt][r * 2 + 0] * alpha;
                Ssm[m * 129 + n + 1] = acc[mt][nt][r * 2 + 1] * alpha;
            }
        }
    if (tid < NQ) mkS[tid] = qmask[zb * NQ + tid];
    __syncthreads();

    {
        float* STb = ST + (long)zb * NQ * NI + m0;
        for (int idx = tid; idx < 128 * 128; idx += 256) {
            int n = idx >> 7, m = idx & 127;
            STb[(long)n * NI + m] = Ssm[m * 129 + n];
        }
    }
    __syncthreads();

    {
        const int m = tid >> 1;
        const int h = (tid & 1) * 64;
        float* row = Ssm + m * 129;
        float mx = -3.4e38f;
#pragma unroll 8
        for (int j = 0; j < 64; j++) {
            int n = h + j;
            float x = (mkS[n] != 0u) ? NEGV : row[n];
            row[n] = x;
            mx = fmaxf(mx, x);
        }
        mx = fmaxf(mx, __shfl_xor_sync(0xffffffffu, mx, 1));
        float sum = 0.f;
#pragma unroll 8
        for (int j = 0; j < 64; j++) {
            float e = __expf(row[h + j] - mx);
            row[h + j] = e;
            sum += e;
        }
        sum += __shfl_xor_sync(0xffffffffu, sum, 1);
        float inv = 1.f / sum;
        __half2* P = (__half2*)(P1h + (long)zb * NI * NQ + (long)(m0 + m) * NQ + h);
#pragma unroll 8
        for (int j = 0; j < 32; j++)
            P[j] = __floats2half2_rn(row[h + 2 * j] * inv, row[h + 2 * j + 1] * inv);
    }
}

// =============== fp16-accum fp16 GEMM (logit-only paths) — occupancy 3 ===============
// EPI 2: fused attflat logits: attOut[zb*sC + m] += sum_n relu(acc+b1[n])*w2[n]
// EPI 3: store Ch (f16) only
template <int EPI>
__global__ __launch_bounds__(256, 3)
void hgemm_h(const __half* __restrict__ A, const __half* __restrict__ BT,
             __half* __restrict__ Ch,
             int M, int N, int K, long sA, long sB, long sC,
             const float* __restrict__ b1, const float* __restrict__ w2,
             float* __restrict__ attOut)
{
    const int zb = blockIdx.z;
    A  += (long)zb * sA;
    BT += (long)zb * sB;
    HG_PROLOG_AND_VARS(A, BT, K)

    uint32_t hacc[4][4][2];
#pragma unroll
    for (int i = 0; i < 4; i++)
#pragma unroll
        for (int j = 0; j < 4; j++) { hacc[i][j][0] = 0u; hacc[i][j][1] = 0u; }

    const int nc = K >> 6;
    HG_ISSUE(smb, 0);
#pragma unroll 1
    for (int c = 0; c < nc; ++c) {
        CP_WAIT0();
        __syncthreads();
        if (c + 1 < nc) HG_ISSUE(smb + ((c + 1) & 1) * STAGE2_B, (long)(c + 1) * 64);
        const uint32_t sb = smb + (c & 1) * STAGE2_B;
        const uint32_t aB = sb + aRowOff;
        const uint32_t bB = sb + bRowOff;
#pragma unroll
        for (int ks = 0; ks < 4; ++ks) {
            uint32_t b[2][4];
            ldmx4(b[0], bB + ks * 32);
            ldmx4(b[1], bB + 16 * (SSTR * 2) + ks * 32);
#pragma unroll
            for (int mt = 0; mt < 4; ++mt) {
                uint32_t a[4];
                ldmx4(a, aB + mt * 16 * (SSTR * 2) + ks * 32);
                mma_h16(hacc[mt][0], a, b[0][0], b[0][2]);
                mma_h16(hacc[mt][1], a, b[0][1], b[0][3]);
                mma_h16(hacc[mt][2], a, b[1][0], b[1][2]);
                mma_h16(hacc[mt][3], a, b[1][1], b[1][3]);
            }
        }
    }

    if (EPI == 2) {
        attOut += (long)zb * sC;
        float bv[8], wv[8];
#pragma unroll
        for (int nt = 0; nt < 4; nt++)
#pragma unroll
            for (int cc = 0; cc < 2; cc++) {
                int n = n0 + warp_n * 32 + nt * 8 + tig * 2 + cc;
                bv[nt * 2 + cc] = b1[n];
                wv[nt * 2 + cc] = w2[n];
            }
#pragma unroll
        for (int mt = 0; mt < 4; mt++) {
#pragma unroll
            for (int r = 0; r < 2; r++) {
                float s = 0.f;
#pragma unroll
                for (int nt = 0; nt < 4; nt++) {
                    float2 v = __half22float2(*(__half2*)&hacc[mt][nt][r]);
                    s += fmaxf(v.x + bv[nt * 2 + 0], 0.f) * wv[nt * 2 + 0];
                    s += fmaxf(v.y + bv[nt * 2 + 1], 0.f) * wv[nt * 2 + 1];
                }
                s += __shfl_xor_sync(0xffffffffu, s, 1);
                s += __shfl_xor_sync(0xffffffffu, s, 2);
                if (tig == 0) {
                    int m = m0 + warp_m * 64 + mt * 16 + r * 8 + gid;
                    atomicAdd(attOut + m, s);
                }
            }
        }
    } else {
        Ch += (long)zb * sC;
#pragma unroll
        for (int mt = 0; mt < 4; mt++) {
#pragma unroll
            for (int r = 0; r < 2; r++) {
                long m = m0 + warp_m * 64 + mt * 16 + r * 8 + gid;
#pragma unroll
                for (int nt = 0; nt < 4; nt++) {
                    int n = n0 + warp_n * 32 + nt * 8 + tig * 2;
                    *(uint32_t*)(Ch + m * N + n) = hacc[mt][nt][r];
                }
            }
        }
    }
}

// ---- f32 [Nseq,DD] -> fp16 same layout + fp16 transposed [DD,Nseq], per batch ----
__global__ void conv_trans(const float* __restrict__ X, __half* __restrict__ Xh,
                           __half* __restrict__ XhT, int Nseq)
{
    __shared__ float t[32][33];
    const long bo = (long)blockIdx.z * Nseq * DD;
    X += bo; Xh += bo; XhT += bo;
    const int d0 = blockIdx.x * 32, s0 = blockIdx.y * 32;
    const int tx = threadIdx.x;
#pragma unroll
    for (int i = threadIdx.y; i < 32; i += 8) {
        float v = X[(long)(s0 + i) * DD + d0 + tx];
        t[i][tx] = v;
        Xh[(long)(s0 + i) * DD + d0 + tx] = __float2half(v);
    }
    __syncthreads();
#pragma unroll
    for (int i = threadIdx.y; i < 32; i += 8)
        XhT[(long)(d0 + i) * Nseq + s0 + tx] = __float2half(t[tx][i]);
}

// ---- plain f32 -> fp16 convert ----
__global__ void conv_h(const float4* __restrict__ in, __half2* __restrict__ out, int n4)
{
    int i = blockIdx.x * 256 + threadIdx.x;
    if (i < n4) {
        float4 v = in[i];
        out[2 * i]     = __floats2half2_rn(v.x, v.y);
        out[2 * i + 1] = __floats2half2_rn(v.z, v.w);
    }
}

// ---- both W1 (640x1280 f32) -> W1T (1280x640 fp16), z selects ----
__global__ void transpose_h2(const float* __restrict__ W0, const float* __restrict__ W1,
                             __half* __restrict__ WT0, __half* __restrict__ WT1)
{
    __shared__ float t[32][33];
    const float* W = blockIdx.z ? W1 : W0;
    __half* WT = blockIdx.z ? WT1 : WT0;
    int c0 = blockIdx.x * 32, r0 = blockIdx.y * 32;
#pragma unroll
    for (int i = threadIdx.y; i < 32; i += 8)
        t[i][threadIdx.x] = W[(long)(r0 + i) * DH + c0 + threadIdx.x];
    __syncthreads();
#pragma unroll
    for (int i = threadIdx.y; i < 32; i += 8)
        WT[(long)(c0 + i) * DD + r0 + threadIdx.x] = __float2half(t[threadIdx.x][i]);
}

// ---------------- final linears, both paths in one launch (z selects) -------------
__global__ __launch_bounds__(256, 2)
void gemm_final(const float* __restrict__ pool,
                const float* __restrict__ W0, const float* __restrict__ W1,
                const float* __restrict__ b0, const float* __restrict__ b1,
                float* __restrict__ out)
{
    __shared__ __align__(16) float As[16][128];
    __shared__ __align__(16) float Bs[16][128];

    const int z = blockIdx.z;
    const float* A  = pool + (long)z * BB * DD;
    const float* Bm = z ? W1 : W0;
    const float* bias = z ? b1 : b0;
    float* C = out + (long)z * BB * DD;

    const int M = BB, N = DD, K = DD;
    const int m0 = 0;
    const int n0 = blockIdx.x * 128;
    const int tid = threadIdx.x;
    const int tx = tid & 15;
    const int ty = tid >> 4;

    float acc[8][8];
#pragma unroll
    for (int i = 0; i < 8; i++)
#pragma unroll
        for (int j = 0; j < 8; j++) acc[i][j] = 0.f;

    for (int k0 = 0; k0 < K; k0 += 16) {
#pragma unroll
        for (int i = 0; i < 2; i++) {
            int f  = tid + i * 256;
            int ml = f >> 2;
            int kl = (f & 3) << 2;
            float4 v = make_float4(0.f, 0.f, 0.f, 0.f);
            if (m0 + ml < M)
                v = *(const float4*)(A + (long)(m0 + ml) * K + (k0 + kl));
            As[kl + 0][ml] = v.x; As[kl + 1][ml] = v.y;
            As[kl + 2][ml] = v.z; As[kl + 3][ml] = v.w;
        }
#pragma unroll
        for (int i = 0; i < 2; i++) {
            int f  = tid + i * 256;
            int kl = f >> 5;
            int nl = (f & 31) << 2;
            float4 v = *(const float4*)(Bm + (long)(k0 + kl) * N + (n0 + nl));
            *(float4*)&Bs[kl][nl] = v;
        }
        __syncthreads();

#pragma unroll
        for (int kk = 0; kk < 16; kk++) {
            float a[8], b[8];
            *(float4*)&a[0] = *(const float4*)&As[kk][ty * 4];
            *(float4*)&a[4] = *(const float4*)&As[kk][64 + ty * 4];
            *(float4*)&b[0] = *(const float4*)&Bs[kk][tx * 4];
            *(float4*)&b[4] = *(const float4*)&Bs[kk][64 + tx * 4];
#pragma unroll
            for (int i = 0; i < 8; i++)
#pragma unroll
                for (int j = 0; j < 8; j++)
                    acc[i][j] = fmaf(a[i], b[j], acc[i][j]);
        }
        __syncthreads();
    }

#pragma unroll
    for (int i = 0; i < 8; i++) {
        int m = m0 + ((i < 4) ? (ty * 4 + i) : (64 + ty * 4 + i - 4));
        if (m >= M) continue;
#pragma unroll
        for (int g = 0; g < 2; g++) {
            int n = n0 + g * 64 + tx * 4;
            float4 v;
            v.x = acc[i][g * 4 + 0] + bias[n];
            v.y = acc[i][g * 4 + 1] + bias[n + 1];
            v.z = acc[i][g * 4 + 2] + bias[n + 2];
            v.w = acc[i][g * 4 + 3] + bias[n + 3];
            *(float4*)(C + (long)m * N + n) = v;
        }
    }
}

// ---------------- masked row softmax ----------------
__device__ __forceinline__ float warpMax(float v)
{
#pragma unroll
    for (int o = 16; o > 0; o >>= 1) v = fmaxf(v, __shfl_xor_sync(0xffffffffu, v, o));
    return v;
}
__device__ __forceinline__ float warpSum(float v)
{
#pragma unroll
    for (int o = 16; o > 0; o >>= 1) v += __shfl_xor_sync(0xffffffffu, v, o);
    return v;
}

__global__ void softmax_rows(float* __restrict__ P,
                             const unsigned int* __restrict__ mask,
                             int rowsPerBatch, int N,
                             __half* __restrict__ pout,
                             float* __restrict__ wout)
{
    const int row = blockIdx.x;
    const int bb  = row / rowsPerBatch;
    float* prow = P + (long)row * N;
    const unsigned int* mrow = mask + (long)bb * N;
    const int tid = threadIdx.x;
    const int cnt = N >> 7;

    float v[4];
    float mx = -3.4e38f;
    for (int c = 0; c < cnt; c++) {
        int n = (c << 7) + tid;
        float x = prow[n];
        if (mrow[n] != 0u) x = NEGV;
        v[c] = x;
        mx = fmaxf(mx, x);
    }
    __shared__ float sr[4];
    float wm = warpMax(mx);
    if ((tid & 31) == 0) sr[tid >> 5] = wm;
    __syncthreads();
    mx = fmaxf(fmaxf(sr[0], sr[1]), fmaxf(sr[2], sr[3]));

    float sum = 0.f;
    for (int c = 0; c < cnt; c++) { v[c] = __expf(v[c] - mx); sum += v[c]; }
    __syncthreads();
    float ws = warpSum(sum);
    if ((tid & 31) == 0) sr[tid >> 5] = ws;
    __syncthreads();
    sum = sr[0] + sr[1] + sr[2] + sr[3];

    float inv = 1.f / sum;
    for (int c = 0; c < cnt; c++) {
        int n = (c << 7) + tid;
        float r = v[c] * inv;
        if (pout) pout[(long)row * N + n] = __float2half(r);
        else      prow[n] = r;
        if (wout) wout[(long)row * N + n] = r;
    }
}

// ---- w[b,k] = sum_{m<Mterms} att[b,m] * P[b, m*Kdim + k] ----
__global__ void gemv_w(const __half* __restrict__ P, const float* __restrict__ att,
                       float* __restrict__ w, int Mterms, int Kdim)
{
    const int b = blockIdx.y;
    const int k = blockIdx.x * 128 + threadIdx.x;
    const __half* Pp = P + (long)b * Mterms * Kdim + k;
    const float* a = att + (long)b * Mterms;
    float s0 = 0.f, s1 = 0.f, s2 = 0.f, s3 = 0.f;
    for (int m = 0; m < Mterms; m += 4) {
        s0 = fmaf(a[m + 0], __half2float(Pp[(long)(m + 0) * Kdim]), s0);
        s1 = fmaf(a[m + 1], __half2float(Pp[(long)(m + 1) * Kdim]), s1);
        s2 = fmaf(a[m + 2], __half2float(Pp[(long)(m + 2) * Kdim]), s2);
        s3 = fmaf(a[m + 3], __half2float(Pp[(long)(m + 3) * Kdim]), s3);
    }
    w[(long)b * Kdim + k] = (s0 + s1) + (s2 + s3);
}

// ---- pooled[b,d] = sum_{k<Nterms} w[b,k] * Xh[b, k*DD + d] ----
__global__ void gemv_pool(const __half* __restrict__ Xh, const float* __restrict__ w,
                          float* __restrict__ pooled, int Nterms)
{
    const int b = blockIdx.y;
    const int d = blockIdx.x * 128 + threadIdx.x;
    const __half* X = Xh + (long)b * Nterms * DD + d;
    const float* wp = w + (long)b * Nterms;
    float s0 = 0.f, s1 = 0.f, s2 = 0.f, s3 = 0.f;
    for (int k = 0; k < Nterms; k += 4) {
        s0 = fmaf(wp[k + 0], __half2float(X[(long)(k + 0) * DD]), s0);
        s1 = fmaf(wp[k + 1], __half2float(X[(long)(k + 1) * DD]), s1);
        s2 = fmaf(wp[k + 2], __half2float(X[(long)(k + 2) * DD]), s2);
        s3 = fmaf(wp[k + 3], __half2float(X[(long)(k + 3) * DD]), s3);
    }
    pooled[(long)b * DD + d] = (s0 + s1) + (s2 + s3);
}

// ---------------------------------- launch ----------------------------------
extern "C" void kernel_launch(void* const* d_in, const int* in_sizes, int n_in,
                              void* d_out, int out_size)
{
    const float* i_batch = (const float*)d_in[0];
    const float* q_batch = (const float*)d_in[1];
    const unsigned int* i_mask = (const unsigned int*)d_in[2];
    const unsigned int* q_mask = (const unsigned int*)d_in[3];
    const float* lW1 = (const float*)d_in[4];
    const float* lb1 = (const float*)d_in[5];
    const float* lW2 = (const float*)d_in[6];
    const float* lWm = (const float*)d_in[8];
    const float* lbm = (const float*)d_in[9];
    const float* iW1 = (const float*)d_in[10];
    const float* ib1 = (const float*)d_in[11];
    const float* iW2 = (const float*)d_in[12];
    const float* iWm = (const float*)d_in[14];
    const float* ibm = (const float*)d_in[15];
    float* out = (float*)d_out;

    float *ST, *atti, *attl, *w1, *w2v, *pool;
    __half *ih, *qh, *ihT, *P1h, *P2h, *latth, *qW1T, *WT0, *WT1;
    cudaGetSymbolAddress((void**)&ST, g_ST);
    cudaGetSymbolAddress((void**)&atti, g_atti);
    cudaGetSymbolAddress((void**)&attl, g_attl);
    cudaGetSymbolAddress((void**)&w1, g_w1);
    cudaGetSymbolAddress((void**)&w2v, g_w2v);
    cudaGetSymbolAddress((void**)&pool, g_pool);
    cudaGetSymbolAddress((void**)&ih, g_ih);
    cudaGetSymbolAddress((void**)&qh, g_qh);
    cudaGetSymbolAddress((void**)&ihT, g_ihT);
    cudaGetSymbolAddress((void**)&P1h, g_P1h);
    cudaGetSymbolAddress((void**)&P2h, g_P2h);
    cudaGetSymbolAddress((void**)&latth, g_latth);
    cudaGetSymbolAddress((void**)&qW1T, g_qW1T);
    cudaGetSymbolAddress((void**)&WT0, g_WT0);
    cudaGetSymbolAddress((void**)&WT1, g_WT1);

    cudaFuncSetAttribute(hgemm_score, cudaFuncAttributeMaxDynamicSharedMemorySize, HG_SMEM);
    cudaFuncSetAttribute(hgemm_latt, cudaFuncAttributeMaxDynamicSharedMemorySize, HG_SMEM);
    cudaFuncSetAttribute(hgemm_h<2>, cudaFuncAttributeMaxDynamicSharedMemorySize, HG_SMEM);
    cudaFuncSetAttribute(hgemm_h<3>, cudaFuncAttributeMaxDynamicSharedMemorySize, HG_SMEM);

    const float SCALE = 0.039528470752104744f;  // 1/sqrt(640)

    // ---- fp16 conversions + weight transposes (independent prologue) ----
    conv_trans<<<dim3(DD / 32, NI / 32, BB), dim3(32, 8)>>>(i_batch, ih, ihT, NI);
    conv_h<<<(BB * NQ * DD / 4 + 255) / 256, 256>>>(
        (const float4*)q_batch, (__half2*)qh, BB * NQ * DD / 4);
    transpose_h2<<<dim3(DH / 32, DD / 32, 2), dim3(32, 8)>>>(lW1, iW1, WT0, WT1);
    cudaMemsetAsync(atti, 0, BB * NI * sizeof(float));
    cudaMemsetAsync(attl, 0, BB * NQ * sizeof(float));

    // ---- scores ONCE with fused P1 softmax + transposed raw store ----
    hgemm_score<<<dim3(1, NI / 128, BB), 256, HG_SMEM>>>(
        ih, qh, ST, P1h, q_mask, SCALE);

    // ---- P2 = softmax(ST, i_mask); latth = (P2 @ i) fp16 (f32 accum) ----
    softmax_rows<<<BB * NQ, 128>>>(ST, i_mask, NQ, NI, P2h, nullptr);
    hgemm_latt<<<dim3(DD / 128, NQ / 128, BB), 256, HG_SMEM>>>(
        P2h, ihT, latth, NQ, DD, NI,
        (long)NQ * NI, (long)DD * NI, (long)NQ * DD);

    // ---- i-path (factored): logits_i = relu(P1 @ (q@lW1) + lb1) @ lW2 ----
    hgemm_h<3><<<dim3(NQ / 128, DH / 128, BB), 256, HG_SMEM>>>(
        WT0, qh, qW1T, DH, NQ, DD,
        0, (long)NQ * DD, (long)DH * NQ, nullptr, nullptr, nullptr);
    hgemm_h<2><<<dim3(DH / 128, NI / 128, BB), 256, HG_SMEM>>>(
        P1h, qW1T, nullptr, NI, DH, NQ,
        (long)NI * NQ, (long)DH * NQ, NI, lb1, lW2, atti);

    // ---- l-path (direct): logits_l = relu(latt @ iW1 + ib1) @ iW2 ----
    hgemm_h<2><<<dim3(DH / 128, (BB * NQ) / 128, 1), 256, HG_SMEM>>>(
        latth, WT1, nullptr, BB * NQ, DH, DD, 0, 0, 0, ib1, iW2, attl);

    // ---- attflat softmax over sequence (i path emits i_weight) ----
    softmax_rows<<<BB, 128>>>(atti, i_mask, 1, NI, nullptr, out + 2 * BB * DD);
    softmax_rows<<<BB, 128>>>(attl, q_mask, 1, NQ, nullptr, nullptr);

    // ---- pooled_i = (atti @ P1) @ q ;  pooled_l = (attl @ P2) @ i ----
    gemv_w<<<dim3(NQ / 128, BB), 128>>>(P1h, atti, w1, NI, NQ);
    gemv_pool<<<dim3(DD / 128, BB), 128>>>(qh, w1, pool, NQ);
    gemv_w<<<dim3(NI / 128, BB), 128>>>(P2h, attl, w2v, NQ, NI);
    gemv_pool<<<dim3(DD / 128, BB), 128>>>(ih, w2v, pool + BB * DD, NI);

    // ---- final linears (both paths, one launch) ----
    gemm_final<<<dim3(DD / 128, 1, 2), 256>>>(pool, lWm, iWm, lbm, ibm, out);
}